// round 1
// baseline (speedup 1.0000x reference)
#include <cuda_runtime.h>
#include <math.h>

// ---------------------------------------------------------------------------
// GPT-2 block: B=8, S=1024, D=1024, H=16, Hd=64
// ---------------------------------------------------------------------------
#define B_ 8
#define S_ 1024
#define D_ 1024
#define H_ 16
#define HD_ 64
#define M_ (B_ * S_)          // 8192 rows

// Scratch buffers (device globals: allocation inside kernel_launch is illegal)
__device__ float g_h   [M_ * D_];        // LN1 output
__device__ float g_qkv [M_ * 3 * D_];    // qkv
__device__ float g_ctx [M_ * D_];        // attention context (heads merged)
__device__ float g_h1  [M_ * D_];        // residual after attention
__device__ float g_h2  [M_ * D_];        // LN2 output
__device__ float g_ff  [M_ * 4 * D_];    // gelu(fc) activations

// ---------------------------------------------------------------------------
// LayerNorm: one block per row, 256 threads, float4 per thread (D=1024)
// ---------------------------------------------------------------------------
__global__ void ln_kernel(const float* __restrict__ x,
                          const float* __restrict__ g,
                          const float* __restrict__ b,
                          float* __restrict__ out) {
    __shared__ float red[8];
    int row = blockIdx.x;
    int tid = threadIdx.x;
    const float4* xr = reinterpret_cast<const float4*>(x + (size_t)row * D_);
    float4 v = xr[tid];

    float s = v.x + v.y + v.z + v.w;
    #pragma unroll
    for (int o = 16; o; o >>= 1) s += __shfl_xor_sync(0xffffffffu, s, o);
    if ((tid & 31) == 0) red[tid >> 5] = s;
    __syncthreads();
    float tot = 0.f;
    #pragma unroll
    for (int i = 0; i < 8; i++) tot += red[i];
    float mu = tot * (1.0f / D_);
    __syncthreads();

    float dx = v.x - mu, dy = v.y - mu, dz = v.z - mu, dw = v.w - mu;
    float q = dx * dx + dy * dy + dz * dz + dw * dw;
    #pragma unroll
    for (int o = 16; o; o >>= 1) q += __shfl_xor_sync(0xffffffffu, q, o);
    if ((tid & 31) == 0) red[tid >> 5] = q;
    __syncthreads();
    float qtot = 0.f;
    #pragma unroll
    for (int i = 0; i < 8; i++) qtot += red[i];
    float rstd = rsqrtf(qtot * (1.0f / D_) + 1e-5f);

    const float4 g4 = reinterpret_cast<const float4*>(g)[tid];
    const float4 b4 = reinterpret_cast<const float4*>(b)[tid];
    float4 o4;
    o4.x = dx * rstd * g4.x + b4.x;
    o4.y = dy * rstd * g4.y + b4.y;
    o4.z = dz * rstd * g4.z + b4.z;
    o4.w = dw * rstd * g4.w + b4.w;
    reinterpret_cast<float4*>(out + (size_t)row * D_)[tid] = o4;
}

// ---------------------------------------------------------------------------
// SGEMM: C[M,N] = A[M,K] @ B[K,N] (+bias, epilogue). 128x128 tile, BK=8,
// 256 threads, 8x8 per-thread micro-tile. All dims divisible (no bounds).
// EPI: 0 = +bias ; 1 = gelu(+bias) ; 2 = +bias + residual
// ---------------------------------------------------------------------------
__device__ __forceinline__ float gelu_new(float x) {
    float x3 = x * x * x;
    return 0.5f * x * (1.0f + tanhf(0.7978845608028654f * (x + 0.044715f * x3)));
}

template <int EPI>
__global__ __launch_bounds__(256, 2)
void sgemm_kernel(const float* __restrict__ A, const float* __restrict__ Bm,
                  const float* __restrict__ bias, const float* __restrict__ res,
                  float* __restrict__ C, int N, int K) {
    __shared__ float As[8][128];   // transposed A panel
    __shared__ float Bs[8][128];

    int tid  = threadIdx.x;
    int cCol = blockIdx.x;   // N / 128
    int cRow = blockIdx.y;   // M / 128

    const float* Ab = A + (size_t)cRow * 128 * K;
    const float* Bb = Bm + (size_t)cCol * 128;

    int aRow = tid >> 1, aCol = (tid & 1) * 4;     // 128 x 8 A tile, float4
    int bRow = tid >> 5, bCol = (tid & 31) * 4;    // 8 x 128 B tile, float4
    int tr = tid >> 4, tc = tid & 15;              // 16x16 threads -> 8x8 frags

    float acc[8][8];
    #pragma unroll
    for (int i = 0; i < 8; i++)
        #pragma unroll
        for (int j = 0; j < 8; j++) acc[i][j] = 0.f;

    for (int kk = 0; kk < K; kk += 8) {
        float4 a4 = *reinterpret_cast<const float4*>(Ab + (size_t)aRow * K + kk + aCol);
        As[aCol + 0][aRow] = a4.x;
        As[aCol + 1][aRow] = a4.y;
        As[aCol + 2][aRow] = a4.z;
        As[aCol + 3][aRow] = a4.w;
        *reinterpret_cast<float4*>(&Bs[bRow][bCol]) =
            *reinterpret_cast<const float4*>(Bb + (size_t)(kk + bRow) * N + bCol);
        __syncthreads();

        #pragma unroll
        for (int k = 0; k < 8; k++) {
            float am[8], bn[8];
            *reinterpret_cast<float4*>(am)     = *reinterpret_cast<float4*>(&As[k][tr * 8]);
            *reinterpret_cast<float4*>(am + 4) = *reinterpret_cast<float4*>(&As[k][tr * 8 + 4]);
            *reinterpret_cast<float4*>(bn)     = *reinterpret_cast<float4*>(&Bs[k][tc * 8]);
            *reinterpret_cast<float4*>(bn + 4) = *reinterpret_cast<float4*>(&Bs[k][tc * 8 + 4]);
            #pragma unroll
            for (int i = 0; i < 8; i++)
                #pragma unroll
                for (int j = 0; j < 8; j++)
                    acc[i][j] += am[i] * bn[j];
        }
        __syncthreads();
    }

    int row0 = cRow * 128 + tr * 8;
    int col0 = cCol * 128 + tc * 8;
    float bs[8];
    *reinterpret_cast<float4*>(bs)     = *reinterpret_cast<const float4*>(bias + col0);
    *reinterpret_cast<float4*>(bs + 4) = *reinterpret_cast<const float4*>(bias + col0 + 4);

    #pragma unroll
    for (int i = 0; i < 8; i++) {
        size_t off = (size_t)(row0 + i) * N + col0;
        float v[8];
        #pragma unroll
        for (int j = 0; j < 8; j++) {
            float t = acc[i][j] + bs[j];
            if (EPI == 1) t = gelu_new(t);
            v[j] = t;
        }
        if (EPI == 2) {
            float4 r0 = *reinterpret_cast<const float4*>(res + off);
            float4 r1 = *reinterpret_cast<const float4*>(res + off + 4);
            v[0] += r0.x; v[1] += r0.y; v[2] += r0.z; v[3] += r0.w;
            v[4] += r1.x; v[5] += r1.y; v[6] += r1.z; v[7] += r1.w;
        }
        *reinterpret_cast<float4*>(C + off)     = *reinterpret_cast<float4*>(v);
        *reinterpret_cast<float4*>(C + off + 4) = *reinterpret_cast<float4*>(v + 4);
    }
}

// ---------------------------------------------------------------------------
// Flash-style causal attention. Block = (q-tile of 64 rows, head, batch).
// 256 threads, thread (ty,tx) owns a 4x4 score/out fragment.
// Smem: q^T, k^T (reused as p^T), v  -- 3 * 16KB = 48KB static.
// Online softmax state (m,l) kept in registers, reduced with 16-lane shuffles.
// ---------------------------------------------------------------------------
__global__ __launch_bounds__(256, 2)
void attn_kernel(const float* __restrict__ qkv, float* __restrict__ ctx) {
    __shared__ float qsm[64 * 64];   // qsm[d*64 + r]
    __shared__ float ksm[64 * 64];   // ksm[d*64 + c]; later psm[c*64 + r]
    __shared__ float vsm[64 * 64];   // vsm[c*64 + d]

    const int qt = blockIdx.x;           // 0..15
    const int h  = blockIdx.y;           // 0..15
    const int b  = blockIdx.z;           // 0..7
    const int tid = threadIdx.x;
    const int tx = tid & 15, ty = tid >> 4;
    const int q0 = qt * 64;
    const int ld = 3 * D_;

    const float* qbase = qkv + (size_t)b * S_ * ld + h * HD_;
    const float* kbase = qbase + D_;
    const float* vbase = qbase + 2 * D_;

    // load Q tile transposed
    #pragma unroll
    for (int it = 0; it < 4; it++) {
        int f = tid + it * 256;               // float4 index 0..1023
        int r = f >> 4, d4 = (f & 15) * 4;
        float4 v4 = *reinterpret_cast<const float4*>(qbase + (size_t)(q0 + r) * ld + d4);
        qsm[(d4 + 0) * 64 + r] = v4.x;
        qsm[(d4 + 1) * 64 + r] = v4.y;
        qsm[(d4 + 2) * 64 + r] = v4.z;
        qsm[(d4 + 3) * 64 + r] = v4.w;
    }

    float acc[4][4];
    float m[4], l[4];
    #pragma unroll
    for (int i = 0; i < 4; i++) {
        m[i] = -INFINITY; l[i] = 0.f;
        #pragma unroll
        for (int j = 0; j < 4; j++) acc[i][j] = 0.f;
    }

    for (int kt = 0; kt <= qt; kt++) {
        __syncthreads();   // protect ksm/vsm reuse from previous iteration
        const int kv0 = kt * 64;
        // load K tile transposed, V tile natural
        #pragma unroll
        for (int it = 0; it < 4; it++) {
            int f = tid + it * 256;
            int r = f >> 4, d4 = (f & 15) * 4;
            float4 kv4 = *reinterpret_cast<const float4*>(kbase + (size_t)(kv0 + r) * ld + d4);
            ksm[(d4 + 0) * 64 + r] = kv4.x;
            ksm[(d4 + 1) * 64 + r] = kv4.y;
            ksm[(d4 + 2) * 64 + r] = kv4.z;
            ksm[(d4 + 3) * 64 + r] = kv4.w;
            float4 vv4 = *reinterpret_cast<const float4*>(vbase + (size_t)(kv0 + r) * ld + d4);
            *reinterpret_cast<float4*>(&vsm[r * 64 + d4]) = vv4;
        }
        __syncthreads();

        // scores: s = q . k  (4x4 per thread)
        float s[4][4];
        #pragma unroll
        for (int i = 0; i < 4; i++)
            #pragma unroll
            for (int j = 0; j < 4; j++) s[i][j] = 0.f;
        #pragma unroll 8
        for (int d = 0; d < 64; d++) {
            float4 a4 = *reinterpret_cast<float4*>(&qsm[d * 64 + ty * 4]);
            float4 b4 = *reinterpret_cast<float4*>(&ksm[d * 64 + tx * 4]);
            float am[4] = {a4.x, a4.y, a4.z, a4.w};
            float bn[4] = {b4.x, b4.y, b4.z, b4.w};
            #pragma unroll
            for (int i = 0; i < 4; i++)
                #pragma unroll
                for (int j = 0; j < 4; j++)
                    s[i][j] += am[i] * bn[j];
        }
        // scale + causal mask
        const bool diag = (kt == qt);
        #pragma unroll
        for (int i = 0; i < 4; i++) {
            int qr = q0 + ty * 4 + i;
            #pragma unroll
            for (int j = 0; j < 4; j++) {
                int kc = kv0 + tx * 4 + j;
                float t = s[i][j] * 0.125f;
                if (diag && kc > qr) t = -1e30f;
                s[i][j] = t;
            }
        }

        // online softmax (reduce across the 16 tx-lanes; lanes of one ty are
        // a contiguous 16-lane shuffle segment)
        float p[4][4];
        float alpha[4];
        #pragma unroll
        for (int i = 0; i < 4; i++) {
            float rm = fmaxf(fmaxf(s[i][0], s[i][1]), fmaxf(s[i][2], s[i][3]));
            #pragma unroll
            for (int o = 8; o; o >>= 1)
                rm = fmaxf(rm, __shfl_xor_sync(0xffffffffu, rm, o, 16));
            float nm = fmaxf(m[i], rm);
            alpha[i] = expf(m[i] - nm);
            float rs = 0.f;
            #pragma unroll
            for (int j = 0; j < 4; j++) {
                float e = expf(s[i][j] - nm);
                p[i][j] = e;
                rs += e;
            }
            #pragma unroll
            for (int o = 8; o; o >>= 1)
                rs += __shfl_xor_sync(0xffffffffu, rs, o, 16);
            l[i] = l[i] * alpha[i] + rs;
            m[i] = nm;
            #pragma unroll
            for (int j = 0; j < 4; j++) acc[i][j] *= alpha[i];
        }

        __syncthreads();   // everyone done reading ksm as K
        // write p transposed into ksm: psm[c*64 + r]
        #pragma unroll
        for (int i = 0; i < 4; i++)
            #pragma unroll
            for (int j = 0; j < 4; j++)
                ksm[(tx * 4 + j) * 64 + ty * 4 + i] = p[i][j];
        __syncthreads();

        // acc += p @ v
        #pragma unroll 8
        for (int c = 0; c < 64; c++) {
            float4 pv = *reinterpret_cast<float4*>(&ksm[c * 64 + ty * 4]);
            float4 vv = *reinterpret_cast<float4*>(&vsm[c * 64 + tx * 4]);
            float pm[4] = {pv.x, pv.y, pv.z, pv.w};
            float vn[4] = {vv.x, vv.y, vv.z, vv.w};
            #pragma unroll
            for (int i = 0; i < 4; i++)
                #pragma unroll
                for (int j = 0; j < 4; j++)
                    acc[i][j] += pm[i] * vn[j];
        }
    }

    // write out: ctx[b, q0+r, h*64 + dv]
    #pragma unroll
    for (int i = 0; i < 4; i++) {
        float inv = 1.0f / l[i];
        size_t off = ((size_t)b * S_ + q0 + ty * 4 + i) * D_ + h * HD_ + tx * 4;
        float4 o4;
        o4.x = acc[i][0] * inv;
        o4.y = acc[i][1] * inv;
        o4.z = acc[i][2] * inv;
        o4.w = acc[i][3] * inv;
        *reinterpret_cast<float4*>(ctx + off) = o4;
    }
}

// ---------------------------------------------------------------------------
// launch
// ---------------------------------------------------------------------------
extern "C" void kernel_launch(void* const* d_in, const int* in_sizes, int n_in,
                              void* d_out, int out_size) {
    const float* x        = (const float*)d_in[0];
    const float* ln1_g    = (const float*)d_in[1];
    const float* ln1_b    = (const float*)d_in[2];
    const float* c_attn_w = (const float*)d_in[3];
    const float* c_attn_b = (const float*)d_in[4];
    const float* c_proj_w = (const float*)d_in[5];
    const float* c_proj_b = (const float*)d_in[6];
    const float* ln2_g    = (const float*)d_in[7];
    const float* ln2_b    = (const float*)d_in[8];
    const float* fc_w     = (const float*)d_in[9];
    const float* fc_b     = (const float*)d_in[10];
    const float* proj_w   = (const float*)d_in[11];
    const float* proj_b   = (const float*)d_in[12];
    float* out = (float*)d_out;

    float *h, *qkv, *ctx, *h1, *h2, *ff;
    cudaGetSymbolAddress((void**)&h,   g_h);
    cudaGetSymbolAddress((void**)&qkv, g_qkv);
    cudaGetSymbolAddress((void**)&ctx, g_ctx);
    cudaGetSymbolAddress((void**)&h1,  g_h1);
    cudaGetSymbolAddress((void**)&h2,  g_h2);
    cudaGetSymbolAddress((void**)&ff,  g_ff);

    // 1. h = LN1(x)
    ln_kernel<<<M_, 256>>>(x, ln1_g, ln1_b, h);
    // 2. qkv = h @ Wqkv + b
    sgemm_kernel<0><<<dim3(3 * D_ / 128, M_ / 128), 256>>>(h, c_attn_w, c_attn_b,
                                                           nullptr, qkv, 3 * D_, D_);
    // 3. attention
    attn_kernel<<<dim3(S_ / 64, H_, B_), 256>>>(qkv, ctx);
    // 4. h1 = x + ctx @ Wproj + b
    sgemm_kernel<2><<<dim3(D_ / 128, M_ / 128), 256>>>(ctx, c_proj_w, c_proj_b,
                                                       x, h1, D_, D_);
    // 5. h2 = LN2(h1)
    ln_kernel<<<M_, 256>>>(h1, ln2_g, ln2_b, h2);
    // 6. ff = gelu(h2 @ fc_w + fc_b)
    sgemm_kernel<1><<<dim3(4 * D_ / 128, M_ / 128), 256>>>(h2, fc_w, fc_b,
                                                           nullptr, ff, 4 * D_, D_);
    // 7. out = h1 + ff @ proj_w + proj_b
    sgemm_kernel<2><<<dim3(D_ / 128, M_ / 128), 256>>>(ff, proj_w, proj_b,
                                                       h1, out, D_, 4 * D_);
}

// round 2
// speedup vs baseline: 1.0482x; 1.0482x over previous
#include <cuda_runtime.h>
#include <math.h>

// ---------------------------------------------------------------------------
// GPT-2 block: B=8, S=1024, D=1024, H=16, Hd=64
// ---------------------------------------------------------------------------
#define B_ 8
#define S_ 1024
#define D_ 1024
#define H_ 16
#define HD_ 64
#define M_ (B_ * S_)          // 8192 rows

// Scratch buffers (device globals: allocation inside kernel_launch is illegal)
__device__ float g_h   [M_ * D_];        // LN1 output
__device__ float g_qkv [M_ * 3 * D_];    // qkv
__device__ float g_ctx [M_ * D_];        // attention context (heads merged)
__device__ float g_h1  [M_ * D_];        // residual after attention
__device__ float g_h2  [M_ * D_];        // LN2 output
__device__ float g_ff  [M_ * 4 * D_];    // gelu(fc) activations

// ---------------------------------------------------------------------------
// LayerNorm: one block per row, 256 threads, float4 per thread (D=1024)
// ---------------------------------------------------------------------------
__global__ void ln_kernel(const float* __restrict__ x,
                          const float* __restrict__ g,
                          const float* __restrict__ b,
                          float* __restrict__ out) {
    __shared__ float red[8];
    int row = blockIdx.x;
    int tid = threadIdx.x;
    const float4* xr = reinterpret_cast<const float4*>(x + (size_t)row * D_);
    float4 v = xr[tid];

    float s = v.x + v.y + v.z + v.w;
    #pragma unroll
    for (int o = 16; o; o >>= 1) s += __shfl_xor_sync(0xffffffffu, s, o);
    if ((tid & 31) == 0) red[tid >> 5] = s;
    __syncthreads();
    float tot = 0.f;
    #pragma unroll
    for (int i = 0; i < 8; i++) tot += red[i];
    float mu = tot * (1.0f / D_);
    __syncthreads();

    float dx = v.x - mu, dy = v.y - mu, dz = v.z - mu, dw = v.w - mu;
    float q = dx * dx + dy * dy + dz * dz + dw * dw;
    #pragma unroll
    for (int o = 16; o; o >>= 1) q += __shfl_xor_sync(0xffffffffu, q, o);
    if ((tid & 31) == 0) red[tid >> 5] = q;
    __syncthreads();
    float qtot = 0.f;
    #pragma unroll
    for (int i = 0; i < 8; i++) qtot += red[i];
    float rstd = rsqrtf(qtot * (1.0f / D_) + 1e-5f);

    const float4 g4 = reinterpret_cast<const float4*>(g)[tid];
    const float4 b4 = reinterpret_cast<const float4*>(b)[tid];
    float4 o4;
    o4.x = dx * rstd * g4.x + b4.x;
    o4.y = dy * rstd * g4.y + b4.y;
    o4.z = dz * rstd * g4.z + b4.z;
    o4.w = dw * rstd * g4.w + b4.w;
    reinterpret_cast<float4*>(out + (size_t)row * D_)[tid] = o4;
}

// ---------------------------------------------------------------------------
// TF32 tensor-core GEMM with 3xTF32 precision recovery.
// C[M,N] = A[M,K] @ B[K,N] (+bias, epilogue). 128x128 CTA tile, BK=16,
// 256 threads = 8 warps (2 x 4), warp tile 64x32, mma.m16n8k8.tf32.
// EPI: 0 = +bias ; 1 = gelu(+bias) ; 2 = +bias + residual
// ---------------------------------------------------------------------------
__device__ __forceinline__ float gelu_new(float x) {
    float x3 = x * x * x;
    return 0.5f * x * (1.0f + tanhf(0.7978845608028654f * (x + 0.044715f * x3)));
}

__device__ __forceinline__ unsigned f2tf32(float x) {
    unsigned u;
    asm("cvt.rna.tf32.f32 %0, %1;" : "=r"(u) : "f"(x));
    return u;
}

__device__ __forceinline__ void mma_tf32(float* d, const unsigned* a, const unsigned* b) {
    asm volatile(
        "mma.sync.aligned.m16n8k8.row.col.f32.tf32.tf32.f32 "
        "{%0,%1,%2,%3}, {%4,%5,%6,%7}, {%8,%9}, {%0,%1,%2,%3};"
        : "+f"(d[0]), "+f"(d[1]), "+f"(d[2]), "+f"(d[3])
        : "r"(a[0]), "r"(a[1]), "r"(a[2]), "r"(a[3]), "r"(b[0]), "r"(b[1]));
}

#define AS_LD 20
#define BS_LD 132

template <int EPI>
__global__ __launch_bounds__(256, 1)
void tgemm_kernel(const float* __restrict__ A, const float* __restrict__ Bm,
                  const float* __restrict__ bias, const float* __restrict__ res,
                  float* __restrict__ C, int N, int K) {
    __shared__ unsigned As_hi[128][AS_LD];
    __shared__ unsigned As_lo[128][AS_LD];
    __shared__ unsigned Bs_hi[16][BS_LD];
    __shared__ unsigned Bs_lo[16][BS_LD];

    const int tid  = threadIdx.x;
    const int lane = tid & 31;
    const int wid  = tid >> 5;
    const int warpM = wid >> 2;           // 0..1
    const int warpN = wid & 3;            // 0..3
    const int g   = lane >> 2;            // groupID 0..7
    const int tig = lane & 3;             // thread in group 0..3

    const int cCol = blockIdx.x;
    const int cRow = blockIdx.y;

    const float* Ab = A + (size_t)cRow * 128 * K;
    const float* Bb = Bm + (size_t)cCol * 128;

    // gmem load coordinates
    const int arow = tid >> 2;            // 0..63 (+64 second it)
    const int acol = (tid & 3) * 4;
    const int brow = tid >> 5;            // 0..7 (+8 second it)
    const int bcol = (tid & 31) * 4;

    float acc[4][4][4];
    #pragma unroll
    for (int i = 0; i < 4; i++)
        #pragma unroll
        for (int j = 0; j < 4; j++)
            #pragma unroll
            for (int r = 0; r < 4; r++) acc[i][j][r] = 0.f;

    const int mrow = warpM * 64;
    const int ncol = warpN * 32;

    for (int kk = 0; kk < K; kk += 16) {
        // ---- gmem loads (overlap with previous tile's MMAs) ----
        float4 aL[2], bL[2];
        #pragma unroll
        for (int it = 0; it < 2; it++) {
            aL[it] = *reinterpret_cast<const float4*>(
                Ab + (size_t)(arow + it * 64) * K + kk + acol);
            bL[it] = *reinterpret_cast<const float4*>(
                Bb + (size_t)(kk + brow + it * 8) * N + bcol);
        }
        __syncthreads();
        // ---- convert + stage to smem ----
        #pragma unroll
        for (int it = 0; it < 2; it++) {
            float av[4] = {aL[it].x, aL[it].y, aL[it].z, aL[it].w};
            unsigned h4[4], l4[4];
            #pragma unroll
            for (int e = 0; e < 4; e++) {
                unsigned h = f2tf32(av[e]);
                h4[e] = h;
                l4[e] = f2tf32(av[e] - __uint_as_float(h));
            }
            int r = arow + it * 64;
            *reinterpret_cast<uint4*>(&As_hi[r][acol]) = make_uint4(h4[0], h4[1], h4[2], h4[3]);
            *reinterpret_cast<uint4*>(&As_lo[r][acol]) = make_uint4(l4[0], l4[1], l4[2], l4[3]);

            float bv[4] = {bL[it].x, bL[it].y, bL[it].z, bL[it].w};
            #pragma unroll
            for (int e = 0; e < 4; e++) {
                unsigned h = f2tf32(bv[e]);
                h4[e] = h;
                l4[e] = f2tf32(bv[e] - __uint_as_float(h));
            }
            int br = brow + it * 8;
            *reinterpret_cast<uint4*>(&Bs_hi[br][bcol]) = make_uint4(h4[0], h4[1], h4[2], h4[3]);
            *reinterpret_cast<uint4*>(&Bs_lo[br][bcol]) = make_uint4(l4[0], l4[1], l4[2], l4[3]);
        }
        __syncthreads();

        // ---- compute: 2 k8 steps ----
        #pragma unroll
        for (int ks = 0; ks < 2; ks++) {
            const int k0 = ks * 8;
            unsigned ah[4][4], al[4][4], bh[4][2], bl[4][2];
            #pragma unroll
            for (int mt = 0; mt < 4; mt++) {
                int r0 = mrow + mt * 16 + g;
                ah[mt][0] = As_hi[r0][k0 + tig];
                ah[mt][1] = As_hi[r0 + 8][k0 + tig];
                ah[mt][2] = As_hi[r0][k0 + tig + 4];
                ah[mt][3] = As_hi[r0 + 8][k0 + tig + 4];
                al[mt][0] = As_lo[r0][k0 + tig];
                al[mt][1] = As_lo[r0 + 8][k0 + tig];
                al[mt][2] = As_lo[r0][k0 + tig + 4];
                al[mt][3] = As_lo[r0 + 8][k0 + tig + 4];
            }
            #pragma unroll
            for (int nt = 0; nt < 4; nt++) {
                int c0 = ncol + nt * 8 + g;
                bh[nt][0] = Bs_hi[k0 + tig][c0];
                bh[nt][1] = Bs_hi[k0 + tig + 4][c0];
                bl[nt][0] = Bs_lo[k0 + tig][c0];
                bl[nt][1] = Bs_lo[k0 + tig + 4][c0];
            }
            #pragma unroll
            for (int mt = 0; mt < 4; mt++)
                #pragma unroll
                for (int nt = 0; nt < 4; nt++) {
                    mma_tf32(acc[mt][nt], ah[mt], bh[nt]);
                    mma_tf32(acc[mt][nt], ah[mt], bl[nt]);
                    mma_tf32(acc[mt][nt], al[mt], bh[nt]);
                }
        }
    }

    // ---- epilogue ----
    const int row_base = cRow * 128 + mrow;
    const int col_base = cCol * 128 + ncol;
    #pragma unroll
    for (int mt = 0; mt < 4; mt++) {
        #pragma unroll
        for (int nt = 0; nt < 4; nt++) {
            int c = col_base + nt * 8 + tig * 2;
            float b0 = bias[c], b1 = bias[c + 1];
            #pragma unroll
            for (int half = 0; half < 2; half++) {
                int r = row_base + mt * 16 + g + half * 8;
                size_t off = (size_t)r * N + c;
                float v0 = acc[mt][nt][half * 2 + 0] + b0;
                float v1 = acc[mt][nt][half * 2 + 1] + b1;
                if (EPI == 1) { v0 = gelu_new(v0); v1 = gelu_new(v1); }
                if (EPI == 2) {
                    float2 rr = *reinterpret_cast<const float2*>(res + off);
                    v0 += rr.x; v1 += rr.y;
                }
                *reinterpret_cast<float2*>(C + off) = make_float2(v0, v1);
            }
        }
    }
}

// ---------------------------------------------------------------------------
// Flash-style causal attention. Block = (q-tile of 64 rows, head, batch).
// 256 threads, thread (ty,tx) owns a 4x4 score/out fragment.  fp32.
// ---------------------------------------------------------------------------
__global__ __launch_bounds__(256, 2)
void attn_kernel(const float* __restrict__ qkv, float* __restrict__ ctx) {
    __shared__ float qsm[64 * 64];   // qsm[d*64 + r]
    __shared__ float ksm[64 * 64];   // ksm[d*64 + c]; later psm[c*64 + r]
    __shared__ float vsm[64 * 64];   // vsm[c*64 + d]

    const int qt = blockIdx.x;
    const int h  = blockIdx.y;
    const int b  = blockIdx.z;
    const int tid = threadIdx.x;
    const int tx = tid & 15, ty = tid >> 4;
    const int q0 = qt * 64;
    const int ld = 3 * D_;

    const float* qbase = qkv + (size_t)b * S_ * ld + h * HD_;
    const float* kbase = qbase + D_;
    const float* vbase = qbase + 2 * D_;

    #pragma unroll
    for (int it = 0; it < 4; it++) {
        int f = tid + it * 256;
        int r = f >> 4, d4 = (f & 15) * 4;
        float4 v4 = *reinterpret_cast<const float4*>(qbase + (size_t)(q0 + r) * ld + d4);
        qsm[(d4 + 0) * 64 + r] = v4.x;
        qsm[(d4 + 1) * 64 + r] = v4.y;
        qsm[(d4 + 2) * 64 + r] = v4.z;
        qsm[(d4 + 3) * 64 + r] = v4.w;
    }

    float acc[4][4];
    float m[4], l[4];
    #pragma unroll
    for (int i = 0; i < 4; i++) {
        m[i] = -INFINITY; l[i] = 0.f;
        #pragma unroll
        for (int j = 0; j < 4; j++) acc[i][j] = 0.f;
    }

    for (int kt = 0; kt <= qt; kt++) {
        __syncthreads();
        const int kv0 = kt * 64;
        #pragma unroll
        for (int it = 0; it < 4; it++) {
            int f = tid + it * 256;
            int r = f >> 4, d4 = (f & 15) * 4;
            float4 kv4 = *reinterpret_cast<const float4*>(kbase + (size_t)(kv0 + r) * ld + d4);
            ksm[(d4 + 0) * 64 + r] = kv4.x;
            ksm[(d4 + 1) * 64 + r] = kv4.y;
            ksm[(d4 + 2) * 64 + r] = kv4.z;
            ksm[(d4 + 3) * 64 + r] = kv4.w;
            float4 vv4 = *reinterpret_cast<const float4*>(vbase + (size_t)(kv0 + r) * ld + d4);
            *reinterpret_cast<float4*>(&vsm[r * 64 + d4]) = vv4;
        }
        __syncthreads();

        float s[4][4];
        #pragma unroll
        for (int i = 0; i < 4; i++)
            #pragma unroll
            for (int j = 0; j < 4; j++) s[i][j] = 0.f;
        #pragma unroll 8
        for (int d = 0; d < 64; d++) {
            float4 a4 = *reinterpret_cast<float4*>(&qsm[d * 64 + ty * 4]);
            float4 b4 = *reinterpret_cast<float4*>(&ksm[d * 64 + tx * 4]);
            float am[4] = {a4.x, a4.y, a4.z, a4.w};
            float bn[4] = {b4.x, b4.y, b4.z, b4.w};
            #pragma unroll
            for (int i = 0; i < 4; i++)
                #pragma unroll
                for (int j = 0; j < 4; j++)
                    s[i][j] += am[i] * bn[j];
        }
        const bool diag = (kt == qt);
        #pragma unroll
        for (int i = 0; i < 4; i++) {
            int qr = q0 + ty * 4 + i;
            #pragma unroll
            for (int j = 0; j < 4; j++) {
                int kc = kv0 + tx * 4 + j;
                float t = s[i][j] * 0.125f;
                if (diag && kc > qr) t = -1e30f;
                s[i][j] = t;
            }
        }

        float p[4][4];
        float alpha[4];
        #pragma unroll
        for (int i = 0; i < 4; i++) {
            float rm = fmaxf(fmaxf(s[i][0], s[i][1]), fmaxf(s[i][2], s[i][3]));
            #pragma unroll
            for (int o = 8; o; o >>= 1)
                rm = fmaxf(rm, __shfl_xor_sync(0xffffffffu, rm, o, 16));
            float nm = fmaxf(m[i], rm);
            alpha[i] = expf(m[i] - nm);
            float rs = 0.f;
            #pragma unroll
            for (int j = 0; j < 4; j++) {
                float e = expf(s[i][j] - nm);
                p[i][j] = e;
                rs += e;
            }
            #pragma unroll
            for (int o = 8; o; o >>= 1)
                rs += __shfl_xor_sync(0xffffffffu, rs, o, 16);
            l[i] = l[i] * alpha[i] + rs;
            m[i] = nm;
            #pragma unroll
            for (int j = 0; j < 4; j++) acc[i][j] *= alpha[i];
        }

        __syncthreads();
        #pragma unroll
        for (int i = 0; i < 4; i++)
            #pragma unroll
            for (int j = 0; j < 4; j++)
                ksm[(tx * 4 + j) * 64 + ty * 4 + i] = p[i][j];
        __syncthreads();

        #pragma unroll 8
        for (int c = 0; c < 64; c++) {
            float4 pv = *reinterpret_cast<float4*>(&ksm[c * 64 + ty * 4]);
            float4 vv = *reinterpret_cast<float4*>(&vsm[c * 64 + tx * 4]);
            float pm[4] = {pv.x, pv.y, pv.z, pv.w};
            float vn[4] = {vv.x, vv.y, vv.z, vv.w};
            #pragma unroll
            for (int i = 0; i < 4; i++)
                #pragma unroll
                for (int j = 0; j < 4; j++)
                    acc[i][j] += pm[i] * vn[j];
        }
    }

    #pragma unroll
    for (int i = 0; i < 4; i++) {
        float inv = 1.0f / l[i];
        size_t off = ((size_t)b * S_ + q0 + ty * 4 + i) * D_ + h * HD_ + tx * 4;
        float4 o4;
        o4.x = acc[i][0] * inv;
        o4.y = acc[i][1] * inv;
        o4.z = acc[i][2] * inv;
        o4.w = acc[i][3] * inv;
        *reinterpret_cast<float4*>(ctx + off) = o4;
    }
}

// ---------------------------------------------------------------------------
// launch
// ---------------------------------------------------------------------------
extern "C" void kernel_launch(void* const* d_in, const int* in_sizes, int n_in,
                              void* d_out, int out_size) {
    const float* x        = (const float*)d_in[0];
    const float* ln1_g    = (const float*)d_in[1];
    const float* ln1_b    = (const float*)d_in[2];
    const float* c_attn_w = (const float*)d_in[3];
    const float* c_attn_b = (const float*)d_in[4];
    const float* c_proj_w = (const float*)d_in[5];
    const float* c_proj_b = (const float*)d_in[6];
    const float* ln2_g    = (const float*)d_in[7];
    const float* ln2_b    = (const float*)d_in[8];
    const float* fc_w     = (const float*)d_in[9];
    const float* fc_b     = (const float*)d_in[10];
    const float* proj_w   = (const float*)d_in[11];
    const float* proj_b   = (const float*)d_in[12];
    float* out = (float*)d_out;

    float *h, *qkv, *ctx, *h1, *h2, *ff;
    cudaGetSymbolAddress((void**)&h,   g_h);
    cudaGetSymbolAddress((void**)&qkv, g_qkv);
    cudaGetSymbolAddress((void**)&ctx, g_ctx);
    cudaGetSymbolAddress((void**)&h1,  g_h1);
    cudaGetSymbolAddress((void**)&h2,  g_h2);
    cudaGetSymbolAddress((void**)&ff,  g_ff);

    // 1. h = LN1(x)
    ln_kernel<<<M_, 256>>>(x, ln1_g, ln1_b, h);
    // 2. qkv = h @ Wqkv + b
    tgemm_kernel<0><<<dim3(3 * D_ / 128, M_ / 128), 256>>>(h, c_attn_w, c_attn_b,
                                                           nullptr, qkv, 3 * D_, D_);
    // 3. attention
    attn_kernel<<<dim3(S_ / 64, H_, B_), 256>>>(qkv, ctx);
    // 4. h1 = x + ctx @ Wproj + b
    tgemm_kernel<2><<<dim3(D_ / 128, M_ / 128), 256>>>(ctx, c_proj_w, c_proj_b,
                                                       x, h1, D_, D_);
    // 5. h2 = LN2(h1)
    ln_kernel<<<M_, 256>>>(h1, ln2_g, ln2_b, h2);
    // 6. ff = gelu(h2 @ fc_w + fc_b)
    tgemm_kernel<1><<<dim3(4 * D_ / 128, M_ / 128), 256>>>(h2, fc_w, fc_b,
                                                           nullptr, ff, 4 * D_, D_);
    // 7. out = h1 + ff @ proj_w + proj_b
    tgemm_kernel<2><<<dim3(D_ / 128, M_ / 128), 256>>>(ff, proj_w, proj_b,
                                                       h1, out, D_, 4 * D_);
}

// round 6
// speedup vs baseline: 2.0062x; 1.9140x over previous
#include <cuda_runtime.h>
#include <cuda_bf16.h>
#include <cstdint>
#include <math.h>

// ---------------------------------------------------------------------------
// GPT-2 block: B=8, S=1024, D=1024, H=16, Hd=64
// ---------------------------------------------------------------------------
#define B_ 8
#define S_ 1024
#define D_ 1024
#define H_ 16
#define HD_ 64
#define M_ (B_ * S_)          // 8192 rows

typedef __nv_bfloat16 bf16;
typedef __nv_bfloat162 bf162;

// Scratch (device globals; no allocation allowed in kernel_launch)
__device__ bf16  g_h_hi [M_ * D_],     g_h_lo [M_ * D_];
__device__ float g_qkv  [M_ * 3 * D_];
__device__ bf16  g_ctx_hi[M_ * D_],    g_ctx_lo[M_ * D_];
__device__ float g_h1   [M_ * D_];
__device__ bf16  g_h2_hi[M_ * D_],     g_h2_lo[M_ * D_];
__device__ bf16  g_ff_hi[M_ * 4 * D_], g_ff_lo[M_ * 4 * D_];
// transposed weights [N, K] as bf16 hi/lo
__device__ bf16  g_wqkv_hi[3 * D_ * D_], g_wqkv_lo[3 * D_ * D_];
__device__ bf16  g_wpr_hi [D_ * D_],     g_wpr_lo [D_ * D_];
__device__ bf16  g_wfc_hi [4 * D_ * D_], g_wfc_lo [4 * D_ * D_];
__device__ bf16  g_wp2_hi [4 * D_ * D_], g_wp2_lo [4 * D_ * D_];

// ---------------------------------------------------------------------------
// helpers
// ---------------------------------------------------------------------------
__device__ __forceinline__ uint32_t smem_u32(const void* p) {
    uint32_t a;
    asm("{ .reg .u64 t; cvta.to.shared.u64 t, %1; cvt.u32.u64 %0, t; }"
        : "=r"(a) : "l"(p));
    return a;
}
__device__ __forceinline__ void cp16(uint32_t dst, const void* src) {
    asm volatile("cp.async.ca.shared.global [%0], [%1], 16;"
                 :: "r"(dst), "l"(src) : "memory");
}
__device__ __forceinline__ void cp_commit() {
    asm volatile("cp.async.commit_group;" ::: "memory");
}
template <int N>
__device__ __forceinline__ void cp_wait() {
    asm volatile("cp.async.wait_group %0;" :: "n"(N) : "memory");
}
__device__ __forceinline__ void mma_bf16(float* d, const uint32_t* a, const uint32_t* b) {
    asm volatile(
        "mma.sync.aligned.m16n8k16.row.col.f32.bf16.bf16.f32 "
        "{%0,%1,%2,%3}, {%4,%5,%6,%7}, {%8,%9}, {%0,%1,%2,%3};"
        : "+f"(d[0]), "+f"(d[1]), "+f"(d[2]), "+f"(d[3])
        : "r"(a[0]), "r"(a[1]), "r"(a[2]), "r"(a[3]), "r"(b[0]), "r"(b[1]));
}
__device__ __forceinline__ float gelu_new(float x) {
    float x3 = x * x * x;
    return 0.5f * x * (1.0f + tanhf(0.7978845608028654f * (x + 0.044715f * x3)));
}
__device__ __forceinline__ void split_bf16(float v, bf16& hi, bf16& lo) {
    hi = __float2bfloat16(v);
    lo = __float2bfloat16(v - __bfloat162float(hi));
}

// ---------------------------------------------------------------------------
// Weight convert: W[K,N] fp32 -> Wt_hi/Wt_lo[N,K] bf16 (tiled transpose)
// ---------------------------------------------------------------------------
__global__ void wconv_kernel(const float* __restrict__ W,
                             bf16* __restrict__ Th, bf16* __restrict__ Tl,
                             int K, int N) {
    __shared__ float t[32][33];
    int n0 = blockIdx.x * 32, k0 = blockIdx.y * 32;
    int tx = threadIdx.x, ty = threadIdx.y;
    #pragma unroll
    for (int j = 0; j < 4; j++)
        t[ty + j * 8][tx] = W[(size_t)(k0 + ty + j * 8) * N + n0 + tx];
    __syncthreads();
    #pragma unroll
    for (int j = 0; j < 4; j++) {
        int nl = ty + j * 8;
        float v = t[tx][nl];
        bf16 hi, lo; split_bf16(v, hi, lo);
        size_t off = (size_t)(n0 + nl) * K + k0 + tx;
        Th[off] = hi;
        Tl[off] = lo;
    }
}

// ---------------------------------------------------------------------------
// LayerNorm -> bf16 hi/lo pair output
// ---------------------------------------------------------------------------
__global__ void ln_kernel(const float* __restrict__ x,
                          const float* __restrict__ g,
                          const float* __restrict__ b,
                          bf16* __restrict__ oh, bf16* __restrict__ ol) {
    __shared__ float red[8];
    int row = blockIdx.x;
    int tid = threadIdx.x;
    const float4* xr = reinterpret_cast<const float4*>(x + (size_t)row * D_);
    float4 v = xr[tid];

    float s = v.x + v.y + v.z + v.w;
    #pragma unroll
    for (int o = 16; o; o >>= 1) s += __shfl_xor_sync(0xffffffffu, s, o);
    if ((tid & 31) == 0) red[tid >> 5] = s;
    __syncthreads();
    float tot = 0.f;
    #pragma unroll
    for (int i = 0; i < 8; i++) tot += red[i];
    float mu = tot * (1.0f / D_);
    __syncthreads();

    float dx = v.x - mu, dy = v.y - mu, dz = v.z - mu, dw = v.w - mu;
    float q = dx * dx + dy * dy + dz * dz + dw * dw;
    #pragma unroll
    for (int o = 16; o; o >>= 1) q += __shfl_xor_sync(0xffffffffu, q, o);
    if ((tid & 31) == 0) red[tid >> 5] = q;
    __syncthreads();
    float qtot = 0.f;
    #pragma unroll
    for (int i = 0; i < 8; i++) qtot += red[i];
    float rstd = rsqrtf(qtot * (1.0f / D_) + 1e-5f);

    const float4 g4 = reinterpret_cast<const float4*>(g)[tid];
    const float4 b4 = reinterpret_cast<const float4*>(b)[tid];
    float o0 = dx * rstd * g4.x + b4.x;
    float o1 = dy * rstd * g4.y + b4.y;
    float o2 = dz * rstd * g4.z + b4.z;
    float o3 = dw * rstd * g4.w + b4.w;

    bf16 h0, l0, h1, l1, h2, l2, h3, l3;
    split_bf16(o0, h0, l0); split_bf16(o1, h1, l1);
    split_bf16(o2, h2, l2); split_bf16(o3, h3, l3);
    size_t base = (size_t)row * D_ + tid * 4;
    bf162* ohp = reinterpret_cast<bf162*>(oh + base);
    bf162* olp = reinterpret_cast<bf162*>(ol + base);
    ohp[0] = bf162{h0, h1}; ohp[1] = bf162{h2, h3};
    olp[0] = bf162{l0, l1}; olp[1] = bf162{l2, l3};
}

// ---------------------------------------------------------------------------
// bf16 3-term tensor GEMM via mma.sync.m16n8k16.
// C[M,N] = A[M,K] @ W[K,N],  A as [M,K] hi/lo bf16, W as Wt[N,K] hi/lo bf16.
// CTA tile 128x128, BK=32, 3-stage cp.async pipeline, 8 warps (2x4),
// warp tile 64x32 (4x4 m16n8 fragments).
// EPI: 0 = +bias -> fp32 ; 1 = gelu(+bias) -> bf16 pair ; 2 = +bias+res -> fp32
// ---------------------------------------------------------------------------
#define BK_ 32
#define T_LD 40                     // smem row stride in bf16 (80 B)
#define TILE_BYTES (128 * T_LD * 2) // 10240
#define STAGE_BYTES (4 * TILE_BYTES)
#define SMEM_GEMM (3 * STAGE_BYTES) // 122880

template <int EPI>
__global__ __launch_bounds__(256, 1)
void tc_gemm(const bf16* __restrict__ Ah, const bf16* __restrict__ Al,
             const bf16* __restrict__ Bh, const bf16* __restrict__ Bl,
             const float* __restrict__ bias, const float* __restrict__ res,
             float* __restrict__ C, bf16* __restrict__ Ch, bf16* __restrict__ Cl,
             int N, int K) {
    extern __shared__ char dsm[];
    const uint32_t sbase = smem_u32(dsm);
    const int tid  = threadIdx.x;
    const int lane = tid & 31;
    const int wid  = tid >> 5;
    const int g    = lane >> 2;
    const int tig  = lane & 3;
    const int mrow = (wid >> 2) * 64;
    const int ncol = (wid & 3) * 32;
    const int cCol = blockIdx.x, cRow = blockIdx.y;
    const int NC = K / BK_;

    const bf16* srcs[4] = {
        Ah + (size_t)cRow * 128 * K, Al + (size_t)cRow * 128 * K,
        Bh + (size_t)cCol * 128 * K, Bl + (size_t)cCol * 128 * K};

    auto load_stage = [&](int chunk, int s) {
        const int kk = chunk * BK_;
        const uint32_t st = sbase + s * STAGE_BYTES;
        #pragma unroll
        for (int t = 0; t < 4; t++) {
            const bf16* src = srcs[t];
            #pragma unroll
            for (int i = 0; i < 2; i++) {
                int idx = tid + i * 256;
                int r = idx >> 2, ci = idx & 3;
                cp16(st + t * TILE_BYTES + r * 80 + ci * 16,
                     src + (size_t)r * K + kk + ci * 8);
            }
        }
    };

    float acc[4][4][4];
    #pragma unroll
    for (int i = 0; i < 4; i++)
        #pragma unroll
        for (int j = 0; j < 4; j++)
            #pragma unroll
            for (int r = 0; r < 4; r++) acc[i][j][r] = 0.f;

    load_stage(0, 0); cp_commit();
    load_stage(1, 1); cp_commit();

    for (int c = 0; c < NC; c++) {
        cp_wait<1>();
        __syncthreads();
        if (c + 2 < NC) load_stage(c + 2, (c + 2) % 3);
        cp_commit();

        const char* stg = dsm + (c % 3) * STAGE_BYTES;
        const bf16* As_h = reinterpret_cast<const bf16*>(stg);
        const bf16* As_l = reinterpret_cast<const bf16*>(stg + TILE_BYTES);
        const bf16* Bs_h = reinterpret_cast<const bf16*>(stg + 2 * TILE_BYTES);
        const bf16* Bs_l = reinterpret_cast<const bf16*>(stg + 3 * TILE_BYTES);

        #pragma unroll
        for (int ks = 0; ks < 2; ks++) {
            const int k0 = ks * 16 + 2 * tig;
            uint32_t ah[4][4], al[4][4], bh[4][2], bl[4][2];
            #pragma unroll
            for (int mt = 0; mt < 4; mt++) {
                int r0 = mrow + mt * 16 + g;
                ah[mt][0] = *reinterpret_cast<const uint32_t*>(As_h + r0 * T_LD + k0);
                ah[mt][1] = *reinterpret_cast<const uint32_t*>(As_h + (r0 + 8) * T_LD + k0);
                ah[mt][2] = *reinterpret_cast<const uint32_t*>(As_h + r0 * T_LD + k0 + 8);
                ah[mt][3] = *reinterpret_cast<const uint32_t*>(As_h + (r0 + 8) * T_LD + k0 + 8);
                al[mt][0] = *reinterpret_cast<const uint32_t*>(As_l + r0 * T_LD + k0);
                al[mt][1] = *reinterpret_cast<const uint32_t*>(As_l + (r0 + 8) * T_LD + k0);
                al[mt][2] = *reinterpret_cast<const uint32_t*>(As_l + r0 * T_LD + k0 + 8);
                al[mt][3] = *reinterpret_cast<const uint32_t*>(As_l + (r0 + 8) * T_LD + k0 + 8);
            }
            #pragma unroll
            for (int nt = 0; nt < 4; nt++) {
                int n = ncol + nt * 8 + g;
                bh[nt][0] = *reinterpret_cast<const uint32_t*>(Bs_h + n * T_LD + k0);
                bh[nt][1] = *reinterpret_cast<const uint32_t*>(Bs_h + n * T_LD + k0 + 8);
                bl[nt][0] = *reinterpret_cast<const uint32_t*>(Bs_l + n * T_LD + k0);
                bl[nt][1] = *reinterpret_cast<const uint32_t*>(Bs_l + n * T_LD + k0 + 8);
            }
            #pragma unroll
            for (int mt = 0; mt < 4; mt++)
                #pragma unroll
                for (int nt = 0; nt < 4; nt++) {
                    mma_bf16(acc[mt][nt], ah[mt], bh[nt]);
                    mma_bf16(acc[mt][nt], ah[mt], bl[nt]);
                    mma_bf16(acc[mt][nt], al[mt], bh[nt]);
                }
        }
    }

    // ---- epilogue ----
    const int row_base = cRow * 128 + mrow;
    const int col_base = cCol * 128 + ncol;
    #pragma unroll
    for (int mt = 0; mt < 4; mt++) {
        #pragma unroll
        for (int nt = 0; nt < 4; nt++) {
            int cc = col_base + nt * 8 + tig * 2;
            float b0 = bias[cc], b1 = bias[cc + 1];
            #pragma unroll
            for (int half = 0; half < 2; half++) {
                int r = row_base + mt * 16 + g + half * 8;
                size_t off = (size_t)r * N + cc;
                float v0 = acc[mt][nt][half * 2 + 0] + b0;
                float v1 = acc[mt][nt][half * 2 + 1] + b1;
                if (EPI == 1) {
                    v0 = gelu_new(v0); v1 = gelu_new(v1);
                    bf16 h0, l0, h1, l1;
                    split_bf16(v0, h0, l0);
                    split_bf16(v1, h1, l1);
                    *reinterpret_cast<bf162*>(Ch + off) = bf162{h0, h1};
                    *reinterpret_cast<bf162*>(Cl + off) = bf162{l0, l1};
                } else {
                    if (EPI == 2) {
                        float2 rr = *reinterpret_cast<const float2*>(res + off);
                        v0 += rr.x; v1 += rr.y;
                    }
                    *reinterpret_cast<float2*>(C + off) = make_float2(v0, v1);
                }
            }
        }
    }
}

// ---------------------------------------------------------------------------
// Flash-style causal attention (fp32), writes bf16 hi/lo ctx
// ---------------------------------------------------------------------------
__global__ __launch_bounds__(256, 2)
void attn_kernel(const float* __restrict__ qkv,
                 bf16* __restrict__ ctx_hi, bf16* __restrict__ ctx_lo) {
    __shared__ float qsm[64 * 64];
    __shared__ float ksm[64 * 64];
    __shared__ float vsm[64 * 64];

    const int qt = blockIdx.x;
    const int h  = blockIdx.y;
    const int b  = blockIdx.z;
    const int tid = threadIdx.x;
    const int tx = tid & 15, ty = tid >> 4;
    const int q0 = qt * 64;
    const int ld = 3 * D_;

    const float* qbase = qkv + (size_t)b * S_ * ld + h * HD_;
    const float* kbase = qbase + D_;
    const float* vbase = qbase + 2 * D_;

    #pragma unroll
    for (int it = 0; it < 4; it++) {
        int f = tid + it * 256;
        int r = f >> 4, d4 = (f & 15) * 4;
        float4 v4 = *reinterpret_cast<const float4*>(qbase + (size_t)(q0 + r) * ld + d4);
        qsm[(d4 + 0) * 64 + r] = v4.x;
        qsm[(d4 + 1) * 64 + r] = v4.y;
        qsm[(d4 + 2) * 64 + r] = v4.z;
        qsm[(d4 + 3) * 64 + r] = v4.w;
    }

    float acc[4][4];
    float m[4], l[4];
    #pragma unroll
    for (int i = 0; i < 4; i++) {
        m[i] = -INFINITY; l[i] = 0.f;
        #pragma unroll
        for (int j = 0; j < 4; j++) acc[i][j] = 0.f;
    }

    for (int kt = 0; kt <= qt; kt++) {
        __syncthreads();
        const int kv0 = kt * 64;
        #pragma unroll
        for (int it = 0; it < 4; it++) {
            int f = tid + it * 256;
            int r = f >> 4, d4 = (f & 15) * 4;
            float4 kv4 = *reinterpret_cast<const float4*>(kbase + (size_t)(kv0 + r) * ld + d4);
            ksm[(d4 + 0) * 64 + r] = kv4.x;
            ksm[(d4 + 1) * 64 + r] = kv4.y;
            ksm[(d4 + 2) * 64 + r] = kv4.z;
            ksm[(d4 + 3) * 64 + r] = kv4.w;
            float4 vv4 = *reinterpret_cast<const float4*>(vbase + (size_t)(kv0 + r) * ld + d4);
            *reinterpret_cast<float4*>(&vsm[r * 64 + d4]) = vv4;
        }
        __syncthreads();

        float s[4][4];
        #pragma unroll
        for (int i = 0; i < 4; i++)
            #pragma unroll
            for (int j = 0; j < 4; j++) s[i][j] = 0.f;
        #pragma unroll 8
        for (int d = 0; d < 64; d++) {
            float4 a4 = *reinterpret_cast<float4*>(&qsm[d * 64 + ty * 4]);
            float4 b4 = *reinterpret_cast<float4*>(&ksm[d * 64 + tx * 4]);
            float am[4] = {a4.x, a4.y, a4.z, a4.w};
            float bn[4] = {b4.x, b4.y, b4.z, b4.w};
            #pragma unroll
            for (int i = 0; i < 4; i++)
                #pragma unroll
                for (int j = 0; j < 4; j++)
                    s[i][j] += am[i] * bn[j];
        }
        const bool diag = (kt == qt);
        #pragma unroll
        for (int i = 0; i < 4; i++) {
            int qr = q0 + ty * 4 + i;
            #pragma unroll
            for (int j = 0; j < 4; j++) {
                int kc = kv0 + tx * 4 + j;
                float t = s[i][j] * 0.125f;
                if (diag && kc > qr) t = -1e30f;
                s[i][j] = t;
            }
        }

        float p[4][4];
        #pragma unroll
        for (int i = 0; i < 4; i++) {
            float rm = fmaxf(fmaxf(s[i][0], s[i][1]), fmaxf(s[i][2], s[i][3]));
            #pragma unroll
            for (int o = 8; o; o >>= 1)
                rm = fmaxf(rm, __shfl_xor_sync(0xffffffffu, rm, o, 16));
            float nm = fmaxf(m[i], rm);
            float alpha = expf(m[i] - nm);
            float rs = 0.f;
            #pragma unroll
            for (int j = 0; j < 4; j++) {
                float e = expf(s[i][j] - nm);
                p[i][j] = e;
                rs += e;
            }
            #pragma unroll
            for (int o = 8; o; o >>= 1)
                rs += __shfl_xor_sync(0xffffffffu, rs, o, 16);
            l[i] = l[i] * alpha + rs;
            m[i] = nm;
            #pragma unroll
            for (int j = 0; j < 4; j++) acc[i][j] *= alpha;
        }

        __syncthreads();
        #pragma unroll
        for (int i = 0; i < 4; i++)
            #pragma unroll
            for (int j = 0; j < 4; j++)
                ksm[(tx * 4 + j) * 64 + ty * 4 + i] = p[i][j];
        __syncthreads();

        #pragma unroll 8
        for (int c = 0; c < 64; c++) {
            float4 pv = *reinterpret_cast<float4*>(&ksm[c * 64 + ty * 4]);
            float4 vv = *reinterpret_cast<float4*>(&vsm[c * 64 + tx * 4]);
            float pm[4] = {pv.x, pv.y, pv.z, pv.w};
            float vn[4] = {vv.x, vv.y, vv.z, vv.w};
            #pragma unroll
            for (int i = 0; i < 4; i++)
                #pragma unroll
                for (int j = 0; j < 4; j++)
                    acc[i][j] += pm[i] * vn[j];
        }
    }

    #pragma unroll
    for (int i = 0; i < 4; i++) {
        float inv = 1.0f / l[i];
        size_t off = ((size_t)b * S_ + q0 + ty * 4 + i) * D_ + h * HD_ + tx * 4;
        float o0 = acc[i][0] * inv, o1 = acc[i][1] * inv;
        float o2 = acc[i][2] * inv, o3 = acc[i][3] * inv;
        bf16 h0, l0_, h1, l1_, h2, l2_, h3, l3_;
        split_bf16(o0, h0, l0_); split_bf16(o1, h1, l1_);
        split_bf16(o2, h2, l2_); split_bf16(o3, h3, l3_);
        bf162* hp = reinterpret_cast<bf162*>(ctx_hi + off);
        bf162* lp = reinterpret_cast<bf162*>(ctx_lo + off);
        hp[0] = bf162{h0, h1}; hp[1] = bf162{h2, h3};
        lp[0] = bf162{l0_, l1_}; lp[1] = bf162{l2_, l3_};
    }
}

// ---------------------------------------------------------------------------
// launch
// ---------------------------------------------------------------------------
extern "C" void kernel_launch(void* const* d_in, const int* in_sizes, int n_in,
                              void* d_out, int out_size) {
    const float* x        = (const float*)d_in[0];
    const float* ln1_g    = (const float*)d_in[1];
    const float* ln1_b    = (const float*)d_in[2];
    const float* c_attn_w = (const float*)d_in[3];
    const float* c_attn_b = (const float*)d_in[4];
    const float* c_proj_w = (const float*)d_in[5];
    const float* c_proj_b = (const float*)d_in[6];
    const float* ln2_g    = (const float*)d_in[7];
    const float* ln2_b    = (const float*)d_in[8];
    const float* fc_w     = (const float*)d_in[9];
    const float* fc_b     = (const float*)d_in[10];
    const float* proj_w   = (const float*)d_in[11];
    const float* proj_b   = (const float*)d_in[12];
    float* out = (float*)d_out;

    cudaFuncSetAttribute(tc_gemm<0>, cudaFuncAttributeMaxDynamicSharedMemorySize, SMEM_GEMM);
    cudaFuncSetAttribute(tc_gemm<1>, cudaFuncAttributeMaxDynamicSharedMemorySize, SMEM_GEMM);
    cudaFuncSetAttribute(tc_gemm<2>, cudaFuncAttributeMaxDynamicSharedMemorySize, SMEM_GEMM);

    bf16 *h_hi, *h_lo, *ctx_hi, *ctx_lo, *h2_hi, *h2_lo, *ff_hi, *ff_lo;
    bf16 *wqkv_hi, *wqkv_lo, *wpr_hi, *wpr_lo, *wfc_hi, *wfc_lo, *wp2_hi, *wp2_lo;
    float *qkv, *h1;
    cudaGetSymbolAddress((void**)&h_hi, g_h_hi);   cudaGetSymbolAddress((void**)&h_lo, g_h_lo);
    cudaGetSymbolAddress((void**)&qkv, g_qkv);
    cudaGetSymbolAddress((void**)&ctx_hi, g_ctx_hi); cudaGetSymbolAddress((void**)&ctx_lo, g_ctx_lo);
    cudaGetSymbolAddress((void**)&h1, g_h1);
    cudaGetSymbolAddress((void**)&h2_hi, g_h2_hi); cudaGetSymbolAddress((void**)&h2_lo, g_h2_lo);
    cudaGetSymbolAddress((void**)&ff_hi, g_ff_hi); cudaGetSymbolAddress((void**)&ff_lo, g_ff_lo);
    cudaGetSymbolAddress((void**)&wqkv_hi, g_wqkv_hi); cudaGetSymbolAddress((void**)&wqkv_lo, g_wqkv_lo);
    cudaGetSymbolAddress((void**)&wpr_hi, g_wpr_hi);   cudaGetSymbolAddress((void**)&wpr_lo, g_wpr_lo);
    cudaGetSymbolAddress((void**)&wfc_hi, g_wfc_hi);   cudaGetSymbolAddress((void**)&wfc_lo, g_wfc_lo);
    cudaGetSymbolAddress((void**)&wp2_hi, g_wp2_hi);   cudaGetSymbolAddress((void**)&wp2_lo, g_wp2_lo);

    dim3 tb(32, 8);
    // weight transposes+splits
    wconv_kernel<<<dim3(3 * D_ / 32, D_ / 32), tb>>>(c_attn_w, wqkv_hi, wqkv_lo, D_, 3 * D_);
    wconv_kernel<<<dim3(D_ / 32, D_ / 32), tb>>>(c_proj_w, wpr_hi, wpr_lo, D_, D_);
    wconv_kernel<<<dim3(4 * D_ / 32, D_ / 32), tb>>>(fc_w, wfc_hi, wfc_lo, D_, 4 * D_);
    wconv_kernel<<<dim3(D_ / 32, 4 * D_ / 32), tb>>>(proj_w, wp2_hi, wp2_lo, 4 * D_, D_);

    // 1. h = LN1(x)
    ln_kernel<<<M_, 256>>>(x, ln1_g, ln1_b, h_hi, h_lo);
    // 2. qkv = h @ Wqkv + b    (fp32 out)
    tc_gemm<0><<<dim3(3 * D_ / 128, M_ / 128), 256, SMEM_GEMM>>>(
        h_hi, h_lo, wqkv_hi, wqkv_lo, c_attn_b, nullptr, qkv, nullptr, nullptr,
        3 * D_, D_);
    // 3. attention -> ctx bf16 pair
    attn_kernel<<<dim3(S_ / 64, H_, B_), 256>>>(qkv, ctx_hi, ctx_lo);
    // 4. h1 = x + ctx @ Wproj + b  (fp32 out)
    tc_gemm<2><<<dim3(D_ / 128, M_ / 128), 256, SMEM_GEMM>>>(
        ctx_hi, ctx_lo, wpr_hi, wpr_lo, c_proj_b, x, h1, nullptr, nullptr,
        D_, D_);
    // 5. h2 = LN2(h1)
    ln_kernel<<<M_, 256>>>(h1, ln2_g, ln2_b, h2_hi, h2_lo);
    // 6. ff = gelu(h2 @ fc_w + fc_b)  (bf16 pair out)
    tc_gemm<1><<<dim3(4 * D_ / 128, M_ / 128), 256, SMEM_GEMM>>>(
        h2_hi, h2_lo, wfc_hi, wfc_lo, fc_b, nullptr, nullptr, ff_hi, ff_lo,
        4 * D_, D_);
    // 7. out = h1 + ff @ proj_w + proj_b  (fp32 out)
    tc_gemm<2><<<dim3(D_ / 128, M_ / 128), 256, SMEM_GEMM>>>(
        ff_hi, ff_lo, wp2_hi, wp2_lo, proj_b, h1, out, nullptr, nullptr,
        D_, 4 * D_);
}

// round 7
// speedup vs baseline: 2.6786x; 1.3352x over previous
#include <cuda_runtime.h>
#include <cuda_bf16.h>
#include <cstdint>
#include <math.h>

// ---------------------------------------------------------------------------
// GPT-2 block: B=8, S=1024, D=1024, H=16, Hd=64
// ---------------------------------------------------------------------------
#define B_ 8
#define S_ 1024
#define D_ 1024
#define H_ 16
#define HD_ 64
#define M_ (B_ * S_)          // 8192 rows

typedef __nv_bfloat16 bf16;
typedef __nv_bfloat162 bf162;

// Scratch (device globals; no allocation allowed in kernel_launch)
__device__ bf16  g_h_hi [M_ * D_],     g_h_lo [M_ * D_];
__device__ bf16  g_qkv_hi[M_ * 3 * D_], g_qkv_lo[M_ * 3 * D_];
__device__ bf16  g_ctx_hi[M_ * D_],    g_ctx_lo[M_ * D_];
__device__ float g_h1   [M_ * D_];
__device__ bf16  g_h2_hi[M_ * D_],     g_h2_lo[M_ * D_];
__device__ bf16  g_ff_hi[M_ * 4 * D_], g_ff_lo[M_ * 4 * D_];
// transposed weights [N, K] as bf16 hi/lo
__device__ bf16  g_wqkv_hi[3 * D_ * D_], g_wqkv_lo[3 * D_ * D_];
__device__ bf16  g_wpr_hi [D_ * D_],     g_wpr_lo [D_ * D_];
__device__ bf16  g_wfc_hi [4 * D_ * D_], g_wfc_lo [4 * D_ * D_];
__device__ bf16  g_wp2_hi [4 * D_ * D_], g_wp2_lo [4 * D_ * D_];

// ---------------------------------------------------------------------------
// helpers
// ---------------------------------------------------------------------------
__device__ __forceinline__ uint32_t smem_u32(const void* p) {
    uint32_t a;
    asm("{ .reg .u64 t; cvta.to.shared.u64 t, %1; cvt.u32.u64 %0, t; }"
        : "=r"(a) : "l"(p));
    return a;
}
__device__ __forceinline__ void cp16(uint32_t dst, const void* src) {
    asm volatile("cp.async.ca.shared.global [%0], [%1], 16;"
                 :: "r"(dst), "l"(src) : "memory");
}
__device__ __forceinline__ void cp_commit() {
    asm volatile("cp.async.commit_group;" ::: "memory");
}
template <int N>
__device__ __forceinline__ void cp_wait() {
    asm volatile("cp.async.wait_group %0;" :: "n"(N) : "memory");
}
__device__ __forceinline__ void mma_bf16(float* d, const uint32_t* a, const uint32_t* b) {
    asm volatile(
        "mma.sync.aligned.m16n8k16.row.col.f32.bf16.bf16.f32 "
        "{%0,%1,%2,%3}, {%4,%5,%6,%7}, {%8,%9}, {%0,%1,%2,%3};"
        : "+f"(d[0]), "+f"(d[1]), "+f"(d[2]), "+f"(d[3])
        : "r"(a[0]), "r"(a[1]), "r"(a[2]), "r"(a[3]), "r"(b[0]), "r"(b[1]));
}
__device__ __forceinline__ void ldm_x4(uint32_t* r, uint32_t addr) {
    asm volatile("ldmatrix.sync.aligned.m8n8.x4.shared.b16 {%0,%1,%2,%3}, [%4];"
                 : "=r"(r[0]), "=r"(r[1]), "=r"(r[2]), "=r"(r[3]) : "r"(addr));
}
__device__ __forceinline__ void ldm_x4_t(uint32_t* r, uint32_t addr) {
    asm volatile("ldmatrix.sync.aligned.m8n8.x4.trans.shared.b16 {%0,%1,%2,%3}, [%4];"
                 : "=r"(r[0]), "=r"(r[1]), "=r"(r[2]), "=r"(r[3]) : "r"(addr));
}
__device__ __forceinline__ float gelu_new(float x) {
    float x3 = x * x * x;
    return 0.5f * x * (1.0f + tanhf(0.7978845608028654f * (x + 0.044715f * x3)));
}
__device__ __forceinline__ void split_bf16(float v, bf16& hi, bf16& lo) {
    hi = __float2bfloat16(v);
    lo = __float2bfloat16(v - __bfloat162float(hi));
}
__device__ __forceinline__ uint32_t pack2(bf16 a, bf16 b) {
    bf162 t{a, b};
    return *reinterpret_cast<uint32_t*>(&t);
}

// ---------------------------------------------------------------------------
// Weight convert: W[K,N] fp32 -> Wt_hi/Wt_lo[N,K] bf16 (tiled transpose)
// ---------------------------------------------------------------------------
__global__ void wconv_kernel(const float* __restrict__ W,
                             bf16* __restrict__ Th, bf16* __restrict__ Tl,
                             int K, int N) {
    __shared__ float t[32][33];
    int n0 = blockIdx.x * 32, k0 = blockIdx.y * 32;
    int tx = threadIdx.x, ty = threadIdx.y;
    #pragma unroll
    for (int j = 0; j < 4; j++)
        t[ty + j * 8][tx] = W[(size_t)(k0 + ty + j * 8) * N + n0 + tx];
    __syncthreads();
    #pragma unroll
    for (int j = 0; j < 4; j++) {
        int nl = ty + j * 8;
        float v = t[tx][nl];
        bf16 hi, lo; split_bf16(v, hi, lo);
        size_t off = (size_t)(n0 + nl) * K + k0 + tx;
        Th[off] = hi;
        Tl[off] = lo;
    }
}

// ---------------------------------------------------------------------------
// LayerNorm -> bf16 hi/lo pair output
// ---------------------------------------------------------------------------
__global__ void ln_kernel(const float* __restrict__ x,
                          const float* __restrict__ g,
                          const float* __restrict__ b,
                          bf16* __restrict__ oh, bf16* __restrict__ ol) {
    __shared__ float red[8];
    int row = blockIdx.x;
    int tid = threadIdx.x;
    const float4* xr = reinterpret_cast<const float4*>(x + (size_t)row * D_);
    float4 v = xr[tid];

    float s = v.x + v.y + v.z + v.w;
    #pragma unroll
    for (int o = 16; o; o >>= 1) s += __shfl_xor_sync(0xffffffffu, s, o);
    if ((tid & 31) == 0) red[tid >> 5] = s;
    __syncthreads();
    float tot = 0.f;
    #pragma unroll
    for (int i = 0; i < 8; i++) tot += red[i];
    float mu = tot * (1.0f / D_);
    __syncthreads();

    float dx = v.x - mu, dy = v.y - mu, dz = v.z - mu, dw = v.w - mu;
    float q = dx * dx + dy * dy + dz * dz + dw * dw;
    #pragma unroll
    for (int o = 16; o; o >>= 1) q += __shfl_xor_sync(0xffffffffu, q, o);
    if ((tid & 31) == 0) red[tid >> 5] = q;
    __syncthreads();
    float qtot = 0.f;
    #pragma unroll
    for (int i = 0; i < 8; i++) qtot += red[i];
    float rstd = rsqrtf(qtot * (1.0f / D_) + 1e-5f);

    const float4 g4 = reinterpret_cast<const float4*>(g)[tid];
    const float4 b4 = reinterpret_cast<const float4*>(b)[tid];
    float o0 = dx * rstd * g4.x + b4.x;
    float o1 = dy * rstd * g4.y + b4.y;
    float o2 = dz * rstd * g4.z + b4.z;
    float o3 = dw * rstd * g4.w + b4.w;

    bf16 h0, l0, h1, l1, h2, l2, h3, l3;
    split_bf16(o0, h0, l0); split_bf16(o1, h1, l1);
    split_bf16(o2, h2, l2); split_bf16(o3, h3, l3);
    size_t base = (size_t)row * D_ + tid * 4;
    bf162* ohp = reinterpret_cast<bf162*>(oh + base);
    bf162* olp = reinterpret_cast<bf162*>(ol + base);
    ohp[0] = bf162{h0, h1}; ohp[1] = bf162{h2, h3};
    olp[0] = bf162{l0, l1}; olp[1] = bf162{l2, l3};
}

// ---------------------------------------------------------------------------
// bf16 3-term tensor GEMM via mma.sync.m16n8k16 + ldmatrix.
// C[M,N] = A[M,K] @ W[K,N],  A as [M,K] hi/lo bf16, W as Wt[N,K] hi/lo bf16.
// CTA tile 128x128, BK=32, 3-stage cp.async pipeline, 8 warps (2x4),
// warp tile 64x32.
// EPI: 0 = +bias -> bf16 pair ; 1 = gelu(+bias) -> bf16 pair ;
//      2 = +bias+res -> fp32
// ---------------------------------------------------------------------------
#define BK_ 32
#define T_LD 40                     // smem row stride in bf16 (80 B)
#define TILE_BYTES (128 * T_LD * 2) // 10240
#define STAGE_BYTES (4 * TILE_BYTES)
#define SMEM_GEMM (3 * STAGE_BYTES) // 122880

template <int EPI>
__global__ __launch_bounds__(256, 1)
void tc_gemm(const bf16* __restrict__ Ah, const bf16* __restrict__ Al,
             const bf16* __restrict__ Bh, const bf16* __restrict__ Bl,
             const float* __restrict__ bias, const float* __restrict__ res,
             float* __restrict__ C, bf16* __restrict__ Ch, bf16* __restrict__ Cl,
             int N, int K) {
    extern __shared__ char dsm[];
    const uint32_t sbase = smem_u32(dsm);
    const int tid  = threadIdx.x;
    const int lane = tid & 31;
    const int wid  = tid >> 5;
    const int g    = lane >> 2;
    const int tig  = lane & 3;
    const int mrow = (wid >> 2) * 64;
    const int ncol = (wid & 3) * 32;
    const int cCol = blockIdx.x, cRow = blockIdx.y;
    const int NC = K / BK_;
    // ldmatrix lane address components
    const int lr  = lane & 7;
    const int l8  = (lane & 8) ? 8 : 0;
    const int l16 = (lane & 16) ? 8 : 0;

    const bf16* srcs[4] = {
        Ah + (size_t)cRow * 128 * K, Al + (size_t)cRow * 128 * K,
        Bh + (size_t)cCol * 128 * K, Bl + (size_t)cCol * 128 * K};

    auto load_stage = [&](int chunk, int s) {
        const int kk = chunk * BK_;
        const uint32_t st = sbase + s * STAGE_BYTES;
        #pragma unroll
        for (int t = 0; t < 4; t++) {
            const bf16* src = srcs[t];
            #pragma unroll
            for (int i = 0; i < 2; i++) {
                int idx = tid + i * 256;
                int r = idx >> 2, ci = idx & 3;
                cp16(st + t * TILE_BYTES + r * 80 + ci * 16,
                     src + (size_t)r * K + kk + ci * 8);
            }
        }
    };

    float acc[4][4][4];
    #pragma unroll
    for (int i = 0; i < 4; i++)
        #pragma unroll
        for (int j = 0; j < 4; j++)
            #pragma unroll
            for (int r = 0; r < 4; r++) acc[i][j][r] = 0.f;

    load_stage(0, 0); cp_commit();
    load_stage(1, 1); cp_commit();

    for (int c = 0; c < NC; c++) {
        cp_wait<1>();
        __syncthreads();
        if (c + 2 < NC) load_stage(c + 2, (c + 2) % 3);
        cp_commit();

        const uint32_t ust = sbase + (c % 3) * STAGE_BYTES;
        const uint32_t uAh = ust;
        const uint32_t uAl = ust + TILE_BYTES;
        const uint32_t uBh = ust + 2 * TILE_BYTES;
        const uint32_t uBl = ust + 3 * TILE_BYTES;

        #pragma unroll
        for (int ks = 0; ks < 2; ks++) {
            const int k0 = ks * 16;
            uint32_t ah[4][4], al[4][4], bh[4][2], bl[4][2];
            #pragma unroll
            for (int mt = 0; mt < 4; mt++) {
                int row = mrow + mt * 16 + lr + l8;
                uint32_t off = (uint32_t)(row * T_LD + k0 + l16) * 2;
                ldm_x4(ah[mt], uAh + off);
                ldm_x4(al[mt], uAl + off);
            }
            #pragma unroll
            for (int ntp = 0; ntp < 2; ntp++) {
                int row = ncol + ntp * 16 + lr + l16;
                uint32_t off = (uint32_t)(row * T_LD + k0 + l8) * 2;
                uint32_t t4[4];
                ldm_x4(t4, uBh + off);
                bh[2 * ntp][0] = t4[0]; bh[2 * ntp][1] = t4[1];
                bh[2 * ntp + 1][0] = t4[2]; bh[2 * ntp + 1][1] = t4[3];
                ldm_x4(t4, uBl + off);
                bl[2 * ntp][0] = t4[0]; bl[2 * ntp][1] = t4[1];
                bl[2 * ntp + 1][0] = t4[2]; bl[2 * ntp + 1][1] = t4[3];
            }
            #pragma unroll
            for (int mt = 0; mt < 4; mt++)
                #pragma unroll
                for (int nt = 0; nt < 4; nt++) {
                    mma_bf16(acc[mt][nt], ah[mt], bh[nt]);
                    mma_bf16(acc[mt][nt], ah[mt], bl[nt]);
                    mma_bf16(acc[mt][nt], al[mt], bh[nt]);
                }
        }
    }

    // ---- epilogue ----
    const int row_base = cRow * 128 + mrow;
    const int col_base = cCol * 128 + ncol;
    #pragma unroll
    for (int mt = 0; mt < 4; mt++) {
        #pragma unroll
        for (int nt = 0; nt < 4; nt++) {
            int cc = col_base + nt * 8 + tig * 2;
            float b0 = bias[cc], b1 = bias[cc + 1];
            #pragma unroll
            for (int half = 0; half < 2; half++) {
                int r = row_base + mt * 16 + g + half * 8;
                size_t off = (size_t)r * N + cc;
                float v0 = acc[mt][nt][half * 2 + 0] + b0;
                float v1 = acc[mt][nt][half * 2 + 1] + b1;
                if (EPI == 0 || EPI == 1) {
                    if (EPI == 1) { v0 = gelu_new(v0); v1 = gelu_new(v1); }
                    bf16 h0, l0, h1, l1;
                    split_bf16(v0, h0, l0);
                    split_bf16(v1, h1, l1);
                    *reinterpret_cast<bf162*>(Ch + off) = bf162{h0, h1};
                    *reinterpret_cast<bf162*>(Cl + off) = bf162{l0, l1};
                } else {
                    float2 rr = *reinterpret_cast<const float2*>(res + off);
                    v0 += rr.x; v1 += rr.y;
                    *reinterpret_cast<float2*>(C + off) = make_float2(v0, v1);
                }
            }
        }
    }
}

// ---------------------------------------------------------------------------
// Tensor-core flash attention. Block = (q-tile 128 rows, head, batch),
// 8 warps x 16 rows. QK^T and P*V via bf16 3-term mma.sync; online softmax
// per-thread; K/V double-buffered cp.async; V via ldmatrix.trans.
// ---------------------------------------------------------------------------
#define AT_LD 72
#define AT_ARR (64 * AT_LD)                 // elems per array (4608)
#define AT_STAGE (4 * AT_ARR)               // elems per stage (18432)
#define SMEM_ATTN (2 * AT_STAGE * 2)        // bytes: 73728

__global__ __launch_bounds__(256, 1)
void attn_kernel(const bf16* __restrict__ qkvh, const bf16* __restrict__ qkvl,
                 bf16* __restrict__ ctx_hi, bf16* __restrict__ ctx_lo) {
    extern __shared__ char dsm[];
    bf16* sm = reinterpret_cast<bf16*>(dsm);
    const uint32_t usm = smem_u32(dsm);

    const int qt = blockIdx.x;           // 0..7  (128-row q tiles)
    const int h  = blockIdx.y;
    const int b  = blockIdx.z;
    const int tid = threadIdx.x;
    const int wid = tid >> 5;
    const int lane = tid & 31;
    const int g   = lane >> 2;
    const int tig = lane & 3;
    const int lr  = lane & 7;
    const int l8  = (lane & 8) ? 8 : 0;
    const int l16 = (lane & 16) ? 8 : 0;

    const int q0 = qt * 128;
    const int row0 = wid * 16;           // warp row offset in tile
    const int LD3 = 3 * D_;
    const size_t bbase = (size_t)b * S_ * LD3 + h * HD_;

    // ---- load Q fragments (scaled by 1/8, exact on bf16) ----
    uint32_t qh[4][4], ql[4][4];
    {
        const bf162 s8 = __floats2bfloat162_rn(0.125f, 0.125f);
        const size_t r0a = bbase + (size_t)(q0 + row0 + g) * LD3;
        const size_t r1a = r0a + (size_t)8 * LD3;
        #pragma unroll
        for (int kc = 0; kc < 4; kc++) {
            int col = kc * 16 + 2 * tig;
            #pragma unroll
            for (int e = 0; e < 4; e++) {
                size_t a = ((e & 1) ? r1a : r0a) + col + ((e & 2) ? 8 : 0);
                bf162 vh = *reinterpret_cast<const bf162*>(qkvh + a);
                bf162 vl = *reinterpret_cast<const bf162*>(qkvl + a);
                vh = __hmul2(vh, s8);
                vl = __hmul2(vl, s8);
                qh[kc][e] = *reinterpret_cast<uint32_t*>(&vh);
                ql[kc][e] = *reinterpret_cast<uint32_t*>(&vl);
            }
        }
    }

    // smem array bases (bf16 elem offsets): [stage][arr][64][AT_LD]
    // arr 0 = K hi, 1 = K lo, 2 = V hi, 3 = V lo
    auto load_tile = [&](int kt, int s) {
        const int kv0 = kt * 64;
        #pragma unroll
        for (int i = 0; i < 2; i++) {
            int c = tid + i * 256;           // 512 chunks of 16B per array
            int r = c >> 3, c8 = (c & 7) * 8;
            size_t src = bbase + (size_t)(kv0 + r) * LD3 + c8;
            uint32_t dst = usm + (uint32_t)(s * AT_STAGE + r * AT_LD + c8) * 2;
            cp16(dst,                      qkvh + src + D_);       // K hi
            cp16(dst + AT_ARR * 2,         qkvl + src + D_);       // K lo
            cp16(dst + 2 * AT_ARR * 2,     qkvh + src + 2 * D_);   // V hi
            cp16(dst + 3 * AT_ARR * 2,     qkvl + src + 2 * D_);   // V lo
        }
    };

    float o[8][4];
    #pragma unroll
    for (int i = 0; i < 8; i++)
        #pragma unroll
        for (int j = 0; j < 4; j++) o[i][j] = 0.f;
    float m0 = -INFINITY, m1 = -INFINITY, l0 = 0.f, l1 = 0.f;

    const int ktmax = 2 * qt + 1;
    load_tile(0, 0); cp_commit();

    for (int kt = 0; kt <= ktmax; kt++) {
        const int s = kt & 1;
        const int kv0 = kt * 64;
        if (kt < ktmax) { load_tile(kt + 1, s ^ 1); cp_commit(); cp_wait<1>(); }
        else            { cp_wait<0>(); }
        __syncthreads();

        const uint32_t uK_h = usm + (uint32_t)(s * AT_STAGE) * 2;
        const uint32_t uK_l = uK_h + AT_ARR * 2;
        const uint32_t uV_h = uK_h + 2 * AT_ARR * 2;
        const uint32_t uV_l = uK_h + 3 * AT_ARR * 2;

        // ---- scores S = Qs @ K^T ----
        float sS[8][4];
        #pragma unroll
        for (int i = 0; i < 8; i++)
            #pragma unroll
            for (int j = 0; j < 4; j++) sS[i][j] = 0.f;

        #pragma unroll
        for (int ntp = 0; ntp < 4; ntp++) {
            int krow = ntp * 16 + lr + l16;
            #pragma unroll
            for (int kc = 0; kc < 4; kc++) {
                uint32_t off = (uint32_t)(krow * AT_LD + kc * 16 + l8) * 2;
                uint32_t th[4], tl[4];
                ldm_x4(th, uK_h + off);
                ldm_x4(tl, uK_l + off);
                uint32_t bh0[2] = {th[0], th[1]}, bh1[2] = {th[2], th[3]};
                uint32_t bl0[2] = {tl[0], tl[1]}, bl1[2] = {tl[2], tl[3]};
                mma_bf16(sS[2 * ntp],     qh[kc], bh0);
                mma_bf16(sS[2 * ntp],     qh[kc], bl0);
                mma_bf16(sS[2 * ntp],     ql[kc], bh0);
                mma_bf16(sS[2 * ntp + 1], qh[kc], bh1);
                mma_bf16(sS[2 * ntp + 1], qh[kc], bl1);
                mma_bf16(sS[2 * ntp + 1], ql[kc], bh1);
            }
        }

        // ---- causal mask ----
        if (kv0 + 63 > q0 + row0) {
            int r0g = q0 + row0 + g;
            #pragma unroll
            for (int nt = 0; nt < 8; nt++) {
                int c0 = kv0 + nt * 8 + 2 * tig;
                if (c0 > r0g)     sS[nt][0] = -1e30f;
                if (c0 + 1 > r0g) sS[nt][1] = -1e30f;
                if (c0 > r0g + 8)     sS[nt][2] = -1e30f;
                if (c0 + 1 > r0g + 8) sS[nt][3] = -1e30f;
            }
        }

        // ---- online softmax (rows g and g+8) ----
        float rm0 = -1e30f, rm1 = -1e30f;
        #pragma unroll
        for (int nt = 0; nt < 8; nt++) {
            rm0 = fmaxf(rm0, fmaxf(sS[nt][0], sS[nt][1]));
            rm1 = fmaxf(rm1, fmaxf(sS[nt][2], sS[nt][3]));
        }
        rm0 = fmaxf(rm0, __shfl_xor_sync(0xffffffffu, rm0, 1));
        rm0 = fmaxf(rm0, __shfl_xor_sync(0xffffffffu, rm0, 2));
        rm1 = fmaxf(rm1, __shfl_xor_sync(0xffffffffu, rm1, 1));
        rm1 = fmaxf(rm1, __shfl_xor_sync(0xffffffffu, rm1, 2));
        float nm0 = fmaxf(m0, rm0), nm1 = fmaxf(m1, rm1);
        float a0 = __expf(m0 - nm0), a1 = __expf(m1 - nm1);
        float rs0 = 0.f, rs1 = 0.f;
        #pragma unroll
        for (int nt = 0; nt < 8; nt++) {
            sS[nt][0] = __expf(sS[nt][0] - nm0);
            sS[nt][1] = __expf(sS[nt][1] - nm0);
            sS[nt][2] = __expf(sS[nt][2] - nm1);
            sS[nt][3] = __expf(sS[nt][3] - nm1);
            rs0 += sS[nt][0] + sS[nt][1];
            rs1 += sS[nt][2] + sS[nt][3];
        }
        rs0 += __shfl_xor_sync(0xffffffffu, rs0, 1);
        rs0 += __shfl_xor_sync(0xffffffffu, rs0, 2);
        rs1 += __shfl_xor_sync(0xffffffffu, rs1, 1);
        rs1 += __shfl_xor_sync(0xffffffffu, rs1, 2);
        l0 = l0 * a0 + rs0; l1 = l1 * a1 + rs1;
        m0 = nm0; m1 = nm1;
        #pragma unroll
        for (int nt = 0; nt < 8; nt++) {
            o[nt][0] *= a0; o[nt][1] *= a0;
            o[nt][2] *= a1; o[nt][3] *= a1;
        }

        // ---- pack P as A-fragments (hi/lo) ----
        uint32_t pah[4][4], pal[4][4];
        #pragma unroll
        for (int kc2 = 0; kc2 < 4; kc2++) {
            #pragma unroll
            for (int e = 0; e < 4; e++) {
                int nt = 2 * kc2 + (e >> 1);
                int j0 = (e & 1) ? 2 : 0;
                bf16 h0, lo0, h1, lo1;
                split_bf16(sS[nt][j0], h0, lo0);
                split_bf16(sS[nt][j0 + 1], h1, lo1);
                // e: 0 -> a0 (row g, k lo half), 1 -> a1 (row g+8), 2 -> a2, 3 -> a3
                pah[kc2][e] = pack2(h0, h1);
                pal[kc2][e] = pack2(lo0, lo1);
            }
        }

        // ---- O += P @ V ----
        #pragma unroll
        for (int dn = 0; dn < 4; dn++) {
            #pragma unroll
            for (int kc2 = 0; kc2 < 4; kc2++) {
                int vrow = kc2 * 16 + lr + l8;
                uint32_t off = (uint32_t)(vrow * AT_LD + dn * 16 + l16) * 2;
                uint32_t th[4], tl[4];
                ldm_x4_t(th, uV_h + off);
                ldm_x4_t(tl, uV_l + off);
                uint32_t bh0[2] = {th[0], th[1]}, bh1[2] = {th[2], th[3]};
                uint32_t bl0[2] = {tl[0], tl[1]}, bl1[2] = {tl[2], tl[3]};
                mma_bf16(o[2 * dn],     pah[kc2], bh0);
                mma_bf16(o[2 * dn],     pah[kc2], bl0);
                mma_bf16(o[2 * dn],     pal[kc2], bh0);
                mma_bf16(o[2 * dn + 1], pah[kc2], bh1);
                mma_bf16(o[2 * dn + 1], pah[kc2], bl1);
                mma_bf16(o[2 * dn + 1], pal[kc2], bh1);
            }
        }
        __syncthreads();
    }

    // ---- write ctx (bf16 hi/lo) ----
    float inv0 = 1.0f / l0, inv1 = 1.0f / l1;
    size_t r0o = ((size_t)b * S_ + q0 + row0 + g) * D_ + h * HD_;
    size_t r1o = r0o + (size_t)8 * D_;
    #pragma unroll
    for (int nt = 0; nt < 8; nt++) {
        int col = nt * 8 + 2 * tig;
        bf16 h0, lo0, h1, lo1;
        split_bf16(o[nt][0] * inv0, h0, lo0);
        split_bf16(o[nt][1] * inv0, h1, lo1);
        *reinterpret_cast<uint32_t*>(ctx_hi + r0o + col) = pack2(h0, h1);
        *reinterpret_cast<uint32_t*>(ctx_lo + r0o + col) = pack2(lo0, lo1);
        split_bf16(o[nt][2] * inv1, h0, lo0);
        split_bf16(o[nt][3] * inv1, h1, lo1);
        *reinterpret_cast<uint32_t*>(ctx_hi + r1o + col) = pack2(h0, h1);
        *reinterpret_cast<uint32_t*>(ctx_lo + r1o + col) = pack2(lo0, lo1);
    }
}

// ---------------------------------------------------------------------------
// launch
// ---------------------------------------------------------------------------
extern "C" void kernel_launch(void* const* d_in, const int* in_sizes, int n_in,
                              void* d_out, int out_size) {
    const float* x        = (const float*)d_in[0];
    const float* ln1_g    = (const float*)d_in[1];
    const float* ln1_b    = (const float*)d_in[2];
    const float* c_attn_w = (const float*)d_in[3];
    const float* c_attn_b = (const float*)d_in[4];
    const float* c_proj_w = (const float*)d_in[5];
    const float* c_proj_b = (const float*)d_in[6];
    const float* ln2_g    = (const float*)d_in[7];
    const float* ln2_b    = (const float*)d_in[8];
    const float* fc_w     = (const float*)d_in[9];
    const float* fc_b     = (const float*)d_in[10];
    const float* proj_w   = (const float*)d_in[11];
    const float* proj_b   = (const float*)d_in[12];
    float* out = (float*)d_out;

    cudaFuncSetAttribute(tc_gemm<0>, cudaFuncAttributeMaxDynamicSharedMemorySize, SMEM_GEMM);
    cudaFuncSetAttribute(tc_gemm<1>, cudaFuncAttributeMaxDynamicSharedMemorySize, SMEM_GEMM);
    cudaFuncSetAttribute(tc_gemm<2>, cudaFuncAttributeMaxDynamicSharedMemorySize, SMEM_GEMM);
    cudaFuncSetAttribute(attn_kernel, cudaFuncAttributeMaxDynamicSharedMemorySize, SMEM_ATTN);

    bf16 *h_hi, *h_lo, *qkv_hi, *qkv_lo, *ctx_hi, *ctx_lo, *h2_hi, *h2_lo, *ff_hi, *ff_lo;
    bf16 *wqkv_hi, *wqkv_lo, *wpr_hi, *wpr_lo, *wfc_hi, *wfc_lo, *wp2_hi, *wp2_lo;
    float *h1;
    cudaGetSymbolAddress((void**)&h_hi, g_h_hi);   cudaGetSymbolAddress((void**)&h_lo, g_h_lo);
    cudaGetSymbolAddress((void**)&qkv_hi, g_qkv_hi); cudaGetSymbolAddress((void**)&qkv_lo, g_qkv_lo);
    cudaGetSymbolAddress((void**)&ctx_hi, g_ctx_hi); cudaGetSymbolAddress((void**)&ctx_lo, g_ctx_lo);
    cudaGetSymbolAddress((void**)&h1, g_h1);
    cudaGetSymbolAddress((void**)&h2_hi, g_h2_hi); cudaGetSymbolAddress((void**)&h2_lo, g_h2_lo);
    cudaGetSymbolAddress((void**)&ff_hi, g_ff_hi); cudaGetSymbolAddress((void**)&ff_lo, g_ff_lo);
    cudaGetSymbolAddress((void**)&wqkv_hi, g_wqkv_hi); cudaGetSymbolAddress((void**)&wqkv_lo, g_wqkv_lo);
    cudaGetSymbolAddress((void**)&wpr_hi, g_wpr_hi);   cudaGetSymbolAddress((void**)&wpr_lo, g_wpr_lo);
    cudaGetSymbolAddress((void**)&wfc_hi, g_wfc_hi);   cudaGetSymbolAddress((void**)&wfc_lo, g_wfc_lo);
    cudaGetSymbolAddress((void**)&wp2_hi, g_wp2_hi);   cudaGetSymbolAddress((void**)&wp2_lo, g_wp2_lo);

    dim3 tb(32, 8);
    wconv_kernel<<<dim3(3 * D_ / 32, D_ / 32), tb>>>(c_attn_w, wqkv_hi, wqkv_lo, D_, 3 * D_);
    wconv_kernel<<<dim3(D_ / 32, D_ / 32), tb>>>(c_proj_w, wpr_hi, wpr_lo, D_, D_);
    wconv_kernel<<<dim3(4 * D_ / 32, D_ / 32), tb>>>(fc_w, wfc_hi, wfc_lo, D_, 4 * D_);
    wconv_kernel<<<dim3(D_ / 32, 4 * D_ / 32), tb>>>(proj_w, wp2_hi, wp2_lo, 4 * D_, D_);

    // 1. h = LN1(x)
    ln_kernel<<<M_, 256>>>(x, ln1_g, ln1_b, h_hi, h_lo);
    // 2. qkv = h @ Wqkv + b  -> bf16 hi/lo
    tc_gemm<0><<<dim3(3 * D_ / 128, M_ / 128), 256, SMEM_GEMM>>>(
        h_hi, h_lo, wqkv_hi, wqkv_lo, c_attn_b, nullptr, nullptr, qkv_hi, qkv_lo,
        3 * D_, D_);
    // 3. attention -> ctx bf16 pair (tensor cores)
    attn_kernel<<<dim3(S_ / 128, H_, B_), 256, SMEM_ATTN>>>(qkv_hi, qkv_lo, ctx_hi, ctx_lo);
    // 4. h1 = x + ctx @ Wproj + b  (fp32 out)
    tc_gemm<2><<<dim3(D_ / 128, M_ / 128), 256, SMEM_GEMM>>>(
        ctx_hi, ctx_lo, wpr_hi, wpr_lo, c_proj_b, x, h1, nullptr, nullptr,
        D_, D_);
    // 5. h2 = LN2(h1)
    ln_kernel<<<M_, 256>>>(h1, ln2_g, ln2_b, h2_hi, h2_lo);
    // 6. ff = gelu(h2 @ fc_w + fc_b)  (bf16 pair out)
    tc_gemm<1><<<dim3(4 * D_ / 128, M_ / 128), 256, SMEM_GEMM>>>(
        h2_hi, h2_lo, wfc_hi, wfc_lo, fc_b, nullptr, nullptr, ff_hi, ff_lo,
        4 * D_, D_);
    // 7. out = h1 + ff @ proj_w + proj_b  (fp32 out)
    tc_gemm<2><<<dim3(D_ / 128, M_ / 128), 256, SMEM_GEMM>>>(
        ff_hi, ff_lo, wp2_hi, wp2_lo, proj_b, h1, out, nullptr, nullptr,
        D_, 4 * D_);
}

// round 8
// speedup vs baseline: 2.8509x; 1.0643x over previous
#include <cuda_runtime.h>
#include <cuda_bf16.h>
#include <cstdint>
#include <math.h>

// ---------------------------------------------------------------------------
// GPT-2 block: B=8, S=1024, D=1024, H=16, Hd=64
// ---------------------------------------------------------------------------
#define B_ 8
#define S_ 1024
#define D_ 1024
#define H_ 16
#define HD_ 64
#define M_ (B_ * S_)          // 8192 rows

typedef __nv_bfloat16 bf16;
typedef __nv_bfloat162 bf162;

// Scratch (device globals; no allocation allowed in kernel_launch)
__device__ bf16  g_h_hi [M_ * D_],     g_h_lo [M_ * D_];
__device__ bf16  g_qkv_hi[M_ * 3 * D_], g_qkv_lo[M_ * 3 * D_];
__device__ bf16  g_ctx_hi[M_ * D_],    g_ctx_lo[M_ * D_];
__device__ float g_h1   [M_ * D_];
__device__ bf16  g_h2_hi[M_ * D_],     g_h2_lo[M_ * D_];
__device__ bf16  g_ff_hi[M_ * 4 * D_], g_ff_lo[M_ * 4 * D_];
// transposed weights [N, K] as bf16 hi/lo
__device__ bf16  g_wqkv_hi[3 * D_ * D_], g_wqkv_lo[3 * D_ * D_];
__device__ bf16  g_wpr_hi [D_ * D_],     g_wpr_lo [D_ * D_];
__device__ bf16  g_wfc_hi [4 * D_ * D_], g_wfc_lo [4 * D_ * D_];
__device__ bf16  g_wp2_hi [4 * D_ * D_], g_wp2_lo [4 * D_ * D_];

// ---------------------------------------------------------------------------
// helpers
// ---------------------------------------------------------------------------
__device__ __forceinline__ uint32_t smem_u32(const void* p) {
    uint32_t a;
    asm("{ .reg .u64 t; cvta.to.shared.u64 t, %1; cvt.u32.u64 %0, t; }"
        : "=r"(a) : "l"(p));
    return a;
}
__device__ __forceinline__ void cp16(uint32_t dst, const void* src) {
    asm volatile("cp.async.ca.shared.global [%0], [%1], 16;"
                 :: "r"(dst), "l"(src) : "memory");
}
__device__ __forceinline__ void cp_commit() {
    asm volatile("cp.async.commit_group;" ::: "memory");
}
template <int N>
__device__ __forceinline__ void cp_wait() {
    asm volatile("cp.async.wait_group %0;" :: "n"(N) : "memory");
}
__device__ __forceinline__ void mma_bf16(float* d, const uint32_t* a, const uint32_t* b) {
    asm volatile(
        "mma.sync.aligned.m16n8k16.row.col.f32.bf16.bf16.f32 "
        "{%0,%1,%2,%3}, {%4,%5,%6,%7}, {%8,%9}, {%0,%1,%2,%3};"
        : "+f"(d[0]), "+f"(d[1]), "+f"(d[2]), "+f"(d[3])
        : "r"(a[0]), "r"(a[1]), "r"(a[2]), "r"(a[3]), "r"(b[0]), "r"(b[1]));
}
__device__ __forceinline__ void ldm_x4(uint32_t* r, uint32_t addr) {
    asm volatile("ldmatrix.sync.aligned.m8n8.x4.shared.b16 {%0,%1,%2,%3}, [%4];"
                 : "=r"(r[0]), "=r"(r[1]), "=r"(r[2]), "=r"(r[3]) : "r"(addr));
}
__device__ __forceinline__ void ldm_x4_t(uint32_t* r, uint32_t addr) {
    asm volatile("ldmatrix.sync.aligned.m8n8.x4.trans.shared.b16 {%0,%1,%2,%3}, [%4];"
                 : "=r"(r[0]), "=r"(r[1]), "=r"(r[2]), "=r"(r[3]) : "r"(addr));
}
__device__ __forceinline__ float gelu_new(float x) {
    float x3 = x * x * x;
    return 0.5f * x * (1.0f + tanhf(0.7978845608028654f * (x + 0.044715f * x3)));
}
__device__ __forceinline__ void split_bf16(float v, bf16& hi, bf16& lo) {
    hi = __float2bfloat16(v);
    lo = __float2bfloat16(v - __bfloat162float(hi));
}
__device__ __forceinline__ uint32_t pack2(bf16 a, bf16 b) {
    bf162 t{a, b};
    return *reinterpret_cast<uint32_t*>(&t);
}

// ---------------------------------------------------------------------------
// Weight convert: W[K,N] fp32 -> Wt_hi/Wt_lo[N,K] bf16 (tiled transpose)
// ---------------------------------------------------------------------------
__global__ void wconv_kernel(const float* __restrict__ W,
                             bf16* __restrict__ Th, bf16* __restrict__ Tl,
                             int K, int N) {
    __shared__ float t[32][33];
    int n0 = blockIdx.x * 32, k0 = blockIdx.y * 32;
    int tx = threadIdx.x, ty = threadIdx.y;
    #pragma unroll
    for (int j = 0; j < 4; j++)
        t[ty + j * 8][tx] = W[(size_t)(k0 + ty + j * 8) * N + n0 + tx];
    __syncthreads();
    #pragma unroll
    for (int j = 0; j < 4; j++) {
        int nl = ty + j * 8;
        float v = t[tx][nl];
        bf16 hi, lo; split_bf16(v, hi, lo);
        size_t off = (size_t)(n0 + nl) * K + k0 + tx;
        Th[off] = hi;
        Tl[off] = lo;
    }
}

// ---------------------------------------------------------------------------
// LayerNorm -> bf16 hi/lo pair output
// ---------------------------------------------------------------------------
__global__ void ln_kernel(const float* __restrict__ x,
                          const float* __restrict__ g,
                          const float* __restrict__ b,
                          bf16* __restrict__ oh, bf16* __restrict__ ol) {
    __shared__ float red[8];
    int row = blockIdx.x;
    int tid = threadIdx.x;
    const float4* xr = reinterpret_cast<const float4*>(x + (size_t)row * D_);
    float4 v = xr[tid];

    float s = v.x + v.y + v.z + v.w;
    #pragma unroll
    for (int o = 16; o; o >>= 1) s += __shfl_xor_sync(0xffffffffu, s, o);
    if ((tid & 31) == 0) red[tid >> 5] = s;
    __syncthreads();
    float tot = 0.f;
    #pragma unroll
    for (int i = 0; i < 8; i++) tot += red[i];
    float mu = tot * (1.0f / D_);
    __syncthreads();

    float dx = v.x - mu, dy = v.y - mu, dz = v.z - mu, dw = v.w - mu;
    float q = dx * dx + dy * dy + dz * dz + dw * dw;
    #pragma unroll
    for (int o = 16; o; o >>= 1) q += __shfl_xor_sync(0xffffffffu, q, o);
    if ((tid & 31) == 0) red[tid >> 5] = q;
    __syncthreads();
    float qtot = 0.f;
    #pragma unroll
    for (int i = 0; i < 8; i++) qtot += red[i];
    float rstd = rsqrtf(qtot * (1.0f / D_) + 1e-5f);

    const float4 g4 = reinterpret_cast<const float4*>(g)[tid];
    const float4 b4 = reinterpret_cast<const float4*>(b)[tid];
    float o0 = dx * rstd * g4.x + b4.x;
    float o1 = dy * rstd * g4.y + b4.y;
    float o2 = dz * rstd * g4.z + b4.z;
    float o3 = dw * rstd * g4.w + b4.w;

    bf16 h0, l0, h1, l1, h2, l2, h3, l3;
    split_bf16(o0, h0, l0); split_bf16(o1, h1, l1);
    split_bf16(o2, h2, l2); split_bf16(o3, h3, l3);
    size_t base = (size_t)row * D_ + tid * 4;
    bf162* ohp = reinterpret_cast<bf162*>(oh + base);
    bf162* olp = reinterpret_cast<bf162*>(ol + base);
    ohp[0] = bf162{h0, h1}; ohp[1] = bf162{h2, h3};
    olp[0] = bf162{l0, l1}; olp[1] = bf162{l2, l3};
}

// ---------------------------------------------------------------------------
// bf16 3-term tensor GEMM via mma.sync.m16n8k16 + ldmatrix.
// C[M,N] = A[M,K] @ W[K,N],  A as [M,K] hi/lo bf16, W as Wt[N,K] hi/lo bf16.
// CTA tile 128x128, BK=32, 2-stage cp.async pipeline, 8 warps (2x4),
// warp tile 64x32.  2 CTAs/SM (80KB smem, 128-reg budget).
// EPI: 0 = +bias -> bf16 pair ; 1 = gelu(+bias) -> bf16 pair ;
//      2 = +bias+res -> fp32
// ---------------------------------------------------------------------------
#define BK_ 32
#define T_LD 40                     // smem row stride in bf16 (80 B)
#define TILE_BYTES (128 * T_LD * 2) // 10240
#define STAGE_BYTES (4 * TILE_BYTES)
#define SMEM_GEMM (2 * STAGE_BYTES) // 81920

template <int EPI>
__global__ __launch_bounds__(256, 2)
void tc_gemm(const bf16* __restrict__ Ah, const bf16* __restrict__ Al,
             const bf16* __restrict__ Bh, const bf16* __restrict__ Bl,
             const float* __restrict__ bias, const float* __restrict__ res,
             float* __restrict__ C, bf16* __restrict__ Ch, bf16* __restrict__ Cl,
             int N, int K) {
    extern __shared__ char dsm[];
    const uint32_t sbase = smem_u32(dsm);
    const int tid  = threadIdx.x;
    const int lane = tid & 31;
    const int wid  = tid >> 5;
    const int g    = lane >> 2;
    const int tig  = lane & 3;
    const int mrow = (wid >> 2) * 64;
    const int ncol = (wid & 3) * 32;
    const int cCol = blockIdx.x, cRow = blockIdx.y;
    const int NC = K / BK_;
    // ldmatrix lane address components
    const int lr  = lane & 7;
    const int l8  = (lane & 8) ? 8 : 0;
    const int l16 = (lane & 16) ? 8 : 0;

    const bf16* srcs[4] = {
        Ah + (size_t)cRow * 128 * K, Al + (size_t)cRow * 128 * K,
        Bh + (size_t)cCol * 128 * K, Bl + (size_t)cCol * 128 * K};

    auto load_stage = [&](int chunk, int s) {
        const int kk = chunk * BK_;
        const uint32_t st = sbase + s * STAGE_BYTES;
        #pragma unroll
        for (int t = 0; t < 4; t++) {
            const bf16* src = srcs[t];
            #pragma unroll
            for (int i = 0; i < 2; i++) {
                int idx = tid + i * 256;
                int r = idx >> 2, ci = idx & 3;
                cp16(st + t * TILE_BYTES + r * 80 + ci * 16,
                     src + (size_t)r * K + kk + ci * 8);
            }
        }
    };

    float acc[4][4][4];
    #pragma unroll
    for (int i = 0; i < 4; i++)
        #pragma unroll
        for (int j = 0; j < 4; j++)
            #pragma unroll
            for (int r = 0; r < 4; r++) acc[i][j][r] = 0.f;

    load_stage(0, 0); cp_commit();
    load_stage(1, 1); cp_commit();

    for (int c = 0; c < NC; c++) {
        cp_wait<1>();
        __syncthreads();

        const uint32_t ust = sbase + (c & 1) * STAGE_BYTES;
        const uint32_t uAh = ust;
        const uint32_t uAl = ust + TILE_BYTES;
        const uint32_t uBh = ust + 2 * TILE_BYTES;
        const uint32_t uBl = ust + 3 * TILE_BYTES;

        #pragma unroll
        for (int ks = 0; ks < 2; ks++) {
            const int k0 = ks * 16;
            uint32_t ah[4][4], bh[4][2];
            // term 1: ah * bh
            #pragma unroll
            for (int mt = 0; mt < 4; mt++) {
                int row = mrow + mt * 16 + lr + l8;
                ldm_x4(ah[mt], uAh + (uint32_t)(row * T_LD + k0 + l16) * 2);
            }
            #pragma unroll
            for (int ntp = 0; ntp < 2; ntp++) {
                int row = ncol + ntp * 16 + lr + l16;
                uint32_t t4[4];
                ldm_x4(t4, uBh + (uint32_t)(row * T_LD + k0 + l8) * 2);
                bh[2 * ntp][0] = t4[0]; bh[2 * ntp][1] = t4[1];
                bh[2 * ntp + 1][0] = t4[2]; bh[2 * ntp + 1][1] = t4[3];
            }
            #pragma unroll
            for (int mt = 0; mt < 4; mt++)
                #pragma unroll
                for (int nt = 0; nt < 4; nt++)
                    mma_bf16(acc[mt][nt], ah[mt], bh[nt]);
            // term 2: al * bh  (reuse bh, then release)
            {
                uint32_t al[4][4];
                #pragma unroll
                for (int mt = 0; mt < 4; mt++) {
                    int row = mrow + mt * 16 + lr + l8;
                    ldm_x4(al[mt], uAl + (uint32_t)(row * T_LD + k0 + l16) * 2);
                }
                #pragma unroll
                for (int mt = 0; mt < 4; mt++)
                    #pragma unroll
                    for (int nt = 0; nt < 4; nt++)
                        mma_bf16(acc[mt][nt], al[mt], bh[nt]);
            }
            // term 3: ah * bl
            {
                uint32_t bl[4][2];
                #pragma unroll
                for (int ntp = 0; ntp < 2; ntp++) {
                    int row = ncol + ntp * 16 + lr + l16;
                    uint32_t t4[4];
                    ldm_x4(t4, uBl + (uint32_t)(row * T_LD + k0 + l8) * 2);
                    bl[2 * ntp][0] = t4[0]; bl[2 * ntp][1] = t4[1];
                    bl[2 * ntp + 1][0] = t4[2]; bl[2 * ntp + 1][1] = t4[3];
                }
                #pragma unroll
                for (int mt = 0; mt < 4; mt++)
                    #pragma unroll
                    for (int nt = 0; nt < 4; nt++)
                        mma_bf16(acc[mt][nt], ah[mt], bl[nt]);
            }
        }

        __syncthreads();   // all warps done with stage (c&1) before refill
        if (c + 2 < NC) { load_stage(c + 2, c & 1); }
        cp_commit();
    }

    // ---- epilogue ----
    const int row_base = cRow * 128 + mrow;
    const int col_base = cCol * 128 + ncol;
    #pragma unroll
    for (int mt = 0; mt < 4; mt++) {
        #pragma unroll
        for (int nt = 0; nt < 4; nt++) {
            int cc = col_base + nt * 8 + tig * 2;
            float b0 = bias[cc], b1 = bias[cc + 1];
            #pragma unroll
            for (int half = 0; half < 2; half++) {
                int r = row_base + mt * 16 + g + half * 8;
                size_t off = (size_t)r * N + cc;
                float v0 = acc[mt][nt][half * 2 + 0] + b0;
                float v1 = acc[mt][nt][half * 2 + 1] + b1;
                if (EPI == 0 || EPI == 1) {
                    if (EPI == 1) { v0 = gelu_new(v0); v1 = gelu_new(v1); }
                    bf16 h0, l0, h1, l1;
                    split_bf16(v0, h0, l0);
                    split_bf16(v1, h1, l1);
                    *reinterpret_cast<bf162*>(Ch + off) = bf162{h0, h1};
                    *reinterpret_cast<bf162*>(Cl + off) = bf162{l0, l1};
                } else {
                    float2 rr = *reinterpret_cast<const float2*>(res + off);
                    v0 += rr.x; v1 += rr.y;
                    *reinterpret_cast<float2*>(C + off) = make_float2(v0, v1);
                }
            }
        }
    }
}

// ---------------------------------------------------------------------------
// Tensor-core flash attention. Block = (q-tile 128 rows, head, batch),
// 8 warps x 16 rows. QK^T and P*V via bf16 3-term mma.sync; online softmax
// per-thread; K/V double-buffered cp.async; V via ldmatrix.trans.
// ---------------------------------------------------------------------------
#define AT_LD 72
#define AT_ARR (64 * AT_LD)                 // elems per array (4608)
#define AT_STAGE (4 * AT_ARR)               // elems per stage (18432)
#define SMEM_ATTN (2 * AT_STAGE * 2)        // bytes: 73728

__global__ __launch_bounds__(256, 1)
void attn_kernel(const bf16* __restrict__ qkvh, const bf16* __restrict__ qkvl,
                 bf16* __restrict__ ctx_hi, bf16* __restrict__ ctx_lo) {
    extern __shared__ char dsm[];
    const uint32_t usm = smem_u32(dsm);

    const int qt = blockIdx.x;           // 0..7  (128-row q tiles)
    const int h  = blockIdx.y;
    const int b  = blockIdx.z;
    const int tid = threadIdx.x;
    const int wid = tid >> 5;
    const int lane = tid & 31;
    const int g   = lane >> 2;
    const int tig = lane & 3;
    const int lr  = lane & 7;
    const int l8  = (lane & 8) ? 8 : 0;
    const int l16 = (lane & 16) ? 8 : 0;

    const int q0 = qt * 128;
    const int row0 = wid * 16;           // warp row offset in tile
    const int LD3 = 3 * D_;
    const size_t bbase = (size_t)b * S_ * LD3 + h * HD_;

    // ---- load Q fragments (scaled by 1/8, exact on bf16) ----
    uint32_t qh[4][4], ql[4][4];
    {
        const bf162 s8 = __floats2bfloat162_rn(0.125f, 0.125f);
        const size_t r0a = bbase + (size_t)(q0 + row0 + g) * LD3;
        const size_t r1a = r0a + (size_t)8 * LD3;
        #pragma unroll
        for (int kc = 0; kc < 4; kc++) {
            int col = kc * 16 + 2 * tig;
            #pragma unroll
            for (int e = 0; e < 4; e++) {
                size_t a = ((e & 1) ? r1a : r0a) + col + ((e & 2) ? 8 : 0);
                bf162 vh = *reinterpret_cast<const bf162*>(qkvh + a);
                bf162 vl = *reinterpret_cast<const bf162*>(qkvl + a);
                vh = __hmul2(vh, s8);
                vl = __hmul2(vl, s8);
                qh[kc][e] = *reinterpret_cast<uint32_t*>(&vh);
                ql[kc][e] = *reinterpret_cast<uint32_t*>(&vl);
            }
        }
    }

    // smem array bases (bf16 elem offsets): [stage][arr][64][AT_LD]
    // arr 0 = K hi, 1 = K lo, 2 = V hi, 3 = V lo
    auto load_tile = [&](int kt, int s) {
        const int kv0 = kt * 64;
        #pragma unroll
        for (int i = 0; i < 2; i++) {
            int c = tid + i * 256;           // 512 chunks of 16B per array
            int r = c >> 3, c8 = (c & 7) * 8;
            size_t src = bbase + (size_t)(kv0 + r) * LD3 + c8;
            uint32_t dst = usm + (uint32_t)(s * AT_STAGE + r * AT_LD + c8) * 2;
            cp16(dst,                      qkvh + src + D_);       // K hi
            cp16(dst + AT_ARR * 2,         qkvl + src + D_);       // K lo
            cp16(dst + 2 * AT_ARR * 2,     qkvh + src + 2 * D_);   // V hi
            cp16(dst + 3 * AT_ARR * 2,     qkvl + src + 2 * D_);   // V lo
        }
    };

    float o[8][4];
    #pragma unroll
    for (int i = 0; i < 8; i++)
        #pragma unroll
        for (int j = 0; j < 4; j++) o[i][j] = 0.f;
    float m0 = -INFINITY, m1 = -INFINITY, l0 = 0.f, l1 = 0.f;

    const int ktmax = 2 * qt + 1;
    load_tile(0, 0); cp_commit();

    for (int kt = 0; kt <= ktmax; kt++) {
        const int s = kt & 1;
        const int kv0 = kt * 64;
        if (kt < ktmax) { load_tile(kt + 1, s ^ 1); cp_commit(); cp_wait<1>(); }
        else            { cp_wait<0>(); }
        __syncthreads();

        const uint32_t uK_h = usm + (uint32_t)(s * AT_STAGE) * 2;
        const uint32_t uK_l = uK_h + AT_ARR * 2;
        const uint32_t uV_h = uK_h + 2 * AT_ARR * 2;
        const uint32_t uV_l = uK_h + 3 * AT_ARR * 2;

        // ---- scores S = Qs @ K^T ----
        float sS[8][4];
        #pragma unroll
        for (int i = 0; i < 8; i++)
            #pragma unroll
            for (int j = 0; j < 4; j++) sS[i][j] = 0.f;

        #pragma unroll
        for (int ntp = 0; ntp < 4; ntp++) {
            int krow = ntp * 16 + lr + l16;
            #pragma unroll
            for (int kc = 0; kc < 4; kc++) {
                uint32_t off = (uint32_t)(krow * AT_LD + kc * 16 + l8) * 2;
                uint32_t th[4], tl[4];
                ldm_x4(th, uK_h + off);
                ldm_x4(tl, uK_l + off);
                uint32_t bh0[2] = {th[0], th[1]}, bh1[2] = {th[2], th[3]};
                uint32_t bl0[2] = {tl[0], tl[1]}, bl1[2] = {tl[2], tl[3]};
                mma_bf16(sS[2 * ntp],     qh[kc], bh0);
                mma_bf16(sS[2 * ntp],     qh[kc], bl0);
                mma_bf16(sS[2 * ntp],     ql[kc], bh0);
                mma_bf16(sS[2 * ntp + 1], qh[kc], bh1);
                mma_bf16(sS[2 * ntp + 1], qh[kc], bl1);
                mma_bf16(sS[2 * ntp + 1], ql[kc], bh1);
            }
        }

        // ---- causal mask ----
        if (kv0 + 63 > q0 + row0) {
            int r0g = q0 + row0 + g;
            #pragma unroll
            for (int nt = 0; nt < 8; nt++) {
                int c0 = kv0 + nt * 8 + 2 * tig;
                if (c0 > r0g)     sS[nt][0] = -1e30f;
                if (c0 + 1 > r0g) sS[nt][1] = -1e30f;
                if (c0 > r0g + 8)     sS[nt][2] = -1e30f;
                if (c0 + 1 > r0g + 8) sS[nt][3] = -1e30f;
            }
        }

        // ---- online softmax (rows g and g+8) ----
        float rm0 = -1e30f, rm1 = -1e30f;
        #pragma unroll
        for (int nt = 0; nt < 8; nt++) {
            rm0 = fmaxf(rm0, fmaxf(sS[nt][0], sS[nt][1]));
            rm1 = fmaxf(rm1, fmaxf(sS[nt][2], sS[nt][3]));
        }
        rm0 = fmaxf(rm0, __shfl_xor_sync(0xffffffffu, rm0, 1));
        rm0 = fmaxf(rm0, __shfl_xor_sync(0xffffffffu, rm0, 2));
        rm1 = fmaxf(rm1, __shfl_xor_sync(0xffffffffu, rm1, 1));
        rm1 = fmaxf(rm1, __shfl_xor_sync(0xffffffffu, rm1, 2));
        float nm0 = fmaxf(m0, rm0), nm1 = fmaxf(m1, rm1);
        float a0 = __expf(m0 - nm0), a1 = __expf(m1 - nm1);
        float rs0 = 0.f, rs1 = 0.f;
        #pragma unroll
        for (int nt = 0; nt < 8; nt++) {
            sS[nt][0] = __expf(sS[nt][0] - nm0);
            sS[nt][1] = __expf(sS[nt][1] - nm0);
            sS[nt][2] = __expf(sS[nt][2] - nm1);
            sS[nt][3] = __expf(sS[nt][3] - nm1);
            rs0 += sS[nt][0] + sS[nt][1];
            rs1 += sS[nt][2] + sS[nt][3];
        }
        rs0 += __shfl_xor_sync(0xffffffffu, rs0, 1);
        rs0 += __shfl_xor_sync(0xffffffffu, rs0, 2);
        rs1 += __shfl_xor_sync(0xffffffffu, rs1, 1);
        rs1 += __shfl_xor_sync(0xffffffffu, rs1, 2);
        l0 = l0 * a0 + rs0; l1 = l1 * a1 + rs1;
        m0 = nm0; m1 = nm1;
        #pragma unroll
        for (int nt = 0; nt < 8; nt++) {
            o[nt][0] *= a0; o[nt][1] *= a0;
            o[nt][2] *= a1; o[nt][3] *= a1;
        }

        // ---- pack P as A-fragments (hi/lo) ----
        uint32_t pah[4][4], pal[4][4];
        #pragma unroll
        for (int kc2 = 0; kc2 < 4; kc2++) {
            #pragma unroll
            for (int e = 0; e < 4; e++) {
                int nt = 2 * kc2 + (e >> 1);
                int j0 = (e & 1) ? 2 : 0;
                bf16 h0, lo0, h1, lo1;
                split_bf16(sS[nt][j0], h0, lo0);
                split_bf16(sS[nt][j0 + 1], h1, lo1);
                pah[kc2][e] = pack2(h0, h1);
                pal[kc2][e] = pack2(lo0, lo1);
            }
        }

        // ---- O += P @ V ----
        #pragma unroll
        for (int dn = 0; dn < 4; dn++) {
            #pragma unroll
            for (int kc2 = 0; kc2 < 4; kc2++) {
                int vrow = kc2 * 16 + lr + l8;
                uint32_t off = (uint32_t)(vrow * AT_LD + dn * 16 + l16) * 2;
                uint32_t th[4], tl[4];
                ldm_x4_t(th, uV_h + off);
                ldm_x4_t(tl, uV_l + off);
                uint32_t bh0[2] = {th[0], th[1]}, bh1[2] = {th[2], th[3]};
                uint32_t bl0[2] = {tl[0], tl[1]}, bl1[2] = {tl[2], tl[3]};
                mma_bf16(o[2 * dn],     pah[kc2], bh0);
                mma_bf16(o[2 * dn],     pah[kc2], bl0);
                mma_bf16(o[2 * dn],     pal[kc2], bh0);
                mma_bf16(o[2 * dn + 1], pah[kc2], bh1);
                mma_bf16(o[2 * dn + 1], pah[kc2], bl1);
                mma_bf16(o[2 * dn + 1], pal[kc2], bh1);
            }
        }
        __syncthreads();
    }

    // ---- write ctx (bf16 hi/lo) ----
    float inv0 = 1.0f / l0, inv1 = 1.0f / l1;
    size_t r0o = ((size_t)b * S_ + q0 + row0 + g) * D_ + h * HD_;
    size_t r1o = r0o + (size_t)8 * D_;
    #pragma unroll
    for (int nt = 0; nt < 8; nt++) {
        int col = nt * 8 + 2 * tig;
        bf16 h0, lo0, h1, lo1;
        split_bf16(o[nt][0] * inv0, h0, lo0);
        split_bf16(o[nt][1] * inv0, h1, lo1);
        *reinterpret_cast<uint32_t*>(ctx_hi + r0o + col) = pack2(h0, h1);
        *reinterpret_cast<uint32_t*>(ctx_lo + r0o + col) = pack2(lo0, lo1);
        split_bf16(o[nt][2] * inv1, h0, lo0);
        split_bf16(o[nt][3] * inv1, h1, lo1);
        *reinterpret_cast<uint32_t*>(ctx_hi + r1o + col) = pack2(h0, h1);
        *reinterpret_cast<uint32_t*>(ctx_lo + r1o + col) = pack2(lo0, lo1);
    }
}

// ---------------------------------------------------------------------------
// launch
// ---------------------------------------------------------------------------
extern "C" void kernel_launch(void* const* d_in, const int* in_sizes, int n_in,
                              void* d_out, int out_size) {
    const float* x        = (const float*)d_in[0];
    const float* ln1_g    = (const float*)d_in[1];
    const float* ln1_b    = (const float*)d_in[2];
    const float* c_attn_w = (const float*)d_in[3];
    const float* c_attn_b = (const float*)d_in[4];
    const float* c_proj_w = (const float*)d_in[5];
    const float* c_proj_b = (const float*)d_in[6];
    const float* ln2_g    = (const float*)d_in[7];
    const float* ln2_b    = (const float*)d_in[8];
    const float* fc_w     = (const float*)d_in[9];
    const float* fc_b     = (const float*)d_in[10];
    const float* proj_w   = (const float*)d_in[11];
    const float* proj_b   = (const float*)d_in[12];
    float* out = (float*)d_out;

    cudaFuncSetAttribute(tc_gemm<0>, cudaFuncAttributeMaxDynamicSharedMemorySize, SMEM_GEMM);
    cudaFuncSetAttribute(tc_gemm<1>, cudaFuncAttributeMaxDynamicSharedMemorySize, SMEM_GEMM);
    cudaFuncSetAttribute(tc_gemm<2>, cudaFuncAttributeMaxDynamicSharedMemorySize, SMEM_GEMM);
    cudaFuncSetAttribute(attn_kernel, cudaFuncAttributeMaxDynamicSharedMemorySize, SMEM_ATTN);

    bf16 *h_hi, *h_lo, *qkv_hi, *qkv_lo, *ctx_hi, *ctx_lo, *h2_hi, *h2_lo, *ff_hi, *ff_lo;
    bf16 *wqkv_hi, *wqkv_lo, *wpr_hi, *wpr_lo, *wfc_hi, *wfc_lo, *wp2_hi, *wp2_lo;
    float *h1;
    cudaGetSymbolAddress((void**)&h_hi, g_h_hi);   cudaGetSymbolAddress((void**)&h_lo, g_h_lo);
    cudaGetSymbolAddress((void**)&qkv_hi, g_qkv_hi); cudaGetSymbolAddress((void**)&qkv_lo, g_qkv_lo);
    cudaGetSymbolAddress((void**)&ctx_hi, g_ctx_hi); cudaGetSymbolAddress((void**)&ctx_lo, g_ctx_lo);
    cudaGetSymbolAddress((void**)&h1, g_h1);
    cudaGetSymbolAddress((void**)&h2_hi, g_h2_hi); cudaGetSymbolAddress((void**)&h2_lo, g_h2_lo);
    cudaGetSymbolAddress((void**)&ff_hi, g_ff_hi); cudaGetSymbolAddress((void**)&ff_lo, g_ff_lo);
    cudaGetSymbolAddress((void**)&wqkv_hi, g_wqkv_hi); cudaGetSymbolAddress((void**)&wqkv_lo, g_wqkv_lo);
    cudaGetSymbolAddress((void**)&wpr_hi, g_wpr_hi);   cudaGetSymbolAddress((void**)&wpr_lo, g_wpr_lo);
    cudaGetSymbolAddress((void**)&wfc_hi, g_wfc_hi);   cudaGetSymbolAddress((void**)&wfc_lo, g_wfc_lo);
    cudaGetSymbolAddress((void**)&wp2_hi, g_wp2_hi);   cudaGetSymbolAddress((void**)&wp2_lo, g_wp2_lo);

    dim3 tb(32, 8);
    wconv_kernel<<<dim3(3 * D_ / 32, D_ / 32), tb>>>(c_attn_w, wqkv_hi, wqkv_lo, D_, 3 * D_);
    wconv_kernel<<<dim3(D_ / 32, D_ / 32), tb>>>(c_proj_w, wpr_hi, wpr_lo, D_, D_);
    wconv_kernel<<<dim3(4 * D_ / 32, D_ / 32), tb>>>(fc_w, wfc_hi, wfc_lo, D_, 4 * D_);
    wconv_kernel<<<dim3(D_ / 32, 4 * D_ / 32), tb>>>(proj_w, wp2_hi, wp2_lo, 4 * D_, D_);

    // 1. h = LN1(x)
    ln_kernel<<<M_, 256>>>(x, ln1_g, ln1_b, h_hi, h_lo);
    // 2. qkv = h @ Wqkv + b  -> bf16 hi/lo
    tc_gemm<0><<<dim3(3 * D_ / 128, M_ / 128), 256, SMEM_GEMM>>>(
        h_hi, h_lo, wqkv_hi, wqkv_lo, c_attn_b, nullptr, nullptr, qkv_hi, qkv_lo,
        3 * D_, D_);
    // 3. attention -> ctx bf16 pair (tensor cores)
    attn_kernel<<<dim3(S_ / 128, H_, B_), 256, SMEM_ATTN>>>(qkv_hi, qkv_lo, ctx_hi, ctx_lo);
    // 4. h1 = x + ctx @ Wproj + b  (fp32 out)
    tc_gemm<2><<<dim3(D_ / 128, M_ / 128), 256, SMEM_GEMM>>>(
        ctx_hi, ctx_lo, wpr_hi, wpr_lo, c_proj_b, x, h1, nullptr, nullptr,
        D_, D_);
    // 5. h2 = LN2(h1)
    ln_kernel<<<M_, 256>>>(h1, ln2_g, ln2_b, h2_hi, h2_lo);
    // 6. ff = gelu(h2 @ fc_w + fc_b)  (bf16 pair out)
    tc_gemm<1><<<dim3(4 * D_ / 128, M_ / 128), 256, SMEM_GEMM>>>(
        h2_hi, h2_lo, wfc_hi, wfc_lo, fc_b, nullptr, nullptr, ff_hi, ff_lo,
        4 * D_, D_);
    // 7. out = h1 + ff @ proj_w + proj_b  (fp32 out)
    tc_gemm<2><<<dim3(D_ / 128, M_ / 128), 256, SMEM_GEMM>>>(
        ff_hi, ff_lo, wp2_hi, wp2_lo, proj_b, h1, out, nullptr, nullptr,
        D_, 4 * D_);
}

// round 9
// speedup vs baseline: 3.7303x; 1.3084x over previous
#include <cuda_runtime.h>
#include <cuda_bf16.h>
#include <cuda_fp16.h>
#include <cstdint>
#include <math.h>

// ---------------------------------------------------------------------------
// GPT-2 block: B=8, S=1024, D=1024, H=16, Hd=64
// ---------------------------------------------------------------------------
#define B_ 8
#define S_ 1024
#define D_ 1024
#define H_ 16
#define HD_ 64
#define M_ (B_ * S_)          // 8192 rows

typedef __nv_bfloat16 bf16;
typedef __nv_bfloat162 bf162;

// Scratch (device globals; no allocation allowed in kernel_launch)
__device__ __half g_h_hi [M_ * D_],     g_h_lo [M_ * D_];
__device__ bf16   g_qkv_hi[M_ * 3 * D_], g_qkv_lo[M_ * 3 * D_];
__device__ __half g_ctx_hi[M_ * D_],    g_ctx_lo[M_ * D_];
__device__ float  g_h1   [M_ * D_];
__device__ __half g_h2_hi[M_ * D_],     g_h2_lo[M_ * D_];
__device__ __half g_ff_hi[M_ * 4 * D_], g_ff_lo[M_ * 4 * D_];
// transposed weights [N, K] fp16 (hi only)
__device__ __half g_wqkv[3 * D_ * D_];
__device__ __half g_wpr [D_ * D_];
__device__ __half g_wfc [4 * D_ * D_];
__device__ __half g_wp2 [4 * D_ * D_];

// ---------------------------------------------------------------------------
// helpers
// ---------------------------------------------------------------------------
__device__ __forceinline__ uint32_t smem_u32(const void* p) {
    uint32_t a;
    asm("{ .reg .u64 t; cvta.to.shared.u64 t, %1; cvt.u32.u64 %0, t; }"
        : "=r"(a) : "l"(p));
    return a;
}
__device__ __forceinline__ void cp16(uint32_t dst, const void* src) {
    asm volatile("cp.async.ca.shared.global [%0], [%1], 16;"
                 :: "r"(dst), "l"(src) : "memory");
}
__device__ __forceinline__ void cp_commit() {
    asm volatile("cp.async.commit_group;" ::: "memory");
}
template <int N>
__device__ __forceinline__ void cp_wait() {
    asm volatile("cp.async.wait_group %0;" :: "n"(N) : "memory");
}
__device__ __forceinline__ void mma_bf16(float* d, const uint32_t* a, const uint32_t* b) {
    asm volatile(
        "mma.sync.aligned.m16n8k16.row.col.f32.bf16.bf16.f32 "
        "{%0,%1,%2,%3}, {%4,%5,%6,%7}, {%8,%9}, {%0,%1,%2,%3};"
        : "+f"(d[0]), "+f"(d[1]), "+f"(d[2]), "+f"(d[3])
        : "r"(a[0]), "r"(a[1]), "r"(a[2]), "r"(a[3]), "r"(b[0]), "r"(b[1]));
}
__device__ __forceinline__ void mma_f16(float* d, const uint32_t* a, const uint32_t* b) {
    asm volatile(
        "mma.sync.aligned.m16n8k16.row.col.f32.f16.f16.f32 "
        "{%0,%1,%2,%3}, {%4,%5,%6,%7}, {%8,%9}, {%0,%1,%2,%3};"
        : "+f"(d[0]), "+f"(d[1]), "+f"(d[2]), "+f"(d[3])
        : "r"(a[0]), "r"(a[1]), "r"(a[2]), "r"(a[3]), "r"(b[0]), "r"(b[1]));
}
__device__ __forceinline__ void ldm_x4(uint32_t* r, uint32_t addr) {
    asm volatile("ldmatrix.sync.aligned.m8n8.x4.shared.b16 {%0,%1,%2,%3}, [%4];"
                 : "=r"(r[0]), "=r"(r[1]), "=r"(r[2]), "=r"(r[3]) : "r"(addr));
}
__device__ __forceinline__ void ldm_x4_t(uint32_t* r, uint32_t addr) {
    asm volatile("ldmatrix.sync.aligned.m8n8.x4.trans.shared.b16 {%0,%1,%2,%3}, [%4];"
                 : "=r"(r[0]), "=r"(r[1]), "=r"(r[2]), "=r"(r[3]) : "r"(addr));
}
__device__ __forceinline__ float gelu_new(float x) {
    float x3 = x * x * x;
    return 0.5f * x * (1.0f + tanhf(0.7978845608028654f * (x + 0.044715f * x3)));
}
__device__ __forceinline__ void split_bf16(float v, bf16& hi, bf16& lo) {
    hi = __float2bfloat16(v);
    lo = __float2bfloat16(v - __bfloat162float(hi));
}
__device__ __forceinline__ void split_f16(float v, __half& hi, __half& lo) {
    hi = __float2half_rn(v);
    lo = __float2half_rn(v - __half2float(hi));
}
__device__ __forceinline__ uint32_t pack2(bf16 a, bf16 b) {
    bf162 t{a, b};
    return *reinterpret_cast<uint32_t*>(&t);
}
__device__ __forceinline__ uint32_t pack2h(__half a, __half b) {
    __half2 t{a, b};
    return *reinterpret_cast<uint32_t*>(&t);
}

// ---------------------------------------------------------------------------
// Weight convert: W[K,N] fp32 -> Wt[N,K] fp16 (tiled transpose)
// ---------------------------------------------------------------------------
__global__ void wconv_kernel(const float* __restrict__ W,
                             __half* __restrict__ T_, int K, int N) {
    __shared__ float t[32][33];
    int n0 = blockIdx.x * 32, k0 = blockIdx.y * 32;
    int tx = threadIdx.x, ty = threadIdx.y;
    #pragma unroll
    for (int j = 0; j < 4; j++)
        t[ty + j * 8][tx] = W[(size_t)(k0 + ty + j * 8) * N + n0 + tx];
    __syncthreads();
    #pragma unroll
    for (int j = 0; j < 4; j++) {
        int nl = ty + j * 8;
        T_[(size_t)(n0 + nl) * K + k0 + tx] = __float2half_rn(t[tx][nl]);
    }
}

// ---------------------------------------------------------------------------
// LayerNorm -> fp16 hi/lo pair output
// ---------------------------------------------------------------------------
__global__ void ln_kernel(const float* __restrict__ x,
                          const float* __restrict__ g,
                          const float* __restrict__ b,
                          __half* __restrict__ oh, __half* __restrict__ ol) {
    __shared__ float red[8];
    int row = blockIdx.x;
    int tid = threadIdx.x;
    const float4* xr = reinterpret_cast<const float4*>(x + (size_t)row * D_);
    float4 v = xr[tid];

    float s = v.x + v.y + v.z + v.w;
    #pragma unroll
    for (int o = 16; o; o >>= 1) s += __shfl_xor_sync(0xffffffffu, s, o);
    if ((tid & 31) == 0) red[tid >> 5] = s;
    __syncthreads();
    float tot = 0.f;
    #pragma unroll
    for (int i = 0; i < 8; i++) tot += red[i];
    float mu = tot * (1.0f / D_);
    __syncthreads();

    float dx = v.x - mu, dy = v.y - mu, dz = v.z - mu, dw = v.w - mu;
    float q = dx * dx + dy * dy + dz * dz + dw * dw;
    #pragma unroll
    for (int o = 16; o; o >>= 1) q += __shfl_xor_sync(0xffffffffu, q, o);
    if ((tid & 31) == 0) red[tid >> 5] = q;
    __syncthreads();
    float qtot = 0.f;
    #pragma unroll
    for (int i = 0; i < 8; i++) qtot += red[i];
    float rstd = rsqrtf(qtot * (1.0f / D_) + 1e-5f);

    const float4 g4 = reinterpret_cast<const float4*>(g)[tid];
    const float4 b4 = reinterpret_cast<const float4*>(b)[tid];
    float o0 = dx * rstd * g4.x + b4.x;
    float o1 = dy * rstd * g4.y + b4.y;
    float o2 = dz * rstd * g4.z + b4.z;
    float o3 = dw * rstd * g4.w + b4.w;

    __half h0, l0, h1, l1, h2, l2, h3, l3;
    split_f16(o0, h0, l0); split_f16(o1, h1, l1);
    split_f16(o2, h2, l2); split_f16(o3, h3, l3);
    size_t base = (size_t)row * D_ + tid * 4;
    uint32_t* ohp = reinterpret_cast<uint32_t*>(oh + base);
    uint32_t* olp = reinterpret_cast<uint32_t*>(ol + base);
    ohp[0] = pack2h(h0, h1); ohp[1] = pack2h(h2, h3);
    olp[0] = pack2h(l0, l1); olp[1] = pack2h(l2, l3);
}

// ---------------------------------------------------------------------------
// fp16 2-term tensor GEMM via mma.sync.m16n8k16 + ldmatrix.
// C[M,N] = A[M,K] @ W[K,N],  A = Ah + Al (fp16 pair, [M,K]), W = Wt[N,K] fp16.
// Terms: ah*b + al*b (weight lo dropped; rel err ~2^-12).
// CTA tile 128x128, BK=32, 3-stage cp.async pipeline, 8 warps (2x4),
// warp tile 64x32, 2 CTAs/SM (92KB smem x2), one barrier per chunk.
// EPI: 0 = +bias -> bf16 pair ; 1 = gelu(+bias) -> fp16 pair ;
//      2 = +bias+res -> fp32
// ---------------------------------------------------------------------------
#define BK_ 32
#define T_LD 40                     // smem row stride in halfwords (80 B)
#define TILE_BYTES (128 * T_LD * 2) // 10240
#define STAGE_BYTES (3 * TILE_BYTES) // 30720
#define SMEM_GEMM (3 * STAGE_BYTES)  // 92160

template <int EPI>
__global__ __launch_bounds__(256, 2)
void tc_gemm(const __half* __restrict__ Ah, const __half* __restrict__ Al,
             const __half* __restrict__ Bh,
             const float* __restrict__ bias, const float* __restrict__ res,
             float* __restrict__ C, void* __restrict__ Cho, void* __restrict__ Clo,
             int N, int K) {
    extern __shared__ char dsm[];
    const uint32_t sbase = smem_u32(dsm);
    const int tid  = threadIdx.x;
    const int lane = tid & 31;
    const int wid  = tid >> 5;
    const int g    = lane >> 2;
    const int tig  = lane & 3;
    const int mrow = (wid >> 2) * 64;
    const int ncol = (wid & 3) * 32;
    const int cCol = blockIdx.x, cRow = blockIdx.y;
    const int NC = K / BK_;
    const int lr  = lane & 7;
    const int l8  = (lane & 8) ? 8 : 0;
    const int l16 = (lane & 16) ? 8 : 0;

    const __half* srcs[3] = {
        Ah + (size_t)cRow * 128 * K, Al + (size_t)cRow * 128 * K,
        Bh + (size_t)cCol * 128 * K};

    auto load_stage = [&](int chunk, int s) {
        const int kk = chunk * BK_;
        const uint32_t st = sbase + s * STAGE_BYTES;
        #pragma unroll
        for (int t = 0; t < 3; t++) {
            const __half* src = srcs[t];
            #pragma unroll
            for (int i = 0; i < 2; i++) {
                int idx = tid + i * 256;
                int r = idx >> 2, ci = idx & 3;
                cp16(st + t * TILE_BYTES + r * 80 + ci * 16,
                     src + (size_t)r * K + kk + ci * 8);
            }
        }
    };

    float acc[4][4][4];
    #pragma unroll
    for (int i = 0; i < 4; i++)
        #pragma unroll
        for (int j = 0; j < 4; j++)
            #pragma unroll
            for (int r = 0; r < 4; r++) acc[i][j][r] = 0.f;

    load_stage(0, 0); cp_commit();
    load_stage(1, 1); cp_commit();

    for (int c = 0; c < NC; c++) {
        cp_wait<1>();
        __syncthreads();
        if (c + 2 < NC) load_stage(c + 2, (c + 2) % 3);
        cp_commit();

        const uint32_t ust = sbase + (c % 3) * STAGE_BYTES;
        const uint32_t uAh = ust;
        const uint32_t uAl = ust + TILE_BYTES;
        const uint32_t uBh = ust + 2 * TILE_BYTES;

        #pragma unroll
        for (int ks = 0; ks < 2; ks++) {
            const int k0 = ks * 16;
            uint32_t ah[4][4], bh[4][2];
            #pragma unroll
            for (int mt = 0; mt < 4; mt++) {
                int row = mrow + mt * 16 + lr + l8;
                ldm_x4(ah[mt], uAh + (uint32_t)(row * T_LD + k0 + l16) * 2);
            }
            #pragma unroll
            for (int ntp = 0; ntp < 2; ntp++) {
                int row = ncol + ntp * 16 + lr + l16;
                uint32_t t4[4];
                ldm_x4(t4, uBh + (uint32_t)(row * T_LD + k0 + l8) * 2);
                bh[2 * ntp][0] = t4[0]; bh[2 * ntp][1] = t4[1];
                bh[2 * ntp + 1][0] = t4[2]; bh[2 * ntp + 1][1] = t4[3];
            }
            #pragma unroll
            for (int mt = 0; mt < 4; mt++)
                #pragma unroll
                for (int nt = 0; nt < 4; nt++)
                    mma_f16(acc[mt][nt], ah[mt], bh[nt]);
            // term 2: al * bh (reload A-lo fragments into same regs)
            #pragma unroll
            for (int mt = 0; mt < 4; mt++) {
                int row = mrow + mt * 16 + lr + l8;
                ldm_x4(ah[mt], uAl + (uint32_t)(row * T_LD + k0 + l16) * 2);
            }
            #pragma unroll
            for (int mt = 0; mt < 4; mt++)
                #pragma unroll
                for (int nt = 0; nt < 4; nt++)
                    mma_f16(acc[mt][nt], ah[mt], bh[nt]);
        }
    }

    // ---- epilogue ----
    const int row_base = cRow * 128 + mrow;
    const int col_base = cCol * 128 + ncol;
    #pragma unroll
    for (int mt = 0; mt < 4; mt++) {
        #pragma unroll
        for (int nt = 0; nt < 4; nt++) {
            int cc = col_base + nt * 8 + tig * 2;
            float b0 = bias[cc], b1 = bias[cc + 1];
            #pragma unroll
            for (int half = 0; half < 2; half++) {
                int r = row_base + mt * 16 + g + half * 8;
                size_t off = (size_t)r * N + cc;
                float v0 = acc[mt][nt][half * 2 + 0] + b0;
                float v1 = acc[mt][nt][half * 2 + 1] + b1;
                if (EPI == 0) {
                    bf16 h0, l0, h1, l1;
                    split_bf16(v0, h0, l0);
                    split_bf16(v1, h1, l1);
                    reinterpret_cast<uint32_t*>((bf16*)Cho + off)[0] = pack2(h0, h1);
                    reinterpret_cast<uint32_t*>((bf16*)Clo + off)[0] = pack2(l0, l1);
                } else if (EPI == 1) {
                    v0 = gelu_new(v0); v1 = gelu_new(v1);
                    __half h0, l0, h1, l1;
                    split_f16(v0, h0, l0);
                    split_f16(v1, h1, l1);
                    reinterpret_cast<uint32_t*>((__half*)Cho + off)[0] = pack2h(h0, h1);
                    reinterpret_cast<uint32_t*>((__half*)Clo + off)[0] = pack2h(l0, l1);
                } else {
                    float2 rr = *reinterpret_cast<const float2*>(res + off);
                    v0 += rr.x; v1 += rr.y;
                    *reinterpret_cast<float2*>(C + off) = make_float2(v0, v1);
                }
            }
        }
    }
}

// ---------------------------------------------------------------------------
// Tensor-core flash attention (bf16 3-term, unchanged math).
// Inputs: qkv bf16 hi/lo; outputs: ctx fp16 hi/lo.
// ---------------------------------------------------------------------------
#define AT_LD 72
#define AT_ARR (64 * AT_LD)                 // elems per array (4608)
#define AT_STAGE (4 * AT_ARR)               // elems per stage (18432)
#define SMEM_ATTN (2 * AT_STAGE * 2)        // bytes: 73728

__global__ __launch_bounds__(256, 1)
void attn_kernel(const bf16* __restrict__ qkvh, const bf16* __restrict__ qkvl,
                 __half* __restrict__ ctx_hi, __half* __restrict__ ctx_lo) {
    extern __shared__ char dsm[];
    const uint32_t usm = smem_u32(dsm);

    const int qt = blockIdx.x;
    const int h  = blockIdx.y;
    const int b  = blockIdx.z;
    const int tid = threadIdx.x;
    const int wid = tid >> 5;
    const int lane = tid & 31;
    const int g   = lane >> 2;
    const int tig = lane & 3;
    const int lr  = lane & 7;
    const int l8  = (lane & 8) ? 8 : 0;
    const int l16 = (lane & 16) ? 8 : 0;

    const int q0 = qt * 128;
    const int row0 = wid * 16;
    const int LD3 = 3 * D_;
    const size_t bbase = (size_t)b * S_ * LD3 + h * HD_;

    // ---- load Q fragments (scaled by 1/8, exact on bf16) ----
    uint32_t qh[4][4], ql[4][4];
    {
        const bf162 s8 = __floats2bfloat162_rn(0.125f, 0.125f);
        const size_t r0a = bbase + (size_t)(q0 + row0 + g) * LD3;
        const size_t r1a = r0a + (size_t)8 * LD3;
        #pragma unroll
        for (int kc = 0; kc < 4; kc++) {
            int col = kc * 16 + 2 * tig;
            #pragma unroll
            for (int e = 0; e < 4; e++) {
                size_t a = ((e & 1) ? r1a : r0a) + col + ((e & 2) ? 8 : 0);
                bf162 vh = *reinterpret_cast<const bf162*>(qkvh + a);
                bf162 vl = *reinterpret_cast<const bf162*>(qkvl + a);
                vh = __hmul2(vh, s8);
                vl = __hmul2(vl, s8);
                qh[kc][e] = *reinterpret_cast<uint32_t*>(&vh);
                ql[kc][e] = *reinterpret_cast<uint32_t*>(&vl);
            }
        }
    }

    auto load_tile = [&](int kt, int s) {
        const int kv0 = kt * 64;
        #pragma unroll
        for (int i = 0; i < 2; i++) {
            int c = tid + i * 256;
            int r = c >> 3, c8 = (c & 7) * 8;
            size_t src = bbase + (size_t)(kv0 + r) * LD3 + c8;
            uint32_t dst = usm + (uint32_t)(s * AT_STAGE + r * AT_LD + c8) * 2;
            cp16(dst,                      qkvh + src + D_);       // K hi
            cp16(dst + AT_ARR * 2,         qkvl + src + D_);       // K lo
            cp16(dst + 2 * AT_ARR * 2,     qkvh + src + 2 * D_);   // V hi
            cp16(dst + 3 * AT_ARR * 2,     qkvl + src + 2 * D_);   // V lo
        }
    };

    float o[8][4];
    #pragma unroll
    for (int i = 0; i < 8; i++)
        #pragma unroll
        for (int j = 0; j < 4; j++) o[i][j] = 0.f;
    float m0 = -INFINITY, m1 = -INFINITY, l0 = 0.f, l1 = 0.f;

    const int ktmax = 2 * qt + 1;
    load_tile(0, 0); cp_commit();

    for (int kt = 0; kt <= ktmax; kt++) {
        const int s = kt & 1;
        const int kv0 = kt * 64;
        if (kt < ktmax) { load_tile(kt + 1, s ^ 1); cp_commit(); cp_wait<1>(); }
        else            { cp_wait<0>(); }
        __syncthreads();

        const uint32_t uK_h = usm + (uint32_t)(s * AT_STAGE) * 2;
        const uint32_t uK_l = uK_h + AT_ARR * 2;
        const uint32_t uV_h = uK_h + 2 * AT_ARR * 2;
        const uint32_t uV_l = uK_h + 3 * AT_ARR * 2;

        float sS[8][4];
        #pragma unroll
        for (int i = 0; i < 8; i++)
            #pragma unroll
            for (int j = 0; j < 4; j++) sS[i][j] = 0.f;

        #pragma unroll
        for (int ntp = 0; ntp < 4; ntp++) {
            int krow = ntp * 16 + lr + l16;
            #pragma unroll
            for (int kc = 0; kc < 4; kc++) {
                uint32_t off = (uint32_t)(krow * AT_LD + kc * 16 + l8) * 2;
                uint32_t th[4], tl[4];
                ldm_x4(th, uK_h + off);
                ldm_x4(tl, uK_l + off);
                uint32_t bh0[2] = {th[0], th[1]}, bh1[2] = {th[2], th[3]};
                uint32_t bl0[2] = {tl[0], tl[1]}, bl1[2] = {tl[2], tl[3]};
                mma_bf16(sS[2 * ntp],     qh[kc], bh0);
                mma_bf16(sS[2 * ntp],     qh[kc], bl0);
                mma_bf16(sS[2 * ntp],     ql[kc], bh0);
                mma_bf16(sS[2 * ntp + 1], qh[kc], bh1);
                mma_bf16(sS[2 * ntp + 1], qh[kc], bl1);
                mma_bf16(sS[2 * ntp + 1], ql[kc], bh1);
            }
        }

        if (kv0 + 63 > q0 + row0) {
            int r0g = q0 + row0 + g;
            #pragma unroll
            for (int nt = 0; nt < 8; nt++) {
                int c0 = kv0 + nt * 8 + 2 * tig;
                if (c0 > r0g)     sS[nt][0] = -1e30f;
                if (c0 + 1 > r0g) sS[nt][1] = -1e30f;
                if (c0 > r0g + 8)     sS[nt][2] = -1e30f;
                if (c0 + 1 > r0g + 8) sS[nt][3] = -1e30f;
            }
        }

        float rm0 = -1e30f, rm1 = -1e30f;
        #pragma unroll
        for (int nt = 0; nt < 8; nt++) {
            rm0 = fmaxf(rm0, fmaxf(sS[nt][0], sS[nt][1]));
            rm1 = fmaxf(rm1, fmaxf(sS[nt][2], sS[nt][3]));
        }
        rm0 = fmaxf(rm0, __shfl_xor_sync(0xffffffffu, rm0, 1));
        rm0 = fmaxf(rm0, __shfl_xor_sync(0xffffffffu, rm0, 2));
        rm1 = fmaxf(rm1, __shfl_xor_sync(0xffffffffu, rm1, 1));
        rm1 = fmaxf(rm1, __shfl_xor_sync(0xffffffffu, rm1, 2));
        float nm0 = fmaxf(m0, rm0), nm1 = fmaxf(m1, rm1);
        float a0 = __expf(m0 - nm0), a1 = __expf(m1 - nm1);
        float rs0 = 0.f, rs1 = 0.f;
        #pragma unroll
        for (int nt = 0; nt < 8; nt++) {
            sS[nt][0] = __expf(sS[nt][0] - nm0);
            sS[nt][1] = __expf(sS[nt][1] - nm0);
            sS[nt][2] = __expf(sS[nt][2] - nm1);
            sS[nt][3] = __expf(sS[nt][3] - nm1);
            rs0 += sS[nt][0] + sS[nt][1];
            rs1 += sS[nt][2] + sS[nt][3];
        }
        rs0 += __shfl_xor_sync(0xffffffffu, rs0, 1);
        rs0 += __shfl_xor_sync(0xffffffffu, rs0, 2);
        rs1 += __shfl_xor_sync(0xffffffffu, rs1, 1);
        rs1 += __shfl_xor_sync(0xffffffffu, rs1, 2);
        l0 = l0 * a0 + rs0; l1 = l1 * a1 + rs1;
        m0 = nm0; m1 = nm1;
        #pragma unroll
        for (int nt = 0; nt < 8; nt++) {
            o[nt][0] *= a0; o[nt][1] *= a0;
            o[nt][2] *= a1; o[nt][3] *= a1;
        }

        uint32_t pah[4][4], pal[4][4];
        #pragma unroll
        for (int kc2 = 0; kc2 < 4; kc2++) {
            #pragma unroll
            for (int e = 0; e < 4; e++) {
                int nt = 2 * kc2 + (e >> 1);
                int j0 = (e & 1) ? 2 : 0;
                bf16 h0, lo0, h1, lo1;
                split_bf16(sS[nt][j0], h0, lo0);
                split_bf16(sS[nt][j0 + 1], h1, lo1);
                pah[kc2][e] = pack2(h0, h1);
                pal[kc2][e] = pack2(lo0, lo1);
            }
        }

        #pragma unroll
        for (int dn = 0; dn < 4; dn++) {
            #pragma unroll
            for (int kc2 = 0; kc2 < 4; kc2++) {
                int vrow = kc2 * 16 + lr + l8;
                uint32_t off = (uint32_t)(vrow * AT_LD + dn * 16 + l16) * 2;
                uint32_t th[4], tl[4];
                ldm_x4_t(th, uV_h + off);
                ldm_x4_t(tl, uV_l + off);
                uint32_t bh0[2] = {th[0], th[1]}, bh1[2] = {th[2], th[3]};
                uint32_t bl0[2] = {tl[0], tl[1]}, bl1[2] = {tl[2], tl[3]};
                mma_bf16(o[2 * dn],     pah[kc2], bh0);
                mma_bf16(o[2 * dn],     pah[kc2], bl0);
                mma_bf16(o[2 * dn],     pal[kc2], bh0);
                mma_bf16(o[2 * dn + 1], pah[kc2], bh1);
                mma_bf16(o[2 * dn + 1], pah[kc2], bl1);
                mma_bf16(o[2 * dn + 1], pal[kc2], bh1);
            }
        }
        __syncthreads();
    }

    // ---- write ctx (fp16 hi/lo) ----
    float inv0 = 1.0f / l0, inv1 = 1.0f / l1;
    size_t r0o = ((size_t)b * S_ + q0 + row0 + g) * D_ + h * HD_;
    size_t r1o = r0o + (size_t)8 * D_;
    #pragma unroll
    for (int nt = 0; nt < 8; nt++) {
        int col = nt * 8 + 2 * tig;
        __half h0, lo0, h1, lo1;
        split_f16(o[nt][0] * inv0, h0, lo0);
        split_f16(o[nt][1] * inv0, h1, lo1);
        *reinterpret_cast<uint32_t*>(ctx_hi + r0o + col) = pack2h(h0, h1);
        *reinterpret_cast<uint32_t*>(ctx_lo + r0o + col) = pack2h(lo0, lo1);
        split_f16(o[nt][2] * inv1, h0, lo0);
        split_f16(o[nt][3] * inv1, h1, lo1);
        *reinterpret_cast<uint32_t*>(ctx_hi + r1o + col) = pack2h(h0, h1);
        *reinterpret_cast<uint32_t*>(ctx_lo + r1o + col) = pack2h(lo0, lo1);
    }
}

// ---------------------------------------------------------------------------
// launch
// ---------------------------------------------------------------------------
extern "C" void kernel_launch(void* const* d_in, const int* in_sizes, int n_in,
                              void* d_out, int out_size) {
    const float* x        = (const float*)d_in[0];
    const float* ln1_g    = (const float*)d_in[1];
    const float* ln1_b    = (const float*)d_in[2];
    const float* c_attn_w = (const float*)d_in[3];
    const float* c_attn_b = (const float*)d_in[4];
    const float* c_proj_w = (const float*)d_in[5];
    const float* c_proj_b = (const float*)d_in[6];
    const float* ln2_g    = (const float*)d_in[7];
    const float* ln2_b    = (const float*)d_in[8];
    const float* fc_w     = (const float*)d_in[9];
    const float* fc_b     = (const float*)d_in[10];
    const float* proj_w   = (const float*)d_in[11];
    const float* proj_b   = (const float*)d_in[12];
    float* out = (float*)d_out;

    cudaFuncSetAttribute(tc_gemm<0>, cudaFuncAttributeMaxDynamicSharedMemorySize, SMEM_GEMM);
    cudaFuncSetAttribute(tc_gemm<1>, cudaFuncAttributeMaxDynamicSharedMemorySize, SMEM_GEMM);
    cudaFuncSetAttribute(tc_gemm<2>, cudaFuncAttributeMaxDynamicSharedMemorySize, SMEM_GEMM);
    cudaFuncSetAttribute(attn_kernel, cudaFuncAttributeMaxDynamicSharedMemorySize, SMEM_ATTN);

    __half *h_hi, *h_lo, *ctx_hi, *ctx_lo, *h2_hi, *h2_lo, *ff_hi, *ff_lo;
    bf16 *qkv_hi, *qkv_lo;
    __half *wqkv, *wpr, *wfc, *wp2;
    float *h1;
    cudaGetSymbolAddress((void**)&h_hi, g_h_hi);   cudaGetSymbolAddress((void**)&h_lo, g_h_lo);
    cudaGetSymbolAddress((void**)&qkv_hi, g_qkv_hi); cudaGetSymbolAddress((void**)&qkv_lo, g_qkv_lo);
    cudaGetSymbolAddress((void**)&ctx_hi, g_ctx_hi); cudaGetSymbolAddress((void**)&ctx_lo, g_ctx_lo);
    cudaGetSymbolAddress((void**)&h1, g_h1);
    cudaGetSymbolAddress((void**)&h2_hi, g_h2_hi); cudaGetSymbolAddress((void**)&h2_lo, g_h2_lo);
    cudaGetSymbolAddress((void**)&ff_hi, g_ff_hi); cudaGetSymbolAddress((void**)&ff_lo, g_ff_lo);
    cudaGetSymbolAddress((void**)&wqkv, g_wqkv);
    cudaGetSymbolAddress((void**)&wpr, g_wpr);
    cudaGetSymbolAddress((void**)&wfc, g_wfc);
    cudaGetSymbolAddress((void**)&wp2, g_wp2);

    dim3 tb(32, 8);
    wconv_kernel<<<dim3(3 * D_ / 32, D_ / 32), tb>>>(c_attn_w, wqkv, D_, 3 * D_);
    wconv_kernel<<<dim3(D_ / 32, D_ / 32), tb>>>(c_proj_w, wpr, D_, D_);
    wconv_kernel<<<dim3(4 * D_ / 32, D_ / 32), tb>>>(fc_w, wfc, D_, 4 * D_);
    wconv_kernel<<<dim3(D_ / 32, 4 * D_ / 32), tb>>>(proj_w, wp2, 4 * D_, D_);

    // 1. h = LN1(x)  -> fp16 pair
    ln_kernel<<<M_, 256>>>(x, ln1_g, ln1_b, h_hi, h_lo);
    // 2. qkv = h @ Wqkv + b  -> bf16 pair (for attention)
    tc_gemm<0><<<dim3(3 * D_ / 128, M_ / 128), 256, SMEM_GEMM>>>(
        h_hi, h_lo, wqkv, c_attn_b, nullptr, nullptr, qkv_hi, qkv_lo,
        3 * D_, D_);
    // 3. attention -> ctx fp16 pair
    attn_kernel<<<dim3(S_ / 128, H_, B_), 256, SMEM_ATTN>>>(qkv_hi, qkv_lo, ctx_hi, ctx_lo);
    // 4. h1 = x + ctx @ Wproj + b  (fp32 out)
    tc_gemm<2><<<dim3(D_ / 128, M_ / 128), 256, SMEM_GEMM>>>(
        ctx_hi, ctx_lo, wpr, c_proj_b, x, h1, nullptr, nullptr,
        D_, D_);
    // 5. h2 = LN2(h1)  -> fp16 pair
    ln_kernel<<<M_, 256>>>(h1, ln2_g, ln2_b, h2_hi, h2_lo);
    // 6. ff = gelu(h2 @ fc_w + fc_b)  -> fp16 pair
    tc_gemm<1><<<dim3(4 * D_ / 128, M_ / 128), 256, SMEM_GEMM>>>(
        h2_hi, h2_lo, wfc, fc_b, nullptr, nullptr, ff_hi, ff_lo,
        4 * D_, D_);
    // 7. out = h1 + ff @ proj_w + proj_b  (fp32 out)
    tc_gemm<2><<<dim3(D_ / 128, M_ / 128), 256, SMEM_GEMM>>>(
        ff_hi, ff_lo, wp2, proj_b, h1, out, nullptr, nullptr,
        D_, 4 * D_);
}

// round 10
// speedup vs baseline: 3.9076x; 1.0475x over previous
#include <cuda_runtime.h>
#include <cuda_bf16.h>
#include <cuda_fp16.h>
#include <cstdint>
#include <math.h>

// ---------------------------------------------------------------------------
// GPT-2 block: B=8, S=1024, D=1024, H=16, Hd=64
// ---------------------------------------------------------------------------
#define B_ 8
#define S_ 1024
#define D_ 1024
#define H_ 16
#define HD_ 64
#define M_ (B_ * S_)          // 8192 rows

typedef __nv_bfloat16 bf16;

// Scratch (device globals; no allocation allowed in kernel_launch)
__device__ __half g_h_hi [M_ * D_],     g_h_lo [M_ * D_];
__device__ __half g_qkv_hi[M_ * 3 * D_], g_qkv_lo[M_ * 3 * D_];
__device__ __half g_ctx_hi[M_ * D_],    g_ctx_lo[M_ * D_];
__device__ float  g_h1   [M_ * D_];
__device__ __half g_h2_hi[M_ * D_],     g_h2_lo[M_ * D_];
__device__ __half g_ff_hi[M_ * 4 * D_], g_ff_lo[M_ * 4 * D_];
// transposed weights [N, K] fp16 (hi only)
__device__ __half g_wqkv[3 * D_ * D_];
__device__ __half g_wpr [D_ * D_];
__device__ __half g_wfc [4 * D_ * D_];
__device__ __half g_wp2 [4 * D_ * D_];

// ---------------------------------------------------------------------------
// helpers
// ---------------------------------------------------------------------------
__device__ __forceinline__ uint32_t smem_u32(const void* p) {
    uint32_t a;
    asm("{ .reg .u64 t; cvta.to.shared.u64 t, %1; cvt.u32.u64 %0, t; }"
        : "=r"(a) : "l"(p));
    return a;
}
__device__ __forceinline__ void cp16(uint32_t dst, const void* src) {
    asm volatile("cp.async.ca.shared.global [%0], [%1], 16;"
                 :: "r"(dst), "l"(src) : "memory");
}
__device__ __forceinline__ void cp_commit() {
    asm volatile("cp.async.commit_group;" ::: "memory");
}
template <int N>
__device__ __forceinline__ void cp_wait() {
    asm volatile("cp.async.wait_group %0;" :: "n"(N) : "memory");
}
__device__ __forceinline__ void mma_f16(float* d, const uint32_t* a, const uint32_t* b) {
    asm volatile(
        "mma.sync.aligned.m16n8k16.row.col.f32.f16.f16.f32 "
        "{%0,%1,%2,%3}, {%4,%5,%6,%7}, {%8,%9}, {%0,%1,%2,%3};"
        : "+f"(d[0]), "+f"(d[1]), "+f"(d[2]), "+f"(d[3])
        : "r"(a[0]), "r"(a[1]), "r"(a[2]), "r"(a[3]), "r"(b[0]), "r"(b[1]));
}
__device__ __forceinline__ void ldm_x4(uint32_t* r, uint32_t addr) {
    asm volatile("ldmatrix.sync.aligned.m8n8.x4.shared.b16 {%0,%1,%2,%3}, [%4];"
                 : "=r"(r[0]), "=r"(r[1]), "=r"(r[2]), "=r"(r[3]) : "r"(addr));
}
__device__ __forceinline__ void ldm_x4_t(uint32_t* r, uint32_t addr) {
    asm volatile("ldmatrix.sync.aligned.m8n8.x4.trans.shared.b16 {%0,%1,%2,%3}, [%4];"
                 : "=r"(r[0]), "=r"(r[1]), "=r"(r[2]), "=r"(r[3]) : "r"(addr));
}
__device__ __forceinline__ float gelu_new(float x) {
    float x3 = x * x * x;
    return 0.5f * x * (1.0f + tanhf(0.7978845608028654f * (x + 0.044715f * x3)));
}
__device__ __forceinline__ void split_f16(float v, __half& hi, __half& lo) {
    hi = __float2half_rn(v);
    lo = __float2half_rn(v - __half2float(hi));
}
__device__ __forceinline__ uint32_t pack2h(__half a, __half b) {
    __half2 t{a, b};
    return *reinterpret_cast<uint32_t*>(&t);
}

// ---------------------------------------------------------------------------
// Weight convert: W[K,N] fp32 -> Wt[N,K] fp16 (tiled transpose)
// ---------------------------------------------------------------------------
__global__ void wconv_kernel(const float* __restrict__ W,
                             __half* __restrict__ T_, int K, int N) {
    __shared__ float t[32][33];
    int n0 = blockIdx.x * 32, k0 = blockIdx.y * 32;
    int tx = threadIdx.x, ty = threadIdx.y;
    #pragma unroll
    for (int j = 0; j < 4; j++)
        t[ty + j * 8][tx] = W[(size_t)(k0 + ty + j * 8) * N + n0 + tx];
    __syncthreads();
    #pragma unroll
    for (int j = 0; j < 4; j++) {
        int nl = ty + j * 8;
        T_[(size_t)(n0 + nl) * K + k0 + tx] = __float2half_rn(t[tx][nl]);
    }
}

// ---------------------------------------------------------------------------
// LayerNorm -> fp16 hi/lo pair output
// ---------------------------------------------------------------------------
__global__ void ln_kernel(const float* __restrict__ x,
                          const float* __restrict__ g,
                          const float* __restrict__ b,
                          __half* __restrict__ oh, __half* __restrict__ ol) {
    __shared__ float red[8];
    int row = blockIdx.x;
    int tid = threadIdx.x;
    const float4* xr = reinterpret_cast<const float4*>(x + (size_t)row * D_);
    float4 v = xr[tid];

    float s = v.x + v.y + v.z + v.w;
    #pragma unroll
    for (int o = 16; o; o >>= 1) s += __shfl_xor_sync(0xffffffffu, s, o);
    if ((tid & 31) == 0) red[tid >> 5] = s;
    __syncthreads();
    float tot = 0.f;
    #pragma unroll
    for (int i = 0; i < 8; i++) tot += red[i];
    float mu = tot * (1.0f / D_);
    __syncthreads();

    float dx = v.x - mu, dy = v.y - mu, dz = v.z - mu, dw = v.w - mu;
    float q = dx * dx + dy * dy + dz * dz + dw * dw;
    #pragma unroll
    for (int o = 16; o; o >>= 1) q += __shfl_xor_sync(0xffffffffu, q, o);
    if ((tid & 31) == 0) red[tid >> 5] = q;
    __syncthreads();
    float qtot = 0.f;
    #pragma unroll
    for (int i = 0; i < 8; i++) qtot += red[i];
    float rstd = rsqrtf(qtot * (1.0f / D_) + 1e-5f);

    const float4 g4 = reinterpret_cast<const float4*>(g)[tid];
    const float4 b4 = reinterpret_cast<const float4*>(b)[tid];
    float o0 = dx * rstd * g4.x + b4.x;
    float o1 = dy * rstd * g4.y + b4.y;
    float o2 = dz * rstd * g4.z + b4.z;
    float o3 = dw * rstd * g4.w + b4.w;

    __half h0, l0, h1, l1, h2, l2, h3, l3;
    split_f16(o0, h0, l0); split_f16(o1, h1, l1);
    split_f16(o2, h2, l2); split_f16(o3, h3, l3);
    size_t base = (size_t)row * D_ + tid * 4;
    uint32_t* ohp = reinterpret_cast<uint32_t*>(oh + base);
    uint32_t* olp = reinterpret_cast<uint32_t*>(ol + base);
    ohp[0] = pack2h(h0, h1); ohp[1] = pack2h(h2, h3);
    olp[0] = pack2h(l0, l1); olp[1] = pack2h(l2, l3);
}

// ---------------------------------------------------------------------------
// fp16 2-term tensor GEMM via mma.sync.m16n8k16 + ldmatrix.
// C[M,N] = A[M,K] @ W[K,N],  A = Ah + Al (fp16 pair, [M,K]), W = Wt[N,K] fp16.
// CTA tile 128x128, BK=32, 3-stage cp.async pipeline, 8 warps (2x4),
// warp tile 64x32, 2 CTAs/SM.
// EPI: 0 = +bias -> fp16 pair ; 1 = gelu(+bias) -> fp16 pair ;
//      2 = +bias+res -> fp32
// ---------------------------------------------------------------------------
#define BK_ 32
#define T_LD 40                     // smem row stride in halfwords (80 B)
#define TILE_BYTES (128 * T_LD * 2) // 10240
#define STAGE_BYTES (3 * TILE_BYTES) // 30720
#define SMEM_GEMM (3 * STAGE_BYTES)  // 92160

template <int EPI>
__global__ __launch_bounds__(256, 2)
void tc_gemm(const __half* __restrict__ Ah, const __half* __restrict__ Al,
             const __half* __restrict__ Bh,
             const float* __restrict__ bias, const float* __restrict__ res,
             float* __restrict__ C, __half* __restrict__ Cho, __half* __restrict__ Clo,
             int N, int K) {
    extern __shared__ char dsm[];
    const uint32_t sbase = smem_u32(dsm);
    const int tid  = threadIdx.x;
    const int lane = tid & 31;
    const int wid  = tid >> 5;
    const int g    = lane >> 2;
    const int tig  = lane & 3;
    const int mrow = (wid >> 2) * 64;
    const int ncol = (wid & 3) * 32;
    const int cCol = blockIdx.x, cRow = blockIdx.y;
    const int NC = K / BK_;
    const int lr  = lane & 7;
    const int l8  = (lane & 8) ? 8 : 0;
    const int l16 = (lane & 16) ? 8 : 0;

    const __half* srcs[3] = {
        Ah + (size_t)cRow * 128 * K, Al + (size_t)cRow * 128 * K,
        Bh + (size_t)cCol * 128 * K};

    auto load_stage = [&](int chunk, int s) {
        const int kk = chunk * BK_;
        const uint32_t st = sbase + s * STAGE_BYTES;
        #pragma unroll
        for (int t = 0; t < 3; t++) {
            const __half* src = srcs[t];
            #pragma unroll
            for (int i = 0; i < 2; i++) {
                int idx = tid + i * 256;
                int r = idx >> 2, ci = idx & 3;
                cp16(st + t * TILE_BYTES + r * 80 + ci * 16,
                     src + (size_t)r * K + kk + ci * 8);
            }
        }
    };

    float acc[4][4][4];
    #pragma unroll
    for (int i = 0; i < 4; i++)
        #pragma unroll
        for (int j = 0; j < 4; j++)
            #pragma unroll
            for (int r = 0; r < 4; r++) acc[i][j][r] = 0.f;

    load_stage(0, 0); cp_commit();
    load_stage(1, 1); cp_commit();

    for (int c = 0; c < NC; c++) {
        cp_wait<1>();
        __syncthreads();
        if (c + 2 < NC) load_stage(c + 2, (c + 2) % 3);
        cp_commit();

        const uint32_t ust = sbase + (c % 3) * STAGE_BYTES;
        const uint32_t uAh = ust;
        const uint32_t uAl = ust + TILE_BYTES;
        const uint32_t uBh = ust + 2 * TILE_BYTES;

        #pragma unroll
        for (int ks = 0; ks < 2; ks++) {
            const int k0 = ks * 16;
            uint32_t ah[4][4], bh[4][2];
            #pragma unroll
            for (int mt = 0; mt < 4; mt++) {
                int row = mrow + mt * 16 + lr + l8;
                ldm_x4(ah[mt], uAh + (uint32_t)(row * T_LD + k0 + l16) * 2);
            }
            #pragma unroll
            for (int ntp = 0; ntp < 2; ntp++) {
                int row = ncol + ntp * 16 + lr + l16;
                uint32_t t4[4];
                ldm_x4(t4, uBh + (uint32_t)(row * T_LD + k0 + l8) * 2);
                bh[2 * ntp][0] = t4[0]; bh[2 * ntp][1] = t4[1];
                bh[2 * ntp + 1][0] = t4[2]; bh[2 * ntp + 1][1] = t4[3];
            }
            #pragma unroll
            for (int mt = 0; mt < 4; mt++)
                #pragma unroll
                for (int nt = 0; nt < 4; nt++)
                    mma_f16(acc[mt][nt], ah[mt], bh[nt]);
            // term 2: al * bh (reload A-lo fragments into same regs)
            #pragma unroll
            for (int mt = 0; mt < 4; mt++) {
                int row = mrow + mt * 16 + lr + l8;
                ldm_x4(ah[mt], uAl + (uint32_t)(row * T_LD + k0 + l16) * 2);
            }
            #pragma unroll
            for (int mt = 0; mt < 4; mt++)
                #pragma unroll
                for (int nt = 0; nt < 4; nt++)
                    mma_f16(acc[mt][nt], ah[mt], bh[nt]);
        }
    }

    // ---- epilogue ----
    const int row_base = cRow * 128 + mrow;
    const int col_base = cCol * 128 + ncol;
    #pragma unroll
    for (int mt = 0; mt < 4; mt++) {
        #pragma unroll
        for (int nt = 0; nt < 4; nt++) {
            int cc = col_base + nt * 8 + tig * 2;
            float b0 = bias[cc], b1 = bias[cc + 1];
            #pragma unroll
            for (int half = 0; half < 2; half++) {
                int r = row_base + mt * 16 + g + half * 8;
                size_t off = (size_t)r * N + cc;
                float v0 = acc[mt][nt][half * 2 + 0] + b0;
                float v1 = acc[mt][nt][half * 2 + 1] + b1;
                if (EPI == 0 || EPI == 1) {
                    if (EPI == 1) { v0 = gelu_new(v0); v1 = gelu_new(v1); }
                    __half h0, l0, h1, l1;
                    split_f16(v0, h0, l0);
                    split_f16(v1, h1, l1);
                    *reinterpret_cast<uint32_t*>(Cho + off) = pack2h(h0, h1);
                    *reinterpret_cast<uint32_t*>(Clo + off) = pack2h(l0, l1);
                } else {
                    float2 rr = *reinterpret_cast<const float2*>(res + off);
                    v0 += rr.x; v1 += rr.y;
                    *reinterpret_cast<float2*>(C + off) = make_float2(v0, v1);
                }
            }
        }
    }
}

// ---------------------------------------------------------------------------
// Tensor-core flash attention, fp16.
// Scores = (qh+ql) @ Kh^T (2-term), PV = Ph @ Vh (1-term).
// K/V hi only in smem -> half the cp.async traffic and ldmatrix count.
// Block = (q-tile 128 rows, head, batch), 8 warps x 16 rows.
// ---------------------------------------------------------------------------
#define AT_LD 72
#define AT_ARR (64 * AT_LD)                 // elems per array (4608)
#define AT_STAGE (2 * AT_ARR)               // elems per stage (9216)
#define SMEM_ATTN (2 * AT_STAGE * 2)        // bytes: 36864

__global__ __launch_bounds__(256, 1)
void attn_kernel(const __half* __restrict__ qkvh, const __half* __restrict__ qkvl,
                 __half* __restrict__ ctx_hi, __half* __restrict__ ctx_lo) {
    extern __shared__ char dsm[];
    const uint32_t usm = smem_u32(dsm);

    const int qt = blockIdx.x;
    const int h  = blockIdx.y;
    const int b  = blockIdx.z;
    const int tid = threadIdx.x;
    const int wid = tid >> 5;
    const int lane = tid & 31;
    const int g   = lane >> 2;
    const int tig = lane & 3;
    const int lr  = lane & 7;
    const int l8  = (lane & 8) ? 8 : 0;
    const int l16 = (lane & 16) ? 8 : 0;

    const int q0 = qt * 128;
    const int row0 = wid * 16;
    const int LD3 = 3 * D_;
    const size_t bbase = (size_t)b * S_ * LD3 + h * HD_;

    // ---- load Q fragments (scaled by 1/8, exact on fp16) ----
    uint32_t qh[4][4], ql[4][4];
    {
        const __half2 s8 = __floats2half2_rn(0.125f, 0.125f);
        const size_t r0a = bbase + (size_t)(q0 + row0 + g) * LD3;
        const size_t r1a = r0a + (size_t)8 * LD3;
        #pragma unroll
        for (int kc = 0; kc < 4; kc++) {
            int col = kc * 16 + 2 * tig;
            #pragma unroll
            for (int e = 0; e < 4; e++) {
                size_t a = ((e & 1) ? r1a : r0a) + col + ((e & 2) ? 8 : 0);
                __half2 vh = *reinterpret_cast<const __half2*>(qkvh + a);
                __half2 vl = *reinterpret_cast<const __half2*>(qkvl + a);
                vh = __hmul2(vh, s8);
                vl = __hmul2(vl, s8);
                qh[kc][e] = *reinterpret_cast<uint32_t*>(&vh);
                ql[kc][e] = *reinterpret_cast<uint32_t*>(&vl);
            }
        }
    }

    // smem: [stage][arr][64][AT_LD], arr 0 = K hi, 1 = V hi
    auto load_tile = [&](int kt, int s) {
        const int kv0 = kt * 64;
        #pragma unroll
        for (int i = 0; i < 2; i++) {
            int c = tid + i * 256;           // 512 chunks of 16B per array
            int r = c >> 3, c8 = (c & 7) * 8;
            size_t src = bbase + (size_t)(kv0 + r) * LD3 + c8;
            uint32_t dst = usm + (uint32_t)(s * AT_STAGE + r * AT_LD + c8) * 2;
            cp16(dst,              qkvh + src + D_);       // K hi
            cp16(dst + AT_ARR * 2, qkvh + src + 2 * D_);   // V hi
        }
    };

    float o[8][4];
    #pragma unroll
    for (int i = 0; i < 8; i++)
        #pragma unroll
        for (int j = 0; j < 4; j++) o[i][j] = 0.f;
    float m0 = -INFINITY, m1 = -INFINITY, l0 = 0.f, l1 = 0.f;

    const int ktmax = 2 * qt + 1;
    load_tile(0, 0); cp_commit();

    for (int kt = 0; kt <= ktmax; kt++) {
        const int s = kt & 1;
        const int kv0 = kt * 64;
        if (kt < ktmax) { load_tile(kt + 1, s ^ 1); cp_commit(); cp_wait<1>(); }
        else            { cp_wait<0>(); }
        __syncthreads();

        const uint32_t uK = usm + (uint32_t)(s * AT_STAGE) * 2;
        const uint32_t uV = uK + AT_ARR * 2;

        // ---- scores S = Qs @ K^T  (2-term) ----
        float sS[8][4];
        #pragma unroll
        for (int i = 0; i < 8; i++)
            #pragma unroll
            for (int j = 0; j < 4; j++) sS[i][j] = 0.f;

        #pragma unroll
        for (int ntp = 0; ntp < 4; ntp++) {
            int krow = ntp * 16 + lr + l16;
            #pragma unroll
            for (int kc = 0; kc < 4; kc++) {
                uint32_t off = (uint32_t)(krow * AT_LD + kc * 16 + l8) * 2;
                uint32_t th[4];
                ldm_x4(th, uK + off);
                uint32_t bh0[2] = {th[0], th[1]}, bh1[2] = {th[2], th[3]};
                mma_f16(sS[2 * ntp],     qh[kc], bh0);
                mma_f16(sS[2 * ntp],     ql[kc], bh0);
                mma_f16(sS[2 * ntp + 1], qh[kc], bh1);
                mma_f16(sS[2 * ntp + 1], ql[kc], bh1);
            }
        }

        // ---- causal mask ----
        if (kv0 + 63 > q0 + row0) {
            int r0g = q0 + row0 + g;
            #pragma unroll
            for (int nt = 0; nt < 8; nt++) {
                int c0 = kv0 + nt * 8 + 2 * tig;
                if (c0 > r0g)     sS[nt][0] = -1e30f;
                if (c0 + 1 > r0g) sS[nt][1] = -1e30f;
                if (c0 > r0g + 8)     sS[nt][2] = -1e30f;
                if (c0 + 1 > r0g + 8) sS[nt][3] = -1e30f;
            }
        }

        // ---- online softmax (rows g and g+8) ----
        float rm0 = -1e30f, rm1 = -1e30f;
        #pragma unroll
        for (int nt = 0; nt < 8; nt++) {
            rm0 = fmaxf(rm0, fmaxf(sS[nt][0], sS[nt][1]));
            rm1 = fmaxf(rm1, fmaxf(sS[nt][2], sS[nt][3]));
        }
        rm0 = fmaxf(rm0, __shfl_xor_sync(0xffffffffu, rm0, 1));
        rm0 = fmaxf(rm0, __shfl_xor_sync(0xffffffffu, rm0, 2));
        rm1 = fmaxf(rm1, __shfl_xor_sync(0xffffffffu, rm1, 1));
        rm1 = fmaxf(rm1, __shfl_xor_sync(0xffffffffu, rm1, 2));
        float nm0 = fmaxf(m0, rm0), nm1 = fmaxf(m1, rm1);
        float a0 = __expf(m0 - nm0), a1 = __expf(m1 - nm1);
        float rs0 = 0.f, rs1 = 0.f;
        #pragma unroll
        for (int nt = 0; nt < 8; nt++) {
            sS[nt][0] = __expf(sS[nt][0] - nm0);
            sS[nt][1] = __expf(sS[nt][1] - nm0);
            sS[nt][2] = __expf(sS[nt][2] - nm1);
            sS[nt][3] = __expf(sS[nt][3] - nm1);
            rs0 += sS[nt][0] + sS[nt][1];
            rs1 += sS[nt][2] + sS[nt][3];
        }
        rs0 += __shfl_xor_sync(0xffffffffu, rs0, 1);
        rs0 += __shfl_xor_sync(0xffffffffu, rs0, 2);
        rs1 += __shfl_xor_sync(0xffffffffu, rs1, 1);
        rs1 += __shfl_xor_sync(0xffffffffu, rs1, 2);
        l0 = l0 * a0 + rs0; l1 = l1 * a1 + rs1;
        m0 = nm0; m1 = nm1;
        #pragma unroll
        for (int nt = 0; nt < 8; nt++) {
            o[nt][0] *= a0; o[nt][1] *= a0;
            o[nt][2] *= a1; o[nt][3] *= a1;
        }

        // ---- pack P as fp16 A-fragments (hi only) ----
        uint32_t pah[4][4];
        #pragma unroll
        for (int kc2 = 0; kc2 < 4; kc2++) {
            #pragma unroll
            for (int e = 0; e < 4; e++) {
                int nt = 2 * kc2 + (e >> 1);
                int j0 = (e & 1) ? 2 : 0;
                pah[kc2][e] = pack2h(__float2half_rn(sS[nt][j0]),
                                     __float2half_rn(sS[nt][j0 + 1]));
            }
        }

        // ---- O += P @ V  (1-term) ----
        #pragma unroll
        for (int dn = 0; dn < 4; dn++) {
            #pragma unroll
            for (int kc2 = 0; kc2 < 4; kc2++) {
                int vrow = kc2 * 16 + lr + l8;
                uint32_t off = (uint32_t)(vrow * AT_LD + dn * 16 + l16) * 2;
                uint32_t th[4];
                ldm_x4_t(th, uV + off);
                uint32_t bh0[2] = {th[0], th[1]}, bh1[2] = {th[2], th[3]};
                mma_f16(o[2 * dn],     pah[kc2], bh0);
                mma_f16(o[2 * dn + 1], pah[kc2], bh1);
            }
        }
        __syncthreads();
    }

    // ---- write ctx (fp16 hi/lo) ----
    float inv0 = 1.0f / l0, inv1 = 1.0f / l1;
    size_t r0o = ((size_t)b * S_ + q0 + row0 + g) * D_ + h * HD_;
    size_t r1o = r0o + (size_t)8 * D_;
    #pragma unroll
    for (int nt = 0; nt < 8; nt++) {
        int col = nt * 8 + 2 * tig;
        __half h0, lo0, h1, lo1;
        split_f16(o[nt][0] * inv0, h0, lo0);
        split_f16(o[nt][1] * inv0, h1, lo1);
        *reinterpret_cast<uint32_t*>(ctx_hi + r0o + col) = pack2h(h0, h1);
        *reinterpret_cast<uint32_t*>(ctx_lo + r0o + col) = pack2h(lo0, lo1);
        split_f16(o[nt][2] * inv1, h0, lo0);
        split_f16(o[nt][3] * inv1, h1, lo1);
        *reinterpret_cast<uint32_t*>(ctx_hi + r1o + col) = pack2h(h0, h1);
        *reinterpret_cast<uint32_t*>(ctx_lo + r1o + col) = pack2h(lo0, lo1);
    }
}

// ---------------------------------------------------------------------------
// launch
// ---------------------------------------------------------------------------
extern "C" void kernel_launch(void* const* d_in, const int* in_sizes, int n_in,
                              void* d_out, int out_size) {
    const float* x        = (const float*)d_in[0];
    const float* ln1_g    = (const float*)d_in[1];
    const float* ln1_b    = (const float*)d_in[2];
    const float* c_attn_w = (const float*)d_in[3];
    const float* c_attn_b = (const float*)d_in[4];
    const float* c_proj_w = (const float*)d_in[5];
    const float* c_proj_b = (const float*)d_in[6];
    const float* ln2_g    = (const float*)d_in[7];
    const float* ln2_b    = (const float*)d_in[8];
    const float* fc_w     = (const float*)d_in[9];
    const float* fc_b     = (const float*)d_in[10];
    const float* proj_w   = (const float*)d_in[11];
    const float* proj_b   = (const float*)d_in[12];
    float* out = (float*)d_out;

    cudaFuncSetAttribute(tc_gemm<0>, cudaFuncAttributeMaxDynamicSharedMemorySize, SMEM_GEMM);
    cudaFuncSetAttribute(tc_gemm<1>, cudaFuncAttributeMaxDynamicSharedMemorySize, SMEM_GEMM);
    cudaFuncSetAttribute(tc_gemm<2>, cudaFuncAttributeMaxDynamicSharedMemorySize, SMEM_GEMM);
    cudaFuncSetAttribute(attn_kernel, cudaFuncAttributeMaxDynamicSharedMemorySize, SMEM_ATTN);

    __half *h_hi, *h_lo, *qkv_hi, *qkv_lo, *ctx_hi, *ctx_lo, *h2_hi, *h2_lo, *ff_hi, *ff_lo;
    __half *wqkv, *wpr, *wfc, *wp2;
    float *h1;
    cudaGetSymbolAddress((void**)&h_hi, g_h_hi);   cudaGetSymbolAddress((void**)&h_lo, g_h_lo);
    cudaGetSymbolAddress((void**)&qkv_hi, g_qkv_hi); cudaGetSymbolAddress((void**)&qkv_lo, g_qkv_lo);
    cudaGetSymbolAddress((void**)&ctx_hi, g_ctx_hi); cudaGetSymbolAddress((void**)&ctx_lo, g_ctx_lo);
    cudaGetSymbolAddress((void**)&h1, g_h1);
    cudaGetSymbolAddress((void**)&h2_hi, g_h2_hi); cudaGetSymbolAddress((void**)&h2_lo, g_h2_lo);
    cudaGetSymbolAddress((void**)&ff_hi, g_ff_hi); cudaGetSymbolAddress((void**)&ff_lo, g_ff_lo);
    cudaGetSymbolAddress((void**)&wqkv, g_wqkv);
    cudaGetSymbolAddress((void**)&wpr, g_wpr);
    cudaGetSymbolAddress((void**)&wfc, g_wfc);
    cudaGetSymbolAddress((void**)&wp2, g_wp2);

    dim3 tb(32, 8);
    wconv_kernel<<<dim3(3 * D_ / 32, D_ / 32), tb>>>(c_attn_w, wqkv, D_, 3 * D_);
    wconv_kernel<<<dim3(D_ / 32, D_ / 32), tb>>>(c_proj_w, wpr, D_, D_);
    wconv_kernel<<<dim3(4 * D_ / 32, D_ / 32), tb>>>(fc_w, wfc, D_, 4 * D_);
    wconv_kernel<<<dim3(D_ / 32, 4 * D_ / 32), tb>>>(proj_w, wp2, 4 * D_, D_);

    // 1. h = LN1(x)  -> fp16 pair
    ln_kernel<<<M_, 256>>>(x, ln1_g, ln1_b, h_hi, h_lo);
    // 2. qkv = h @ Wqkv + b  -> fp16 pair
    tc_gemm<0><<<dim3(3 * D_ / 128, M_ / 128), 256, SMEM_GEMM>>>(
        h_hi, h_lo, wqkv, c_attn_b, nullptr, nullptr, qkv_hi, qkv_lo,
        3 * D_, D_);
    // 3. attention -> ctx fp16 pair
    attn_kernel<<<dim3(S_ / 128, H_, B_), 256, SMEM_ATTN>>>(qkv_hi, qkv_lo, ctx_hi, ctx_lo);
    // 4. h1 = x + ctx @ Wproj + b  (fp32 out)
    tc_gemm<2><<<dim3(D_ / 128, M_ / 128), 256, SMEM_GEMM>>>(
        ctx_hi, ctx_lo, wpr, c_proj_b, x, h1, nullptr, nullptr,
        D_, D_);
    // 5. h2 = LN2(h1)  -> fp16 pair
    ln_kernel<<<M_, 256>>>(h1, ln2_g, ln2_b, h2_hi, h2_lo);
    // 6. ff = gelu(h2 @ fc_w + fc_b)  -> fp16 pair
    tc_gemm<1><<<dim3(4 * D_ / 128, M_ / 128), 256, SMEM_GEMM>>>(
        h2_hi, h2_lo, wfc, fc_b, nullptr, nullptr, ff_hi, ff_lo,
        4 * D_, D_);
    // 7. out = h1 + ff @ proj_w + proj_b  (fp32 out)
    tc_gemm<2><<<dim3(D_ / 128, M_ / 128), 256, SMEM_GEMM>>>(
        ff_hi, ff_lo, wp2, proj_b, h1, out, nullptr, nullptr,
        D_, 4 * D_);
}

// round 11
// speedup vs baseline: 6.7799x; 1.7351x over previous
#include <cuda_runtime.h>
#include <cuda_fp16.h>
#include <cstdint>
#include <math.h>

// ---------------------------------------------------------------------------
// GPT-2 block: B=8, S=1024, D=1024, H=16, Hd=64
// ---------------------------------------------------------------------------
#define B_ 8
#define S_ 1024
#define D_ 1024
#define H_ 16
#define HD_ 64
#define M_ (B_ * S_)          // 8192 rows

// Scratch (device globals; no allocation allowed in kernel_launch)
__device__ __half g_h  [M_ * D_];
__device__ __half g_qkv[M_ * 3 * D_];
__device__ __half g_ctx[M_ * D_];
__device__ float  g_h1 [M_ * D_];
__device__ __half g_h2 [M_ * D_];
__device__ __half g_ff [M_ * 4 * D_];
// transposed weights [N, K] fp16
__device__ __half g_wqkv[3 * D_ * D_];
__device__ __half g_wpr [D_ * D_];
__device__ __half g_wfc [4 * D_ * D_];
__device__ __half g_wp2 [4 * D_ * D_];

// ---------------------------------------------------------------------------
// helpers
// ---------------------------------------------------------------------------
__device__ __forceinline__ uint32_t smem_u32(const void* p) {
    uint32_t a;
    asm("{ .reg .u64 t; cvta.to.shared.u64 t, %1; cvt.u32.u64 %0, t; }"
        : "=r"(a) : "l"(p));
    return a;
}
__device__ __forceinline__ void cp16(uint32_t dst, const void* src) {
    asm volatile("cp.async.ca.shared.global [%0], [%1], 16;"
                 :: "r"(dst), "l"(src) : "memory");
}
__device__ __forceinline__ void cp_commit() {
    asm volatile("cp.async.commit_group;" ::: "memory");
}
template <int N>
__device__ __forceinline__ void cp_wait() {
    asm volatile("cp.async.wait_group %0;" :: "n"(N) : "memory");
}
__device__ __forceinline__ void mma_f16(float* d, const uint32_t* a, const uint32_t* b) {
    asm volatile(
        "mma.sync.aligned.m16n8k16.row.col.f32.f16.f16.f32 "
        "{%0,%1,%2,%3}, {%4,%5,%6,%7}, {%8,%9}, {%0,%1,%2,%3};"
        : "+f"(d[0]), "+f"(d[1]), "+f"(d[2]), "+f"(d[3])
        : "r"(a[0]), "r"(a[1]), "r"(a[2]), "r"(a[3]), "r"(b[0]), "r"(b[1]));
}
__device__ __forceinline__ void ldm_x4(uint32_t* r, uint32_t addr) {
    asm volatile("ldmatrix.sync.aligned.m8n8.x4.shared.b16 {%0,%1,%2,%3}, [%4];"
                 : "=r"(r[0]), "=r"(r[1]), "=r"(r[2]), "=r"(r[3]) : "r"(addr));
}
__device__ __forceinline__ void ldm_x4_t(uint32_t* r, uint32_t addr) {
    asm volatile("ldmatrix.sync.aligned.m8n8.x4.trans.shared.b16 {%0,%1,%2,%3}, [%4];"
                 : "=r"(r[0]), "=r"(r[1]), "=r"(r[2]), "=r"(r[3]) : "r"(addr));
}
__device__ __forceinline__ float gelu_new(float x) {
    float x3 = x * x * x;
    return 0.5f * x * (1.0f + tanhf(0.7978845608028654f * (x + 0.044715f * x3)));
}
__device__ __forceinline__ uint32_t pack2h(__half a, __half b) {
    __half2 t{a, b};
    return *reinterpret_cast<uint32_t*>(&t);
}

// ---------------------------------------------------------------------------
// Weight convert: W[K,N] fp32 -> Wt[N,K] fp16 (tiled transpose)
// ---------------------------------------------------------------------------
__global__ void wconv_kernel(const float* __restrict__ W,
                             __half* __restrict__ T_, int K, int N) {
    __shared__ float t[32][33];
    int n0 = blockIdx.x * 32, k0 = blockIdx.y * 32;
    int tx = threadIdx.x, ty = threadIdx.y;
    #pragma unroll
    for (int j = 0; j < 4; j++)
        t[ty + j * 8][tx] = W[(size_t)(k0 + ty + j * 8) * N + n0 + tx];
    __syncthreads();
    #pragma unroll
    for (int j = 0; j < 4; j++) {
        int nl = ty + j * 8;
        T_[(size_t)(n0 + nl) * K + k0 + tx] = __float2half_rn(t[tx][nl]);
    }
}

// ---------------------------------------------------------------------------
// LayerNorm -> fp16 output
// ---------------------------------------------------------------------------
__global__ void ln_kernel(const float* __restrict__ x,
                          const float* __restrict__ g,
                          const float* __restrict__ b,
                          __half* __restrict__ oh) {
    __shared__ float red[8];
    int row = blockIdx.x;
    int tid = threadIdx.x;
    const float4* xr = reinterpret_cast<const float4*>(x + (size_t)row * D_);
    float4 v = xr[tid];

    float s = v.x + v.y + v.z + v.w;
    #pragma unroll
    for (int o = 16; o; o >>= 1) s += __shfl_xor_sync(0xffffffffu, s, o);
    if ((tid & 31) == 0) red[tid >> 5] = s;
    __syncthreads();
    float tot = 0.f;
    #pragma unroll
    for (int i = 0; i < 8; i++) tot += red[i];
    float mu = tot * (1.0f / D_);
    __syncthreads();

    float dx = v.x - mu, dy = v.y - mu, dz = v.z - mu, dw = v.w - mu;
    float q = dx * dx + dy * dy + dz * dz + dw * dw;
    #pragma unroll
    for (int o = 16; o; o >>= 1) q += __shfl_xor_sync(0xffffffffu, q, o);
    if ((tid & 31) == 0) red[tid >> 5] = q;
    __syncthreads();
    float qtot = 0.f;
    #pragma unroll
    for (int i = 0; i < 8; i++) qtot += red[i];
    float rstd = rsqrtf(qtot * (1.0f / D_) + 1e-5f);

    const float4 g4 = reinterpret_cast<const float4*>(g)[tid];
    const float4 b4 = reinterpret_cast<const float4*>(b)[tid];
    float o0 = dx * rstd * g4.x + b4.x;
    float o1 = dy * rstd * g4.y + b4.y;
    float o2 = dz * rstd * g4.z + b4.z;
    float o3 = dw * rstd * g4.w + b4.w;

    size_t base = (size_t)row * D_ + tid * 4;
    uint32_t* ohp = reinterpret_cast<uint32_t*>(oh + base);
    ohp[0] = pack2h(__float2half_rn(o0), __float2half_rn(o1));
    ohp[1] = pack2h(__float2half_rn(o2), __float2half_rn(o3));
}

// ---------------------------------------------------------------------------
// fp16 tensor GEMM via mma.sync.m16n8k16 + ldmatrix.
// C[M,N] = A[M,K] @ W[K,N],  A fp16 [M,K], W = Wt[N,K] fp16.
// CTA tile 128x128, BK=32, 3-stage cp.async pipeline, 8 warps (2x4),
// warp tile 64x32, 2 CTAs/SM.
// EPI: 0 = +bias -> fp16 ; 1 = gelu(+bias) -> fp16 ; 2 = +bias+res -> fp32
// ---------------------------------------------------------------------------
#define BK_ 32
#define T_LD 40                      // smem row stride in halfwords (80 B)
#define TILE_BYTES (128 * T_LD * 2)  // 10240
#define STAGE_BYTES (2 * TILE_BYTES) // 20480
#define SMEM_GEMM (3 * STAGE_BYTES)  // 61440

template <int EPI>
__global__ __launch_bounds__(256, 2)
void tc_gemm(const __half* __restrict__ Ah, const __half* __restrict__ Bh,
             const float* __restrict__ bias, const float* __restrict__ res,
             float* __restrict__ C, __half* __restrict__ Cho,
             int N, int K) {
    extern __shared__ char dsm[];
    const uint32_t sbase = smem_u32(dsm);
    const int tid  = threadIdx.x;
    const int lane = tid & 31;
    const int wid  = tid >> 5;
    const int g    = lane >> 2;
    const int tig  = lane & 3;
    const int mrow = (wid >> 2) * 64;
    const int ncol = (wid & 3) * 32;
    const int cCol = blockIdx.x, cRow = blockIdx.y;
    const int NC = K / BK_;
    const int lr  = lane & 7;
    const int l8  = (lane & 8) ? 8 : 0;
    const int l16 = (lane & 16) ? 8 : 0;

    const __half* srcs[2] = {
        Ah + (size_t)cRow * 128 * K, Bh + (size_t)cCol * 128 * K};

    auto load_stage = [&](int chunk, int s) {
        const int kk = chunk * BK_;
        const uint32_t st = sbase + s * STAGE_BYTES;
        #pragma unroll
        for (int t = 0; t < 2; t++) {
            const __half* src = srcs[t];
            #pragma unroll
            for (int i = 0; i < 2; i++) {
                int idx = tid + i * 256;
                int r = idx >> 2, ci = idx & 3;
                cp16(st + t * TILE_BYTES + r * 80 + ci * 16,
                     src + (size_t)r * K + kk + ci * 8);
            }
        }
    };

    float acc[4][4][4];
    #pragma unroll
    for (int i = 0; i < 4; i++)
        #pragma unroll
        for (int j = 0; j < 4; j++)
            #pragma unroll
            for (int r = 0; r < 4; r++) acc[i][j][r] = 0.f;

    load_stage(0, 0); cp_commit();
    load_stage(1, 1); cp_commit();

    for (int c = 0; c < NC; c++) {
        cp_wait<1>();
        __syncthreads();
        if (c + 2 < NC) load_stage(c + 2, (c + 2) % 3);
        cp_commit();

        const uint32_t ust = sbase + (c % 3) * STAGE_BYTES;
        const uint32_t uAh = ust;
        const uint32_t uBh = ust + TILE_BYTES;

        #pragma unroll
        for (int ks = 0; ks < 2; ks++) {
            const int k0 = ks * 16;
            uint32_t ah[4][4], bh[4][2];
            #pragma unroll
            for (int mt = 0; mt < 4; mt++) {
                int row = mrow + mt * 16 + lr + l8;
                ldm_x4(ah[mt], uAh + (uint32_t)(row * T_LD + k0 + l16) * 2);
            }
            #pragma unroll
            for (int ntp = 0; ntp < 2; ntp++) {
                int row = ncol + ntp * 16 + lr + l16;
                uint32_t t4[4];
                ldm_x4(t4, uBh + (uint32_t)(row * T_LD + k0 + l8) * 2);
                bh[2 * ntp][0] = t4[0]; bh[2 * ntp][1] = t4[1];
                bh[2 * ntp + 1][0] = t4[2]; bh[2 * ntp + 1][1] = t4[3];
            }
            #pragma unroll
            for (int mt = 0; mt < 4; mt++)
                #pragma unroll
                for (int nt = 0; nt < 4; nt++)
                    mma_f16(acc[mt][nt], ah[mt], bh[nt]);
        }
    }

    // ---- epilogue ----
    const int row_base = cRow * 128 + mrow;
    const int col_base = cCol * 128 + ncol;
    #pragma unroll
    for (int mt = 0; mt < 4; mt++) {
        #pragma unroll
        for (int nt = 0; nt < 4; nt++) {
            int cc = col_base + nt * 8 + tig * 2;
            float b0 = bias[cc], b1 = bias[cc + 1];
            #pragma unroll
            for (int half = 0; half < 2; half++) {
                int r = row_base + mt * 16 + g + half * 8;
                size_t off = (size_t)r * N + cc;
                float v0 = acc[mt][nt][half * 2 + 0] + b0;
                float v1 = acc[mt][nt][half * 2 + 1] + b1;
                if (EPI == 0 || EPI == 1) {
                    if (EPI == 1) { v0 = gelu_new(v0); v1 = gelu_new(v1); }
                    *reinterpret_cast<uint32_t*>(Cho + off) =
                        pack2h(__float2half_rn(v0), __float2half_rn(v1));
                } else {
                    float2 rr = *reinterpret_cast<const float2*>(res + off);
                    v0 += rr.x; v1 += rr.y;
                    *reinterpret_cast<float2*>(C + off) = make_float2(v0, v1);
                }
            }
        }
    }
}

// ---------------------------------------------------------------------------
// Tensor-core flash attention, pure fp16 operands, fp32 accum/softmax.
// Scores = Q @ K^T, PV = P @ V.  Block = (q-tile 128 rows, head, batch).
// ---------------------------------------------------------------------------
#define AT_LD 72
#define AT_ARR (64 * AT_LD)                 // elems per array (4608)
#define AT_STAGE (2 * AT_ARR)               // elems per stage (9216)
#define SMEM_ATTN (2 * AT_STAGE * 2)        // bytes: 36864

__global__ __launch_bounds__(256, 1)
void attn_kernel(const __half* __restrict__ qkvh,
                 __half* __restrict__ ctx) {
    extern __shared__ char dsm[];
    const uint32_t usm = smem_u32(dsm);

    const int qt = blockIdx.x;
    const int h  = blockIdx.y;
    const int b  = blockIdx.z;
    const int tid = threadIdx.x;
    const int wid = tid >> 5;
    const int lane = tid & 31;
    const int g   = lane >> 2;
    const int tig = lane & 3;
    const int lr  = lane & 7;
    const int l8  = (lane & 8) ? 8 : 0;
    const int l16 = (lane & 16) ? 8 : 0;

    const int q0 = qt * 128;
    const int row0 = wid * 16;
    const int LD3 = 3 * D_;
    const size_t bbase = (size_t)b * S_ * LD3 + h * HD_;

    // ---- load Q fragments (scaled by 1/8, exact on fp16) ----
    uint32_t qh[4][4];
    {
        const __half2 s8 = __floats2half2_rn(0.125f, 0.125f);
        const size_t r0a = bbase + (size_t)(q0 + row0 + g) * LD3;
        const size_t r1a = r0a + (size_t)8 * LD3;
        #pragma unroll
        for (int kc = 0; kc < 4; kc++) {
            int col = kc * 16 + 2 * tig;
            #pragma unroll
            for (int e = 0; e < 4; e++) {
                size_t a = ((e & 1) ? r1a : r0a) + col + ((e & 2) ? 8 : 0);
                __half2 vh = *reinterpret_cast<const __half2*>(qkvh + a);
                vh = __hmul2(vh, s8);
                qh[kc][e] = *reinterpret_cast<uint32_t*>(&vh);
            }
        }
    }

    // smem: [stage][arr][64][AT_LD], arr 0 = K, 1 = V
    auto load_tile = [&](int kt, int s) {
        const int kv0 = kt * 64;
        #pragma unroll
        for (int i = 0; i < 2; i++) {
            int c = tid + i * 256;           // 512 chunks of 16B per array
            int r = c >> 3, c8 = (c & 7) * 8;
            size_t src = bbase + (size_t)(kv0 + r) * LD3 + c8;
            uint32_t dst = usm + (uint32_t)(s * AT_STAGE + r * AT_LD + c8) * 2;
            cp16(dst,              qkvh + src + D_);       // K
            cp16(dst + AT_ARR * 2, qkvh + src + 2 * D_);   // V
        }
    };

    float o[8][4];
    #pragma unroll
    for (int i = 0; i < 8; i++)
        #pragma unroll
        for (int j = 0; j < 4; j++) o[i][j] = 0.f;
    float m0 = -INFINITY, m1 = -INFINITY, l0 = 0.f, l1 = 0.f;

    const int ktmax = 2 * qt + 1;
    load_tile(0, 0); cp_commit();

    for (int kt = 0; kt <= ktmax; kt++) {
        const int s = kt & 1;
        const int kv0 = kt * 64;
        if (kt < ktmax) { load_tile(kt + 1, s ^ 1); cp_commit(); cp_wait<1>(); }
        else            { cp_wait<0>(); }
        __syncthreads();

        const uint32_t uK = usm + (uint32_t)(s * AT_STAGE) * 2;
        const uint32_t uV = uK + AT_ARR * 2;

        // ---- scores S = Qs @ K^T ----
        float sS[8][4];
        #pragma unroll
        for (int i = 0; i < 8; i++)
            #pragma unroll
            for (int j = 0; j < 4; j++) sS[i][j] = 0.f;

        #pragma unroll
        for (int ntp = 0; ntp < 4; ntp++) {
            int krow = ntp * 16 + lr + l16;
            #pragma unroll
            for (int kc = 0; kc < 4; kc++) {
                uint32_t off = (uint32_t)(krow * AT_LD + kc * 16 + l8) * 2;
                uint32_t th[4];
                ldm_x4(th, uK + off);
                uint32_t bh0[2] = {th[0], th[1]}, bh1[2] = {th[2], th[3]};
                mma_f16(sS[2 * ntp],     qh[kc], bh0);
                mma_f16(sS[2 * ntp + 1], qh[kc], bh1);
            }
        }

        // ---- causal mask ----
        if (kv0 + 63 > q0 + row0) {
            int r0g = q0 + row0 + g;
            #pragma unroll
            for (int nt = 0; nt < 8; nt++) {
                int c0 = kv0 + nt * 8 + 2 * tig;
                if (c0 > r0g)     sS[nt][0] = -1e30f;
                if (c0 + 1 > r0g) sS[nt][1] = -1e30f;
                if (c0 > r0g + 8)     sS[nt][2] = -1e30f;
                if (c0 + 1 > r0g + 8) sS[nt][3] = -1e30f;
            }
        }

        // ---- online softmax (rows g and g+8) ----
        float rm0 = -1e30f, rm1 = -1e30f;
        #pragma unroll
        for (int nt = 0; nt < 8; nt++) {
            rm0 = fmaxf(rm0, fmaxf(sS[nt][0], sS[nt][1]));
            rm1 = fmaxf(rm1, fmaxf(sS[nt][2], sS[nt][3]));
        }
        rm0 = fmaxf(rm0, __shfl_xor_sync(0xffffffffu, rm0, 1));
        rm0 = fmaxf(rm0, __shfl_xor_sync(0xffffffffu, rm0, 2));
        rm1 = fmaxf(rm1, __shfl_xor_sync(0xffffffffu, rm1, 1));
        rm1 = fmaxf(rm1, __shfl_xor_sync(0xffffffffu, rm1, 2));
        float nm0 = fmaxf(m0, rm0), nm1 = fmaxf(m1, rm1);
        float a0 = __expf(m0 - nm0), a1 = __expf(m1 - nm1);
        float rs0 = 0.f, rs1 = 0.f;
        #pragma unroll
        for (int nt = 0; nt < 8; nt++) {
            sS[nt][0] = __expf(sS[nt][0] - nm0);
            sS[nt][1] = __expf(sS[nt][1] - nm0);
            sS[nt][2] = __expf(sS[nt][2] - nm1);
            sS[nt][3] = __expf(sS[nt][3] - nm1);
            rs0 += sS[nt][0] + sS[nt][1];
            rs1 += sS[nt][2] + sS[nt][3];
        }
        rs0 += __shfl_xor_sync(0xffffffffu, rs0, 1);
        rs0 += __shfl_xor_sync(0xffffffffu, rs0, 2);
        rs1 += __shfl_xor_sync(0xffffffffu, rs1, 1);
        rs1 += __shfl_xor_sync(0xffffffffu, rs1, 2);
        l0 = l0 * a0 + rs0; l1 = l1 * a1 + rs1;
        m0 = nm0; m1 = nm1;
        #pragma unroll
        for (int nt = 0; nt < 8; nt++) {
            o[nt][0] *= a0; o[nt][1] *= a0;
            o[nt][2] *= a1; o[nt][3] *= a1;
        }

        // ---- pack P as fp16 A-fragments ----
        uint32_t pah[4][4];
        #pragma unroll
        for (int kc2 = 0; kc2 < 4; kc2++) {
            #pragma unroll
            for (int e = 0; e < 4; e++) {
                int nt = 2 * kc2 + (e >> 1);
                int j0 = (e & 1) ? 2 : 0;
                pah[kc2][e] = pack2h(__float2half_rn(sS[nt][j0]),
                                     __float2half_rn(sS[nt][j0 + 1]));
            }
        }

        // ---- O += P @ V ----
        #pragma unroll
        for (int dn = 0; dn < 4; dn++) {
            #pragma unroll
            for (int kc2 = 0; kc2 < 4; kc2++) {
                int vrow = kc2 * 16 + lr + l8;
                uint32_t off = (uint32_t)(vrow * AT_LD + dn * 16 + l16) * 2;
                uint32_t th[4];
                ldm_x4_t(th, uV + off);
                uint32_t bh0[2] = {th[0], th[1]}, bh1[2] = {th[2], th[3]};
                mma_f16(o[2 * dn],     pah[kc2], bh0);
                mma_f16(o[2 * dn + 1], pah[kc2], bh1);
            }
        }
        __syncthreads();
    }

    // ---- write ctx (fp16) ----
    float inv0 = 1.0f / l0, inv1 = 1.0f / l1;
    size_t r0o = ((size_t)b * S_ + q0 + row0 + g) * D_ + h * HD_;
    size_t r1o = r0o + (size_t)8 * D_;
    #pragma unroll
    for (int nt = 0; nt < 8; nt++) {
        int col = nt * 8 + 2 * tig;
        *reinterpret_cast<uint32_t*>(ctx + r0o + col) =
            pack2h(__float2half_rn(o[nt][0] * inv0), __float2half_rn(o[nt][1] * inv0));
        *reinterpret_cast<uint32_t*>(ctx + r1o + col) =
            pack2h(__float2half_rn(o[nt][2] * inv1), __float2half_rn(o[nt][3] * inv1));
    }
}

// ---------------------------------------------------------------------------
// launch
// ---------------------------------------------------------------------------
extern "C" void kernel_launch(void* const* d_in, const int* in_sizes, int n_in,
                              void* d_out, int out_size) {
    const float* x        = (const float*)d_in[0];
    const float* ln1_g    = (const float*)d_in[1];
    const float* ln1_b    = (const float*)d_in[2];
    const float* c_attn_w = (const float*)d_in[3];
    const float* c_attn_b = (const float*)d_in[4];
    const float* c_proj_w = (const float*)d_in[5];
    const float* c_proj_b = (const float*)d_in[6];
    const float* ln2_g    = (const float*)d_in[7];
    const float* ln2_b    = (const float*)d_in[8];
    const float* fc_w     = (const float*)d_in[9];
    const float* fc_b     = (const float*)d_in[10];
    const float* proj_w   = (const float*)d_in[11];
    const float* proj_b   = (const float*)d_in[12];
    float* out = (float*)d_out;

    cudaFuncSetAttribute(tc_gemm<0>, cudaFuncAttributeMaxDynamicSharedMemorySize, SMEM_GEMM);
    cudaFuncSetAttribute(tc_gemm<1>, cudaFuncAttributeMaxDynamicSharedMemorySize, SMEM_GEMM);
    cudaFuncSetAttribute(tc_gemm<2>, cudaFuncAttributeMaxDynamicSharedMemorySize, SMEM_GEMM);
    cudaFuncSetAttribute(attn_kernel, cudaFuncAttributeMaxDynamicSharedMemorySize, SMEM_ATTN);

    __half *h, *qkv, *ctx, *h2, *ff;
    __half *wqkv, *wpr, *wfc, *wp2;
    float *h1;
    cudaGetSymbolAddress((void**)&h, g_h);
    cudaGetSymbolAddress((void**)&qkv, g_qkv);
    cudaGetSymbolAddress((void**)&ctx, g_ctx);
    cudaGetSymbolAddress((void**)&h1, g_h1);
    cudaGetSymbolAddress((void**)&h2, g_h2);
    cudaGetSymbolAddress((void**)&ff, g_ff);
    cudaGetSymbolAddress((void**)&wqkv, g_wqkv);
    cudaGetSymbolAddress((void**)&wpr, g_wpr);
    cudaGetSymbolAddress((void**)&wfc, g_wfc);
    cudaGetSymbolAddress((void**)&wp2, g_wp2);

    dim3 tb(32, 8);
    wconv_kernel<<<dim3(3 * D_ / 32, D_ / 32), tb>>>(c_attn_w, wqkv, D_, 3 * D_);
    wconv_kernel<<<dim3(D_ / 32, D_ / 32), tb>>>(c_proj_w, wpr, D_, D_);
    wconv_kernel<<<dim3(4 * D_ / 32, D_ / 32), tb>>>(fc_w, wfc, D_, 4 * D_);
    wconv_kernel<<<dim3(D_ / 32, 4 * D_ / 32), tb>>>(proj_w, wp2, 4 * D_, D_);

    // 1. h = LN1(x)  -> fp16
    ln_kernel<<<M_, 256>>>(x, ln1_g, ln1_b, h);
    // 2. qkv = h @ Wqkv + b  -> fp16
    tc_gemm<0><<<dim3(3 * D_ / 128, M_ / 128), 256, SMEM_GEMM>>>(
        h, wqkv, c_attn_b, nullptr, nullptr, qkv, 3 * D_, D_);
    // 3. attention -> ctx fp16
    attn_kernel<<<dim3(S_ / 128, H_, B_), 256, SMEM_ATTN>>>(qkv, ctx);
    // 4. h1 = x + ctx @ Wproj + b  (fp32 out)
    tc_gemm<2><<<dim3(D_ / 128, M_ / 128), 256, SMEM_GEMM>>>(
        ctx, wpr, c_proj_b, x, h1, nullptr, D_, D_);
    // 5. h2 = LN2(h1)  -> fp16
    ln_kernel<<<M_, 256>>>(h1, ln2_g, ln2_b, h2);
    // 6. ff = gelu(h2 @ fc_w + fc_b)  -> fp16
    tc_gemm<1><<<dim3(4 * D_ / 128, M_ / 128), 256, SMEM_GEMM>>>(
        h2, wfc, fc_b, nullptr, nullptr, ff, 4 * D_, D_);
    // 7. out = h1 + ff @ proj_w + proj_b  (fp32 out)
    tc_gemm<2><<<dim3(D_ / 128, M_ / 128), 256, SMEM_GEMM>>>(
        ff, wp2, proj_b, h1, out, nullptr, D_, 4 * D_);
}

// round 12
// speedup vs baseline: 6.8620x; 1.0121x over previous
#include <cuda_runtime.h>
#include <cuda_fp16.h>
#include <cstdint>
#include <math.h>

// ---------------------------------------------------------------------------
// GPT-2 block: B=8, S=1024, D=1024, H=16, Hd=64
// ---------------------------------------------------------------------------
#define B_ 8
#define S_ 1024
#define D_ 1024
#define H_ 16
#define HD_ 64
#define M_ (B_ * S_)          // 8192 rows

// Scratch (device globals; no allocation allowed in kernel_launch)
__device__ __half g_h  [M_ * D_];
__device__ __half g_qkv[M_ * 3 * D_];
__device__ __half g_ctx[M_ * D_];
__device__ float  g_h1 [M_ * D_];
__device__ __half g_h2 [M_ * D_];
__device__ __half g_ff [M_ * 4 * D_];
// transposed weights [N, K] fp16
__device__ __half g_wqkv[3 * D_ * D_];
__device__ __half g_wpr [D_ * D_];
__device__ __half g_wfc [4 * D_ * D_];
__device__ __half g_wp2 [4 * D_ * D_];

// ---------------------------------------------------------------------------
// helpers
// ---------------------------------------------------------------------------
__device__ __forceinline__ uint32_t smem_u32(const void* p) {
    uint32_t a;
    asm("{ .reg .u64 t; cvta.to.shared.u64 t, %1; cvt.u32.u64 %0, t; }"
        : "=r"(a) : "l"(p));
    return a;
}
__device__ __forceinline__ void cp16(uint32_t dst, const void* src) {
    asm volatile("cp.async.ca.shared.global [%0], [%1], 16;"
                 :: "r"(dst), "l"(src) : "memory");
}
__device__ __forceinline__ void cp_commit() {
    asm volatile("cp.async.commit_group;" ::: "memory");
}
template <int N>
__device__ __forceinline__ void cp_wait() {
    asm volatile("cp.async.wait_group %0;" :: "n"(N) : "memory");
}
__device__ __forceinline__ void mma_f16(float* d, const uint32_t* a, const uint32_t* b) {
    asm volatile(
        "mma.sync.aligned.m16n8k16.row.col.f32.f16.f16.f32 "
        "{%0,%1,%2,%3}, {%4,%5,%6,%7}, {%8,%9}, {%0,%1,%2,%3};"
        : "+f"(d[0]), "+f"(d[1]), "+f"(d[2]), "+f"(d[3])
        : "r"(a[0]), "r"(a[1]), "r"(a[2]), "r"(a[3]), "r"(b[0]), "r"(b[1]));
}
__device__ __forceinline__ void ldm_x4(uint32_t* r, uint32_t addr) {
    asm volatile("ldmatrix.sync.aligned.m8n8.x4.shared.b16 {%0,%1,%2,%3}, [%4];"
                 : "=r"(r[0]), "=r"(r[1]), "=r"(r[2]), "=r"(r[3]) : "r"(addr));
}
__device__ __forceinline__ void ldm_x4_t(uint32_t* r, uint32_t addr) {
    asm volatile("ldmatrix.sync.aligned.m8n8.x4.trans.shared.b16 {%0,%1,%2,%3}, [%4];"
                 : "=r"(r[0]), "=r"(r[1]), "=r"(r[2]), "=r"(r[3]) : "r"(addr));
}
__device__ __forceinline__ float gelu_new(float x) {
    float x3 = x * x * x;
    return 0.5f * x * (1.0f + tanhf(0.7978845608028654f * (x + 0.044715f * x3)));
}
__device__ __forceinline__ uint32_t pack2h(__half a, __half b) {
    __half2 t{a, b};
    return *reinterpret_cast<uint32_t*>(&t);
}

// ---------------------------------------------------------------------------
// LayerNorm body (256 threads, one row)
// ---------------------------------------------------------------------------
__device__ __forceinline__ void ln_row(const float* __restrict__ x,
                                       const float* __restrict__ g,
                                       const float* __restrict__ b,
                                       __half* __restrict__ oh,
                                       int row, float* red) {
    int tid = threadIdx.x;
    const float4* xr = reinterpret_cast<const float4*>(x + (size_t)row * D_);
    float4 v = xr[tid];

    float s = v.x + v.y + v.z + v.w;
    #pragma unroll
    for (int o = 16; o; o >>= 1) s += __shfl_xor_sync(0xffffffffu, s, o);
    if ((tid & 31) == 0) red[tid >> 5] = s;
    __syncthreads();
    float tot = 0.f;
    #pragma unroll
    for (int i = 0; i < 8; i++) tot += red[i];
    float mu = tot * (1.0f / D_);
    __syncthreads();

    float dx = v.x - mu, dy = v.y - mu, dz = v.z - mu, dw = v.w - mu;
    float q = dx * dx + dy * dy + dz * dz + dw * dw;
    #pragma unroll
    for (int o = 16; o; o >>= 1) q += __shfl_xor_sync(0xffffffffu, q, o);
    if ((tid & 31) == 0) red[tid >> 5] = q;
    __syncthreads();
    float qtot = 0.f;
    #pragma unroll
    for (int i = 0; i < 8; i++) qtot += red[i];
    float rstd = rsqrtf(qtot * (1.0f / D_) + 1e-5f);

    const float4 g4 = reinterpret_cast<const float4*>(g)[tid];
    const float4 b4 = reinterpret_cast<const float4*>(b)[tid];
    float o0 = dx * rstd * g4.x + b4.x;
    float o1 = dy * rstd * g4.y + b4.y;
    float o2 = dz * rstd * g4.z + b4.z;
    float o3 = dw * rstd * g4.w + b4.w;

    size_t base = (size_t)row * D_ + tid * 4;
    uint32_t* ohp = reinterpret_cast<uint32_t*>(oh + base);
    ohp[0] = pack2h(__float2half_rn(o0), __float2half_rn(o1));
    ohp[1] = pack2h(__float2half_rn(o2), __float2half_rn(o3));
}

// ---------------------------------------------------------------------------
// Weight-transpose tile body (256 threads, 32x32 tile)
// ---------------------------------------------------------------------------
__device__ __forceinline__ void wconv_tile(const float* __restrict__ W,
                                           __half* __restrict__ T_,
                                           int K, int N, int nx, int ky,
                                           float (*t)[33]) {
    int tx = threadIdx.x & 31, ty = threadIdx.x >> 5;
    int n0 = nx * 32, k0 = ky * 32;
    #pragma unroll
    for (int j = 0; j < 4; j++)
        t[ty + j * 8][tx] = W[(size_t)(k0 + ty + j * 8) * N + n0 + tx];
    __syncthreads();
    #pragma unroll
    for (int j = 0; j < 4; j++) {
        int nl = ty + j * 8;
        T_[(size_t)(n0 + nl) * K + k0 + tx] = __float2half_rn(t[tx][nl]);
    }
}

// ---------------------------------------------------------------------------
// Fused prep: LN1 (blocks [0, 8192)) + 4 weight transposes (rest).
// wconv regions: qkv 96x32=3072, c_proj 32x32=1024, fc 128x32=4096,
//                proj 32x128=4096  -> total 12288; grid = 20480.
// ---------------------------------------------------------------------------
__global__ __launch_bounds__(256)
void prep_kernel(const float* __restrict__ x,
                 const float* __restrict__ ln1_g, const float* __restrict__ ln1_b,
                 __half* __restrict__ h,
                 const float* __restrict__ Wqkv, __half* __restrict__ Tqkv,
                 const float* __restrict__ Wpr,  __half* __restrict__ Tpr,
                 const float* __restrict__ Wfc,  __half* __restrict__ Tfc,
                 const float* __restrict__ Wp2,  __half* __restrict__ Tp2) {
    __shared__ float tbuf[32][33];   // wconv staging (also covers ln red[8])
    int bid = blockIdx.x;
    if (bid < M_) {
        ln_row(x, ln1_g, ln1_b, h, bid, &tbuf[0][0]);
        return;
    }
    int wb = bid - M_;
    if (wb < 3072) {
        wconv_tile(Wqkv, Tqkv, D_, 3 * D_, wb % 96, wb / 96, tbuf);
    } else if ((wb -= 3072) < 1024) {
        wconv_tile(Wpr, Tpr, D_, D_, wb % 32, wb / 32, tbuf);
    } else if ((wb -= 1024) < 4096) {
        wconv_tile(Wfc, Tfc, D_, 4 * D_, wb % 128, wb / 128, tbuf);
    } else {
        wb -= 4096;
        wconv_tile(Wp2, Tp2, 4 * D_, D_, wb % 32, wb / 32, tbuf);
    }
}

// ---------------------------------------------------------------------------
// LayerNorm standalone (LN2)
// ---------------------------------------------------------------------------
__global__ void ln_kernel(const float* __restrict__ x,
                          const float* __restrict__ g,
                          const float* __restrict__ b,
                          __half* __restrict__ oh) {
    __shared__ float red[8];
    ln_row(x, g, b, oh, blockIdx.x, red);
}

// ---------------------------------------------------------------------------
// fp16 tensor GEMM via mma.sync.m16n8k16 + ldmatrix.
// C[M,N] = A[M,K] @ W[K,N],  A fp16 [M,K], W = Wt[N,K] fp16.
// CTA tile 128x128, BK=64, 3-stage cp.async pipeline, 8 warps (2x4),
// warp tile 64x32, 2 CTAs/SM (108KB smem each).
// EPI: 0 = +bias -> fp16 ; 1 = gelu(+bias) -> fp16 ; 2 = +bias+res -> fp32
// ---------------------------------------------------------------------------
#define BK_ 64
#define T_LD 72                      // smem row stride in halfwords (144 B)
#define TILE_BYTES (128 * T_LD * 2)  // 18432
#define STAGE_BYTES (2 * TILE_BYTES) // 36864
#define SMEM_GEMM (3 * STAGE_BYTES)  // 110592

template <int EPI>
__global__ __launch_bounds__(256, 2)
void tc_gemm(const __half* __restrict__ Ah, const __half* __restrict__ Bh,
             const float* __restrict__ bias, const float* __restrict__ res,
             float* __restrict__ C, __half* __restrict__ Cho,
             int N, int K) {
    extern __shared__ char dsm[];
    const uint32_t sbase = smem_u32(dsm);
    const int tid  = threadIdx.x;
    const int lane = tid & 31;
    const int wid  = tid >> 5;
    const int g    = lane >> 2;
    const int tig  = lane & 3;
    const int mrow = (wid >> 2) * 64;
    const int ncol = (wid & 3) * 32;
    const int cCol = blockIdx.x, cRow = blockIdx.y;
    const int NC = K / BK_;
    const int lr  = lane & 7;
    const int l8  = (lane & 8) ? 8 : 0;
    const int l16 = (lane & 16) ? 8 : 0;

    const __half* srcs[2] = {
        Ah + (size_t)cRow * 128 * K, Bh + (size_t)cCol * 128 * K};

    auto load_stage = [&](int chunk, int s) {
        const int kk = chunk * BK_;
        const uint32_t st = sbase + s * STAGE_BYTES;
        #pragma unroll
        for (int t = 0; t < 2; t++) {
            const __half* src = srcs[t];
            #pragma unroll
            for (int i = 0; i < 4; i++) {
                int idx = tid + i * 256;       // 1024 chunks of 16B per tile
                int r = idx >> 3, ci = idx & 7;
                cp16(st + t * TILE_BYTES + r * 144 + ci * 16,
                     src + (size_t)r * K + kk + ci * 8);
            }
        }
    };

    float acc[4][4][4];
    #pragma unroll
    for (int i = 0; i < 4; i++)
        #pragma unroll
        for (int j = 0; j < 4; j++)
            #pragma unroll
            for (int r = 0; r < 4; r++) acc[i][j][r] = 0.f;

    load_stage(0, 0); cp_commit();
    load_stage(1, 1); cp_commit();

    for (int c = 0; c < NC; c++) {
        cp_wait<1>();
        __syncthreads();
        if (c + 2 < NC) load_stage(c + 2, (c + 2) % 3);
        cp_commit();

        const uint32_t ust = sbase + (c % 3) * STAGE_BYTES;
        const uint32_t uAh = ust;
        const uint32_t uBh = ust + TILE_BYTES;

        #pragma unroll
        for (int ks = 0; ks < 4; ks++) {
            const int k0 = ks * 16;
            uint32_t ah[4][4], bh[4][2];
            #pragma unroll
            for (int mt = 0; mt < 4; mt++) {
                int row = mrow + mt * 16 + lr + l8;
                ldm_x4(ah[mt], uAh + (uint32_t)(row * T_LD + k0 + l16) * 2);
            }
            #pragma unroll
            for (int ntp = 0; ntp < 2; ntp++) {
                int row = ncol + ntp * 16 + lr + l16;
                uint32_t t4[4];
                ldm_x4(t4, uBh + (uint32_t)(row * T_LD + k0 + l8) * 2);
                bh[2 * ntp][0] = t4[0]; bh[2 * ntp][1] = t4[1];
                bh[2 * ntp + 1][0] = t4[2]; bh[2 * ntp + 1][1] = t4[3];
            }
            #pragma unroll
            for (int mt = 0; mt < 4; mt++)
                #pragma unroll
                for (int nt = 0; nt < 4; nt++)
                    mma_f16(acc[mt][nt], ah[mt], bh[nt]);
        }
    }

    // ---- epilogue ----
    const int row_base = cRow * 128 + mrow;
    const int col_base = cCol * 128 + ncol;
    #pragma unroll
    for (int mt = 0; mt < 4; mt++) {
        #pragma unroll
        for (int nt = 0; nt < 4; nt++) {
            int cc = col_base + nt * 8 + tig * 2;
            float b0 = bias[cc], b1 = bias[cc + 1];
            #pragma unroll
            for (int half = 0; half < 2; half++) {
                int r = row_base + mt * 16 + g + half * 8;
                size_t off = (size_t)r * N + cc;
                float v0 = acc[mt][nt][half * 2 + 0] + b0;
                float v1 = acc[mt][nt][half * 2 + 1] + b1;
                if (EPI == 0 || EPI == 1) {
                    if (EPI == 1) { v0 = gelu_new(v0); v1 = gelu_new(v1); }
                    *reinterpret_cast<uint32_t*>(Cho + off) =
                        pack2h(__float2half_rn(v0), __float2half_rn(v1));
                } else {
                    float2 rr = *reinterpret_cast<const float2*>(res + off);
                    v0 += rr.x; v1 += rr.y;
                    *reinterpret_cast<float2*>(C + off) = make_float2(v0, v1);
                }
            }
        }
    }
}

// ---------------------------------------------------------------------------
// Tensor-core flash attention, pure fp16 operands, fp32 accum/softmax.
// Scores = Q @ K^T, PV = P @ V.  Block = (q-tile 128 rows, head, batch).
// 2 CTAs/SM.
// ---------------------------------------------------------------------------
#define AT_LD 72
#define AT_ARR (64 * AT_LD)                 // elems per array (4608)
#define AT_STAGE (2 * AT_ARR)               // elems per stage (9216)
#define SMEM_ATTN (2 * AT_STAGE * 2)        // bytes: 36864

__global__ __launch_bounds__(256, 2)
void attn_kernel(const __half* __restrict__ qkvh,
                 __half* __restrict__ ctx) {
    extern __shared__ char dsm[];
    const uint32_t usm = smem_u32(dsm);

    const int qt = blockIdx.x;
    const int h  = blockIdx.y;
    const int b  = blockIdx.z;
    const int tid = threadIdx.x;
    const int wid = tid >> 5;
    const int lane = tid & 31;
    const int g   = lane >> 2;
    const int tig = lane & 3;
    const int lr  = lane & 7;
    const int l8  = (lane & 8) ? 8 : 0;
    const int l16 = (lane & 16) ? 8 : 0;

    const int q0 = qt * 128;
    const int row0 = wid * 16;
    const int LD3 = 3 * D_;
    const size_t bbase = (size_t)b * S_ * LD3 + h * HD_;

    // ---- load Q fragments (scaled by 1/8, exact on fp16) ----
    uint32_t qh[4][4];
    {
        const __half2 s8 = __floats2half2_rn(0.125f, 0.125f);
        const size_t r0a = bbase + (size_t)(q0 + row0 + g) * LD3;
        const size_t r1a = r0a + (size_t)8 * LD3;
        #pragma unroll
        for (int kc = 0; kc < 4; kc++) {
            int col = kc * 16 + 2 * tig;
            #pragma unroll
            for (int e = 0; e < 4; e++) {
                size_t a = ((e & 1) ? r1a : r0a) + col + ((e & 2) ? 8 : 0);
                __half2 vh = *reinterpret_cast<const __half2*>(qkvh + a);
                vh = __hmul2(vh, s8);
                qh[kc][e] = *reinterpret_cast<uint32_t*>(&vh);
            }
        }
    }

    // smem: [stage][arr][64][AT_LD], arr 0 = K, 1 = V
    auto load_tile = [&](int kt, int s) {
        const int kv0 = kt * 64;
        #pragma unroll
        for (int i = 0; i < 2; i++) {
            int c = tid + i * 256;           // 512 chunks of 16B per array
            int r = c >> 3, c8 = (c & 7) * 8;
            size_t src = bbase + (size_t)(kv0 + r) * LD3 + c8;
            uint32_t dst = usm + (uint32_t)(s * AT_STAGE + r * AT_LD + c8) * 2;
            cp16(dst,              qkvh + src + D_);       // K
            cp16(dst + AT_ARR * 2, qkvh + src + 2 * D_);   // V
        }
    };

    float o[8][4];
    #pragma unroll
    for (int i = 0; i < 8; i++)
        #pragma unroll
        for (int j = 0; j < 4; j++) o[i][j] = 0.f;
    float m0 = -INFINITY, m1 = -INFINITY, l0 = 0.f, l1 = 0.f;

    const int ktmax = 2 * qt + 1;
    load_tile(0, 0); cp_commit();

    for (int kt = 0; kt <= ktmax; kt++) {
        const int s = kt & 1;
        const int kv0 = kt * 64;
        if (kt < ktmax) { load_tile(kt + 1, s ^ 1); cp_commit(); cp_wait<1>(); }
        else            { cp_wait<0>(); }
        __syncthreads();

        const uint32_t uK = usm + (uint32_t)(s * AT_STAGE) * 2;
        const uint32_t uV = uK + AT_ARR * 2;

        // ---- scores S = Qs @ K^T ----
        float sS[8][4];
        #pragma unroll
        for (int i = 0; i < 8; i++)
            #pragma unroll
            for (int j = 0; j < 4; j++) sS[i][j] = 0.f;

        #pragma unroll
        for (int ntp = 0; ntp < 4; ntp++) {
            int krow = ntp * 16 + lr + l16;
            #pragma unroll
            for (int kc = 0; kc < 4; kc++) {
                uint32_t off = (uint32_t)(krow * AT_LD + kc * 16 + l8) * 2;
                uint32_t th[4];
                ldm_x4(th, uK + off);
                uint32_t bh0[2] = {th[0], th[1]}, bh1[2] = {th[2], th[3]};
                mma_f16(sS[2 * ntp],     qh[kc], bh0);
                mma_f16(sS[2 * ntp + 1], qh[kc], bh1);
            }
        }

        // ---- causal mask ----
        if (kv0 + 63 > q0 + row0) {
            int r0g = q0 + row0 + g;
            #pragma unroll
            for (int nt = 0; nt < 8; nt++) {
                int c0 = kv0 + nt * 8 + 2 * tig;
                if (c0 > r0g)     sS[nt][0] = -1e30f;
                if (c0 + 1 > r0g) sS[nt][1] = -1e30f;
                if (c0 > r0g + 8)     sS[nt][2] = -1e30f;
                if (c0 + 1 > r0g + 8) sS[nt][3] = -1e30f;
            }
        }

        // ---- online softmax (rows g and g+8) ----
        float rm0 = -1e30f, rm1 = -1e30f;
        #pragma unroll
        for (int nt = 0; nt < 8; nt++) {
            rm0 = fmaxf(rm0, fmaxf(sS[nt][0], sS[nt][1]));
            rm1 = fmaxf(rm1, fmaxf(sS[nt][2], sS[nt][3]));
        }
        rm0 = fmaxf(rm0, __shfl_xor_sync(0xffffffffu, rm0, 1));
        rm0 = fmaxf(rm0, __shfl_xor_sync(0xffffffffu, rm0, 2));
        rm1 = fmaxf(rm1, __shfl_xor_sync(0xffffffffu, rm1, 1));
        rm1 = fmaxf(rm1, __shfl_xor_sync(0xffffffffu, rm1, 2));
        float nm0 = fmaxf(m0, rm0), nm1 = fmaxf(m1, rm1);
        float a0 = __expf(m0 - nm0), a1 = __expf(m1 - nm1);
        float rs0 = 0.f, rs1 = 0.f;
        #pragma unroll
        for (int nt = 0; nt < 8; nt++) {
            sS[nt][0] = __expf(sS[nt][0] - nm0);
            sS[nt][1] = __expf(sS[nt][1] - nm0);
            sS[nt][2] = __expf(sS[nt][2] - nm1);
            sS[nt][3] = __expf(sS[nt][3] - nm1);
            rs0 += sS[nt][0] + sS[nt][1];
            rs1 += sS[nt][2] + sS[nt][3];
        }
        rs0 += __shfl_xor_sync(0xffffffffu, rs0, 1);
        rs0 += __shfl_xor_sync(0xffffffffu, rs0, 2);
        rs1 += __shfl_xor_sync(0xffffffffu, rs1, 1);
        rs1 += __shfl_xor_sync(0xffffffffu, rs1, 2);
        l0 = l0 * a0 + rs0; l1 = l1 * a1 + rs1;
        m0 = nm0; m1 = nm1;
        #pragma unroll
        for (int nt = 0; nt < 8; nt++) {
            o[nt][0] *= a0; o[nt][1] *= a0;
            o[nt][2] *= a1; o[nt][3] *= a1;
        }

        // ---- pack P as fp16 A-fragments ----
        uint32_t pah[4][4];
        #pragma unroll
        for (int kc2 = 0; kc2 < 4; kc2++) {
            #pragma unroll
            for (int e = 0; e < 4; e++) {
                int nt = 2 * kc2 + (e >> 1);
                int j0 = (e & 1) ? 2 : 0;
                pah[kc2][e] = pack2h(__float2half_rn(sS[nt][j0]),
                                     __float2half_rn(sS[nt][j0 + 1]));
            }
        }

        // ---- O += P @ V ----
        #pragma unroll
        for (int dn = 0; dn < 4; dn++) {
            #pragma unroll
            for (int kc2 = 0; kc2 < 4; kc2++) {
                int vrow = kc2 * 16 + lr + l8;
                uint32_t off = (uint32_t)(vrow * AT_LD + dn * 16 + l16) * 2;
                uint32_t th[4];
                ldm_x4_t(th, uV + off);
                uint32_t bh0[2] = {th[0], th[1]}, bh1[2] = {th[2], th[3]};
                mma_f16(o[2 * dn],     pah[kc2], bh0);
                mma_f16(o[2 * dn + 1], pah[kc2], bh1);
            }
        }
        __syncthreads();
    }

    // ---- write ctx (fp16) ----
    float inv0 = 1.0f / l0, inv1 = 1.0f / l1;
    size_t r0o = ((size_t)b * S_ + q0 + row0 + g) * D_ + h * HD_;
    size_t r1o = r0o + (size_t)8 * D_;
    #pragma unroll
    for (int nt = 0; nt < 8; nt++) {
        int col = nt * 8 + 2 * tig;
        *reinterpret_cast<uint32_t*>(ctx + r0o + col) =
            pack2h(__float2half_rn(o[nt][0] * inv0), __float2half_rn(o[nt][1] * inv0));
        *reinterpret_cast<uint32_t*>(ctx + r1o + col) =
            pack2h(__float2half_rn(o[nt][2] * inv1), __float2half_rn(o[nt][3] * inv1));
    }
}

// ---------------------------------------------------------------------------
// launch
// ---------------------------------------------------------------------------
extern "C" void kernel_launch(void* const* d_in, const int* in_sizes, int n_in,
                              void* d_out, int out_size) {
    const float* x        = (const float*)d_in[0];
    const float* ln1_g    = (const float*)d_in[1];
    const float* ln1_b    = (const float*)d_in[2];
    const float* c_attn_w = (const float*)d_in[3];
    const float* c_attn_b = (const float*)d_in[4];
    const float* c_proj_w = (const float*)d_in[5];
    const float* c_proj_b = (const float*)d_in[6];
    const float* ln2_g    = (const float*)d_in[7];
    const float* ln2_b    = (const float*)d_in[8];
    const float* fc_w     = (const float*)d_in[9];
    const float* fc_b     = (const float*)d_in[10];
    const float* proj_w   = (const float*)d_in[11];
    const float* proj_b   = (const float*)d_in[12];
    float* out = (float*)d_out;

    cudaFuncSetAttribute(tc_gemm<0>, cudaFuncAttributeMaxDynamicSharedMemorySize, SMEM_GEMM);
    cudaFuncSetAttribute(tc_gemm<1>, cudaFuncAttributeMaxDynamicSharedMemorySize, SMEM_GEMM);
    cudaFuncSetAttribute(tc_gemm<2>, cudaFuncAttributeMaxDynamicSharedMemorySize, SMEM_GEMM);
    cudaFuncSetAttribute(attn_kernel, cudaFuncAttributeMaxDynamicSharedMemorySize, SMEM_ATTN);

    __half *h, *qkv, *ctx, *h2, *ff;
    __half *wqkv, *wpr, *wfc, *wp2;
    float *h1;
    cudaGetSymbolAddress((void**)&h, g_h);
    cudaGetSymbolAddress((void**)&qkv, g_qkv);
    cudaGetSymbolAddress((void**)&ctx, g_ctx);
    cudaGetSymbolAddress((void**)&h1, g_h1);
    cudaGetSymbolAddress((void**)&h2, g_h2);
    cudaGetSymbolAddress((void**)&ff, g_ff);
    cudaGetSymbolAddress((void**)&wqkv, g_wqkv);
    cudaGetSymbolAddress((void**)&wpr, g_wpr);
    cudaGetSymbolAddress((void**)&wfc, g_wfc);
    cudaGetSymbolAddress((void**)&wp2, g_wp2);

    // 0. fused prep: LN1 + all weight transposes (independent work, one launch)
    prep_kernel<<<M_ + 12288, 256>>>(x, ln1_g, ln1_b, h,
                                     c_attn_w, wqkv, c_proj_w, wpr,
                                     fc_w, wfc, proj_w, wp2);
    // 2. qkv = h @ Wqkv + b  -> fp16
    tc_gemm<0><<<dim3(3 * D_ / 128, M_ / 128), 256, SMEM_GEMM>>>(
        h, wqkv, c_attn_b, nullptr, nullptr, qkv, 3 * D_, D_);
    // 3. attention -> ctx fp16
    attn_kernel<<<dim3(S_ / 128, H_, B_), 256, SMEM_ATTN>>>(qkv, ctx);
    // 4. h1 = x + ctx @ Wproj + b  (fp32 out)
    tc_gemm<2><<<dim3(D_ / 128, M_ / 128), 256, SMEM_GEMM>>>(
        ctx, wpr, c_proj_b, x, h1, nullptr, D_, D_);
    // 5. h2 = LN2(h1)  -> fp16
    ln_kernel<<<M_, 256>>>(h1, ln2_g, ln2_b, h2);
    // 6. ff = gelu(h2 @ fc_w + fc_b)  -> fp16
    tc_gemm<1><<<dim3(4 * D_ / 128, M_ / 128), 256, SMEM_GEMM>>>(
        h2, wfc, fc_b, nullptr, nullptr, ff, 4 * D_, D_);
    // 7. out = h1 + ff @ proj_w + proj_b  (fp32 out)
    tc_gemm<2><<<dim3(D_ / 128, M_ / 128), 256, SMEM_GEMM>>>(
        ff, wp2, proj_b, h1, out, nullptr, D_, 4 * D_);
}

// round 13
// speedup vs baseline: 7.0667x; 1.0298x over previous
#include <cuda_runtime.h>
#include <cuda_fp16.h>
#include <cstdint>
#include <math.h>

// ---------------------------------------------------------------------------
// GPT-2 block: B=8, S=1024, D=1024, H=16, Hd=64
// ---------------------------------------------------------------------------
#define B_ 8
#define S_ 1024
#define D_ 1024
#define H_ 16
#define HD_ 64
#define M_ (B_ * S_)          // 8192 rows

// Scratch (device globals; no allocation allowed in kernel_launch)
__device__ __half g_h  [M_ * D_];
__device__ __half g_qkv[M_ * 3 * D_];
__device__ __half g_ctx[M_ * D_];
__device__ float  g_h1 [M_ * D_];
__device__ __half g_h2 [M_ * D_];
__device__ __half g_ff [M_ * 4 * D_];
// transposed weights [N, K] fp16
__device__ __half g_wqkv[3 * D_ * D_];
__device__ __half g_wpr [D_ * D_];
__device__ __half g_wfc [4 * D_ * D_];
__device__ __half g_wp2 [4 * D_ * D_];

// ---------------------------------------------------------------------------
// helpers
// ---------------------------------------------------------------------------
__device__ __forceinline__ uint32_t smem_u32(const void* p) {
    uint32_t a;
    asm("{ .reg .u64 t; cvta.to.shared.u64 t, %1; cvt.u32.u64 %0, t; }"
        : "=r"(a) : "l"(p));
    return a;
}
__device__ __forceinline__ void cp16(uint32_t dst, const void* src) {
    asm volatile("cp.async.cg.shared.global [%0], [%1], 16;"
                 :: "r"(dst), "l"(src) : "memory");
}
__device__ __forceinline__ void cp_commit() {
    asm volatile("cp.async.commit_group;" ::: "memory");
}
template <int N>
__device__ __forceinline__ void cp_wait() {
    asm volatile("cp.async.wait_group %0;" :: "n"(N) : "memory");
}
__device__ __forceinline__ void mma_f16(float* d, const uint32_t* a, const uint32_t* b) {
    asm volatile(
        "mma.sync.aligned.m16n8k16.row.col.f32.f16.f16.f32 "
        "{%0,%1,%2,%3}, {%4,%5,%6,%7}, {%8,%9}, {%0,%1,%2,%3};"
        : "+f"(d[0]), "+f"(d[1]), "+f"(d[2]), "+f"(d[3])
        : "r"(a[0]), "r"(a[1]), "r"(a[2]), "r"(a[3]), "r"(b[0]), "r"(b[1]));
}
__device__ __forceinline__ void ldm_x4(uint32_t* r, uint32_t addr) {
    asm volatile("ldmatrix.sync.aligned.m8n8.x4.shared.b16 {%0,%1,%2,%3}, [%4];"
                 : "=r"(r[0]), "=r"(r[1]), "=r"(r[2]), "=r"(r[3]) : "r"(addr));
}
__device__ __forceinline__ void ldm_x4_t(uint32_t* r, uint32_t addr) {
    asm volatile("ldmatrix.sync.aligned.m8n8.x4.trans.shared.b16 {%0,%1,%2,%3}, [%4];"
                 : "=r"(r[0]), "=r"(r[1]), "=r"(r[2]), "=r"(r[3]) : "r"(addr));
}
__device__ __forceinline__ float gelu_new(float x) {
    float x3 = x * x * x;
    return 0.5f * x * (1.0f + tanhf(0.7978845608028654f * (x + 0.044715f * x3)));
}
__device__ __forceinline__ uint32_t pack2h(__half a, __half b) {
    __half2 t{a, b};
    return *reinterpret_cast<uint32_t*>(&t);
}

// ---------------------------------------------------------------------------
// LayerNorm body (256 threads, one row)
// ---------------------------------------------------------------------------
__device__ __forceinline__ void ln_row(const float* __restrict__ x,
                                       const float* __restrict__ g,
                                       const float* __restrict__ b,
                                       __half* __restrict__ oh,
                                       int row, float* red) {
    int tid = threadIdx.x;
    const float4* xr = reinterpret_cast<const float4*>(x + (size_t)row * D_);
    float4 v = xr[tid];

    float s = v.x + v.y + v.z + v.w;
    #pragma unroll
    for (int o = 16; o; o >>= 1) s += __shfl_xor_sync(0xffffffffu, s, o);
    if ((tid & 31) == 0) red[tid >> 5] = s;
    __syncthreads();
    float tot = 0.f;
    #pragma unroll
    for (int i = 0; i < 8; i++) tot += red[i];
    float mu = tot * (1.0f / D_);
    __syncthreads();

    float dx = v.x - mu, dy = v.y - mu, dz = v.z - mu, dw = v.w - mu;
    float q = dx * dx + dy * dy + dz * dz + dw * dw;
    #pragma unroll
    for (int o = 16; o; o >>= 1) q += __shfl_xor_sync(0xffffffffu, q, o);
    if ((tid & 31) == 0) red[tid >> 5] = q;
    __syncthreads();
    float qtot = 0.f;
    #pragma unroll
    for (int i = 0; i < 8; i++) qtot += red[i];
    float rstd = rsqrtf(qtot * (1.0f / D_) + 1e-5f);

    const float4 g4 = reinterpret_cast<const float4*>(g)[tid];
    const float4 b4 = reinterpret_cast<const float4*>(b)[tid];
    float o0 = dx * rstd * g4.x + b4.x;
    float o1 = dy * rstd * g4.y + b4.y;
    float o2 = dz * rstd * g4.z + b4.z;
    float o3 = dw * rstd * g4.w + b4.w;

    size_t base = (size_t)row * D_ + tid * 4;
    uint32_t* ohp = reinterpret_cast<uint32_t*>(oh + base);
    ohp[0] = pack2h(__float2half_rn(o0), __float2half_rn(o1));
    ohp[1] = pack2h(__float2half_rn(o2), __float2half_rn(o3));
}

// ---------------------------------------------------------------------------
// Weight-transpose tile body (256 threads, 32x32 tile)
// ---------------------------------------------------------------------------
__device__ __forceinline__ void wconv_tile(const float* __restrict__ W,
                                           __half* __restrict__ T_,
                                           int K, int N, int nx, int ky,
                                           float (*t)[33]) {
    int tx = threadIdx.x & 31, ty = threadIdx.x >> 5;
    int n0 = nx * 32, k0 = ky * 32;
    #pragma unroll
    for (int j = 0; j < 4; j++)
        t[ty + j * 8][tx] = W[(size_t)(k0 + ty + j * 8) * N + n0 + tx];
    __syncthreads();
    #pragma unroll
    for (int j = 0; j < 4; j++) {
        int nl = ty + j * 8;
        T_[(size_t)(n0 + nl) * K + k0 + tx] = __float2half_rn(t[tx][nl]);
    }
}

// ---------------------------------------------------------------------------
// Fused prep: LN1 (blocks [0, 8192)) + 4 weight transposes (rest).
// ---------------------------------------------------------------------------
__global__ __launch_bounds__(256)
void prep_kernel(const float* __restrict__ x,
                 const float* __restrict__ ln1_g, const float* __restrict__ ln1_b,
                 __half* __restrict__ h,
                 const float* __restrict__ Wqkv, __half* __restrict__ Tqkv,
                 const float* __restrict__ Wpr,  __half* __restrict__ Tpr,
                 const float* __restrict__ Wfc,  __half* __restrict__ Tfc,
                 const float* __restrict__ Wp2,  __half* __restrict__ Tp2) {
    __shared__ float tbuf[32][33];
    int bid = blockIdx.x;
    if (bid < M_) {
        ln_row(x, ln1_g, ln1_b, h, bid, &tbuf[0][0]);
        return;
    }
    int wb = bid - M_;
    if (wb < 3072) {
        wconv_tile(Wqkv, Tqkv, D_, 3 * D_, wb % 96, wb / 96, tbuf);
    } else if ((wb -= 3072) < 1024) {
        wconv_tile(Wpr, Tpr, D_, D_, wb % 32, wb / 32, tbuf);
    } else if ((wb -= 1024) < 4096) {
        wconv_tile(Wfc, Tfc, D_, 4 * D_, wb % 128, wb / 128, tbuf);
    } else {
        wb -= 4096;
        wconv_tile(Wp2, Tp2, 4 * D_, D_, wb % 32, wb / 32, tbuf);
    }
}

__global__ void ln_kernel(const float* __restrict__ x,
                          const float* __restrict__ g,
                          const float* __restrict__ b,
                          __half* __restrict__ oh) {
    __shared__ float red[8];
    ln_row(x, g, b, oh, blockIdx.x, red);
}

// ---------------------------------------------------------------------------
// fp16 tensor GEMM via mma.sync.m16n8k16 + ldmatrix.
// C[M,N] = A[M,K] @ W[K,N],  A fp16 [M,K], W = Wt[N,K] fp16.
// CTA tile 256x128, 512 threads = 16 warps (4x4), warp tile 64x32,
// BK=64, 3-stage cp.async(.cg) pipeline, 1 CTA/SM (166KB smem).
// EPI: 0 = +bias -> fp16 ; 1 = gelu(+bias) -> fp16 ; 2 = +bias+res -> fp32
// ---------------------------------------------------------------------------
#define BK_ 64
#define T_LD 72                        // smem row stride in halfwords (144 B)
#define A_TILE_B (256 * T_LD * 2)      // 36864
#define B_TILE_B (128 * T_LD * 2)      // 18432
#define STAGE_BYTES (A_TILE_B + B_TILE_B)  // 55296
#define SMEM_GEMM (3 * STAGE_BYTES)        // 165888

template <int EPI>
__global__ __launch_bounds__(512, 1)
void tc_gemm(const __half* __restrict__ Ah, const __half* __restrict__ Bh,
             const float* __restrict__ bias, const float* __restrict__ res,
             float* __restrict__ C, __half* __restrict__ Cho,
             int N, int K) {
    extern __shared__ char dsm[];
    const uint32_t sbase = smem_u32(dsm);
    const int tid  = threadIdx.x;
    const int lane = tid & 31;
    const int wid  = tid >> 5;
    const int g    = lane >> 2;
    const int tig  = lane & 3;
    const int mrow = (wid >> 2) * 64;    // 0..192
    const int ncol = (wid & 3) * 32;     // 0..96
    const int cCol = blockIdx.x, cRow = blockIdx.y;
    const int NC = K / BK_;
    const int lr  = lane & 7;
    const int l8  = (lane & 8) ? 8 : 0;
    const int l16 = (lane & 16) ? 8 : 0;

    const __half* Asrc = Ah + (size_t)cRow * 256 * K;
    const __half* Bsrc = Bh + (size_t)cCol * 128 * K;

    auto load_stage = [&](int chunk, int s) {
        const int kk = chunk * BK_;
        const uint32_t st = sbase + s * STAGE_BYTES;
        // A: 256 rows x 8 chunks of 16B = 2048 chunks; 4 per thread
        #pragma unroll
        for (int i = 0; i < 4; i++) {
            int idx = tid + i * 512;
            int r = idx >> 3, ci = idx & 7;
            cp16(st + r * 144 + ci * 16, Asrc + (size_t)r * K + kk + ci * 8);
        }
        // B: 128 rows x 8 = 1024 chunks; 2 per thread
        #pragma unroll
        for (int i = 0; i < 2; i++) {
            int idx = tid + i * 512;
            int r = idx >> 3, ci = idx & 7;
            cp16(st + A_TILE_B + r * 144 + ci * 16, Bsrc + (size_t)r * K + kk + ci * 8);
        }
    };

    float acc[4][4][4];
    #pragma unroll
    for (int i = 0; i < 4; i++)
        #pragma unroll
        for (int j = 0; j < 4; j++)
            #pragma unroll
            for (int r = 0; r < 4; r++) acc[i][j][r] = 0.f;

    load_stage(0, 0); cp_commit();
    load_stage(1, 1); cp_commit();

    for (int c = 0; c < NC; c++) {
        cp_wait<1>();
        __syncthreads();
        if (c + 2 < NC) load_stage(c + 2, (c + 2) % 3);
        cp_commit();

        const uint32_t ust = sbase + (c % 3) * STAGE_BYTES;
        const uint32_t uAh = ust;
        const uint32_t uBh = ust + A_TILE_B;

        #pragma unroll
        for (int ks = 0; ks < 4; ks++) {
            const int k0 = ks * 16;
            uint32_t ah[4][4], bh[4][2];
            #pragma unroll
            for (int mt = 0; mt < 4; mt++) {
                int row = mrow + mt * 16 + lr + l8;
                ldm_x4(ah[mt], uAh + (uint32_t)(row * T_LD + k0 + l16) * 2);
            }
            #pragma unroll
            for (int ntp = 0; ntp < 2; ntp++) {
                int row = ncol + ntp * 16 + lr + l16;
                uint32_t t4[4];
                ldm_x4(t4, uBh + (uint32_t)(row * T_LD + k0 + l8) * 2);
                bh[2 * ntp][0] = t4[0]; bh[2 * ntp][1] = t4[1];
                bh[2 * ntp + 1][0] = t4[2]; bh[2 * ntp + 1][1] = t4[3];
            }
            #pragma unroll
            for (int mt = 0; mt < 4; mt++)
                #pragma unroll
                for (int nt = 0; nt < 4; nt++)
                    mma_f16(acc[mt][nt], ah[mt], bh[nt]);
        }
    }

    // ---- epilogue ----
    const int row_base = cRow * 256 + mrow;
    const int col_base = cCol * 128 + ncol;
    #pragma unroll
    for (int mt = 0; mt < 4; mt++) {
        #pragma unroll
        for (int nt = 0; nt < 4; nt++) {
            int cc = col_base + nt * 8 + tig * 2;
            float b0 = bias[cc], b1 = bias[cc + 1];
            #pragma unroll
            for (int half = 0; half < 2; half++) {
                int r = row_base + mt * 16 + g + half * 8;
                size_t off = (size_t)r * N + cc;
                float v0 = acc[mt][nt][half * 2 + 0] + b0;
                float v1 = acc[mt][nt][half * 2 + 1] + b1;
                if (EPI == 0 || EPI == 1) {
                    if (EPI == 1) { v0 = gelu_new(v0); v1 = gelu_new(v1); }
                    *reinterpret_cast<uint32_t*>(Cho + off) =
                        pack2h(__float2half_rn(v0), __float2half_rn(v1));
                } else {
                    float2 rr = *reinterpret_cast<const float2*>(res + off);
                    v0 += rr.x; v1 += rr.y;
                    *reinterpret_cast<float2*>(C + off) = make_float2(v0, v1);
                }
            }
        }
    }
}

// ---------------------------------------------------------------------------
// Tensor-core flash attention, pure fp16 operands, fp32 accum/softmax.
// Scores = Q @ K^T, PV = P @ V.  Block = (q-tile 128 rows, head, batch).
// 2 CTAs/SM.
// ---------------------------------------------------------------------------
#define AT_LD 72
#define AT_ARR (64 * AT_LD)                 // elems per array (4608)
#define AT_STAGE (2 * AT_ARR)               // elems per stage (9216)
#define SMEM_ATTN (2 * AT_STAGE * 2)        // bytes: 36864

__global__ __launch_bounds__(256, 2)
void attn_kernel(const __half* __restrict__ qkvh,
                 __half* __restrict__ ctx) {
    extern __shared__ char dsm[];
    const uint32_t usm = smem_u32(dsm);

    const int qt = blockIdx.x;
    const int h  = blockIdx.y;
    const int b  = blockIdx.z;
    const int tid = threadIdx.x;
    const int wid = tid >> 5;
    const int lane = tid & 31;
    const int g   = lane >> 2;
    const int tig = lane & 3;
    const int lr  = lane & 7;
    const int l8  = (lane & 8) ? 8 : 0;
    const int l16 = (lane & 16) ? 8 : 0;

    const int q0 = qt * 128;
    const int row0 = wid * 16;
    const int LD3 = 3 * D_;
    const size_t bbase = (size_t)b * S_ * LD3 + h * HD_;

    // ---- load Q fragments (scaled by 1/8, exact on fp16) ----
    uint32_t qh[4][4];
    {
        const __half2 s8 = __floats2half2_rn(0.125f, 0.125f);
        const size_t r0a = bbase + (size_t)(q0 + row0 + g) * LD3;
        const size_t r1a = r0a + (size_t)8 * LD3;
        #pragma unroll
        for (int kc = 0; kc < 4; kc++) {
            int col = kc * 16 + 2 * tig;
            #pragma unroll
            for (int e = 0; e < 4; e++) {
                size_t a = ((e & 1) ? r1a : r0a) + col + ((e & 2) ? 8 : 0);
                __half2 vh = *reinterpret_cast<const __half2*>(qkvh + a);
                vh = __hmul2(vh, s8);
                qh[kc][e] = *reinterpret_cast<uint32_t*>(&vh);
            }
        }
    }

    // smem: [stage][arr][64][AT_LD], arr 0 = K, 1 = V
    auto load_tile = [&](int kt, int s) {
        const int kv0 = kt * 64;
        #pragma unroll
        for (int i = 0; i < 2; i++) {
            int c = tid + i * 256;
            int r = c >> 3, c8 = (c & 7) * 8;
            size_t src = bbase + (size_t)(kv0 + r) * LD3 + c8;
            uint32_t dst = usm + (uint32_t)(s * AT_STAGE + r * AT_LD + c8) * 2;
            cp16(dst,              qkvh + src + D_);       // K
            cp16(dst + AT_ARR * 2, qkvh + src + 2 * D_);   // V
        }
    };

    float o[8][4];
    #pragma unroll
    for (int i = 0; i < 8; i++)
        #pragma unroll
        for (int j = 0; j < 4; j++) o[i][j] = 0.f;
    float m0 = -INFINITY, m1 = -INFINITY, l0 = 0.f, l1 = 0.f;

    const int ktmax = 2 * qt + 1;
    load_tile(0, 0); cp_commit();

    for (int kt = 0; kt <= ktmax; kt++) {
        const int s = kt & 1;
        const int kv0 = kt * 64;
        if (kt < ktmax) { load_tile(kt + 1, s ^ 1); cp_commit(); cp_wait<1>(); }
        else            { cp_wait<0>(); }
        __syncthreads();

        const uint32_t uK = usm + (uint32_t)(s * AT_STAGE) * 2;
        const uint32_t uV = uK + AT_ARR * 2;

        // ---- scores S = Qs @ K^T ----
        float sS[8][4];
        #pragma unroll
        for (int i = 0; i < 8; i++)
            #pragma unroll
            for (int j = 0; j < 4; j++) sS[i][j] = 0.f;

        #pragma unroll
        for (int ntp = 0; ntp < 4; ntp++) {
            int krow = ntp * 16 + lr + l16;
            #pragma unroll
            for (int kc = 0; kc < 4; kc++) {
                uint32_t off = (uint32_t)(krow * AT_LD + kc * 16 + l8) * 2;
                uint32_t th[4];
                ldm_x4(th, uK + off);
                uint32_t bh0[2] = {th[0], th[1]}, bh1[2] = {th[2], th[3]};
                mma_f16(sS[2 * ntp],     qh[kc], bh0);
                mma_f16(sS[2 * ntp + 1], qh[kc], bh1);
            }
        }

        // ---- causal mask ----
        if (kv0 + 63 > q0 + row0) {
            int r0g = q0 + row0 + g;
            #pragma unroll
            for (int nt = 0; nt < 8; nt++) {
                int c0 = kv0 + nt * 8 + 2 * tig;
                if (c0 > r0g)     sS[nt][0] = -1e30f;
                if (c0 + 1 > r0g) sS[nt][1] = -1e30f;
                if (c0 > r0g + 8)     sS[nt][2] = -1e30f;
                if (c0 + 1 > r0g + 8) sS[nt][3] = -1e30f;
            }
        }

        // ---- online softmax (rows g and g+8) ----
        float rm0 = -1e30f, rm1 = -1e30f;
        #pragma unroll
        for (int nt = 0; nt < 8; nt++) {
            rm0 = fmaxf(rm0, fmaxf(sS[nt][0], sS[nt][1]));
            rm1 = fmaxf(rm1, fmaxf(sS[nt][2], sS[nt][3]));
        }
        rm0 = fmaxf(rm0, __shfl_xor_sync(0xffffffffu, rm0, 1));
        rm0 = fmaxf(rm0, __shfl_xor_sync(0xffffffffu, rm0, 2));
        rm1 = fmaxf(rm1, __shfl_xor_sync(0xffffffffu, rm1, 1));
        rm1 = fmaxf(rm1, __shfl_xor_sync(0xffffffffu, rm1, 2));
        float nm0 = fmaxf(m0, rm0), nm1 = fmaxf(m1, rm1);
        float a0 = __expf(m0 - nm0), a1 = __expf(m1 - nm1);
        float rs0 = 0.f, rs1 = 0.f;
        #pragma unroll
        for (int nt = 0; nt < 8; nt++) {
            sS[nt][0] = __expf(sS[nt][0] - nm0);
            sS[nt][1] = __expf(sS[nt][1] - nm0);
            sS[nt][2] = __expf(sS[nt][2] - nm1);
            sS[nt][3] = __expf(sS[nt][3] - nm1);
            rs0 += sS[nt][0] + sS[nt][1];
            rs1 += sS[nt][2] + sS[nt][3];
        }
        rs0 += __shfl_xor_sync(0xffffffffu, rs0, 1);
        rs0 += __shfl_xor_sync(0xffffffffu, rs0, 2);
        rs1 += __shfl_xor_sync(0xffffffffu, rs1, 1);
        rs1 += __shfl_xor_sync(0xffffffffu, rs1, 2);
        l0 = l0 * a0 + rs0; l1 = l1 * a1 + rs1;
        m0 = nm0; m1 = nm1;
        #pragma unroll
        for (int nt = 0; nt < 8; nt++) {
            o[nt][0] *= a0; o[nt][1] *= a0;
            o[nt][2] *= a1; o[nt][3] *= a1;
        }

        // ---- pack P as fp16 A-fragments ----
        uint32_t pah[4][4];
        #pragma unroll
        for (int kc2 = 0; kc2 < 4; kc2++) {
            #pragma unroll
            for (int e = 0; e < 4; e++) {
                int nt = 2 * kc2 + (e >> 1);
                int j0 = (e & 1) ? 2 : 0;
                pah[kc2][e] = pack2h(__float2half_rn(sS[nt][j0]),
                                     __float2half_rn(sS[nt][j0 + 1]));
            }
        }

        // ---- O += P @ V ----
        #pragma unroll
        for (int dn = 0; dn < 4; dn++) {
            #pragma unroll
            for (int kc2 = 0; kc2 < 4; kc2++) {
                int vrow = kc2 * 16 + lr + l8;
                uint32_t off = (uint32_t)(vrow * AT_LD + dn * 16 + l16) * 2;
                uint32_t th[4];
                ldm_x4_t(th, uV + off);
                uint32_t bh0[2] = {th[0], th[1]}, bh1[2] = {th[2], th[3]};
                mma_f16(o[2 * dn],     pah[kc2], bh0);
                mma_f16(o[2 * dn + 1], pah[kc2], bh1);
            }
        }
        __syncthreads();
    }

    // ---- write ctx (fp16) ----
    float inv0 = 1.0f / l0, inv1 = 1.0f / l1;
    size_t r0o = ((size_t)b * S_ + q0 + row0 + g) * D_ + h * HD_;
    size_t r1o = r0o + (size_t)8 * D_;
    #pragma unroll
    for (int nt = 0; nt < 8; nt++) {
        int col = nt * 8 + 2 * tig;
        *reinterpret_cast<uint32_t*>(ctx + r0o + col) =
            pack2h(__float2half_rn(o[nt][0] * inv0), __float2half_rn(o[nt][1] * inv0));
        *reinterpret_cast<uint32_t*>(ctx + r1o + col) =
            pack2h(__float2half_rn(o[nt][2] * inv1), __float2half_rn(o[nt][3] * inv1));
    }
}

// ---------------------------------------------------------------------------
// launch
// ---------------------------------------------------------------------------
extern "C" void kernel_launch(void* const* d_in, const int* in_sizes, int n_in,
                              void* d_out, int out_size) {
    const float* x        = (const float*)d_in[0];
    const float* ln1_g    = (const float*)d_in[1];
    const float* ln1_b    = (const float*)d_in[2];
    const float* c_attn_w = (const float*)d_in[3];
    const float* c_attn_b = (const float*)d_in[4];
    const float* c_proj_w = (const float*)d_in[5];
    const float* c_proj_b = (const float*)d_in[6];
    const float* ln2_g    = (const float*)d_in[7];
    const float* ln2_b    = (const float*)d_in[8];
    const float* fc_w     = (const float*)d_in[9];
    const float* fc_b     = (const float*)d_in[10];
    const float* proj_w   = (const float*)d_in[11];
    const float* proj_b   = (const float*)d_in[12];
    float* out = (float*)d_out;

    cudaFuncSetAttribute(tc_gemm<0>, cudaFuncAttributeMaxDynamicSharedMemorySize, SMEM_GEMM);
    cudaFuncSetAttribute(tc_gemm<1>, cudaFuncAttributeMaxDynamicSharedMemorySize, SMEM_GEMM);
    cudaFuncSetAttribute(tc_gemm<2>, cudaFuncAttributeMaxDynamicSharedMemorySize, SMEM_GEMM);
    cudaFuncSetAttribute(attn_kernel, cudaFuncAttributeMaxDynamicSharedMemorySize, SMEM_ATTN);

    __half *h, *qkv, *ctx, *h2, *ff;
    __half *wqkv, *wpr, *wfc, *wp2;
    float *h1;
    cudaGetSymbolAddress((void**)&h, g_h);
    cudaGetSymbolAddress((void**)&qkv, g_qkv);
    cudaGetSymbolAddress((void**)&ctx, g_ctx);
    cudaGetSymbolAddress((void**)&h1, g_h1);
    cudaGetSymbolAddress((void**)&h2, g_h2);
    cudaGetSymbolAddress((void**)&ff, g_ff);
    cudaGetSymbolAddress((void**)&wqkv, g_wqkv);
    cudaGetSymbolAddress((void**)&wpr, g_wpr);
    cudaGetSymbolAddress((void**)&wfc, g_wfc);
    cudaGetSymbolAddress((void**)&wp2, g_wp2);

    // 0. fused prep: LN1 + all weight transposes
    prep_kernel<<<M_ + 12288, 256>>>(x, ln1_g, ln1_b, h,
                                     c_attn_w, wqkv, c_proj_w, wpr,
                                     fc_w, wfc, proj_w, wp2);
    // 2. qkv = h @ Wqkv + b  -> fp16
    tc_gemm<0><<<dim3(3 * D_ / 128, M_ / 256), 512, SMEM_GEMM>>>(
        h, wqkv, c_attn_b, nullptr, nullptr, qkv, 3 * D_, D_);
    // 3. attention -> ctx fp16
    attn_kernel<<<dim3(S_ / 128, H_, B_), 256, SMEM_ATTN>>>(qkv, ctx);
    // 4. h1 = x + ctx @ Wproj + b  (fp32 out)
    tc_gemm<2><<<dim3(D_ / 128, M_ / 256), 512, SMEM_GEMM>>>(
        ctx, wpr, c_proj_b, x, h1, nullptr, D_, D_);
    // 5. h2 = LN2(h1)  -> fp16
    ln_kernel<<<M_, 256>>>(h1, ln2_g, ln2_b, h2);
    // 6. ff = gelu(h2 @ fc_w + fc_b)  -> fp16
    tc_gemm<1><<<dim3(4 * D_ / 128, M_ / 256), 512, SMEM_GEMM>>>(
        h2, wfc, fc_b, nullptr, nullptr, ff, 4 * D_, D_);
    // 7. out = h1 + ff @ proj_w + proj_b  (fp32 out)
    tc_gemm<2><<<dim3(D_ / 128, M_ / 256), 512, SMEM_GEMM>>>(
        ff, wp2, proj_b, h1, out, nullptr, D_, 4 * D_);
}